// round 8
// baseline (speedup 1.0000x reference)
#include <cuda_runtime.h>
#include <cuda_bf16.h>
#include <math.h>
#include <stdint.h>

// ============================================================================
// Problem constants
// ============================================================================
namespace {
constexpr int B_ = 8, C_ = 512, L_ = 256;
constexpr int CL_ = C_ * L_;           // 131072
constexpr int C3_ = 3 * C_;            // 1536
constexpr int C4_ = 4 * C_;            // 2048
constexpr int NR_ = L_ * B_;           // 2048
constexpr size_t BLL_ = (size_t)B_ * L_ * L_;   // 524288
constexpr float SCALE_ = 0.044194173824159216f; // 512^-0.5

// ---------------- scratch offsets (float units) ----------------
constexpr size_t OFF_XT_HI   = 0;                                    // bf16 [B,L,C]
constexpr size_t OFF_XT_LO   = OFF_XT_HI   + (size_t)B_ * CL_ / 2;
constexpr size_t OFF_WQKV_HI = OFF_XT_LO   + (size_t)B_ * CL_ / 2;   // bf16 [3C,C]
constexpr size_t OFF_WQKV_LO = OFF_WQKV_HI + (size_t)C3_ * C_ / 2;
constexpr size_t OFF_QKV_B   = OFF_WQKV_LO + (size_t)C3_ * C_ / 2;   // f32 [1536]
constexpr size_t OFF_WWG_HI  = OFF_QKV_B   + 1536;
constexpr size_t OFF_WWG_LO  = OFF_WWG_HI  + (size_t)C_ * C_ / 2;
constexpr size_t OFF_C1WHI   = OFF_WWG_LO  + (size_t)C_ * C_ / 2;
constexpr size_t OFF_C1WLO   = OFF_C1WHI   + (size_t)C4_ * C_ / 2;
constexpr size_t OFF_C2WHI   = OFF_C1WLO   + (size_t)C4_ * C_ / 2;
constexpr size_t OFF_C2WLO   = OFF_C2WHI   + (size_t)C_ * C4_ / 2;
constexpr size_t OFF_QKVT_HI = OFF_C2WLO   + (size_t)C_ * C4_ / 2;   // bf16 [B,L,3C]
constexpr size_t OFF_QKVT_LO = OFF_QKVT_HI + (size_t)B_ * L_ * C3_ / 2;
// S scores: [split(2)][sel(2)][b][L][L] fp32 partials
constexpr size_t OFF_SG      = OFF_QKVT_LO + (size_t)B_ * L_ * C3_ / 2;
constexpr size_t OFF_GP_HI   = OFF_SG      + 4 * BLL_;               // bf16 [B,L,L]
constexpr size_t OFF_GP_LO   = OFF_GP_HI   + BLL_ / 2;
constexpr size_t OFF_GG2_HI  = OFF_GP_LO   + BLL_ / 2;               // bf16 [B,C,L]
constexpr size_t OFF_GG2_LO  = OFF_GG2_HI  + (size_t)B_ * CL_ / 2;
constexpr size_t OFF_GBAR    = OFF_GG2_LO  + (size_t)B_ * CL_ / 2;
constexpr size_t OFF_GATE    = OFF_GBAR    + (size_t)B_ * L_;
constexpr size_t OFF_GOUTT_HI= OFF_GATE    + (size_t)B_ * L_;        // bf16 [B,L,C]
constexpr size_t OFF_GOUTT_LO= OFF_GOUTT_HI+ (size_t)B_ * CL_ / 2;
constexpr size_t OFF_GOUT2T  = OFF_GOUTT_LO+ (size_t)B_ * CL_ / 2;   // f32 [2][B,L,C]
constexpr size_t OFF_H1      = OFF_GOUT2T  + 2 * (size_t)B_ * CL_;   // f32 [NR,C]
constexpr size_t OFF_H1HI    = OFF_H1      + (size_t)NR_ * C_;
constexpr size_t OFF_H1LO    = OFF_H1HI    + (size_t)NR_ * C_ / 2;
constexpr size_t OFF_M1HI    = OFF_H1LO    + (size_t)NR_ * C_ / 2;   // bf16 [NR,C4]
constexpr size_t OFF_M1LO    = OFF_M1HI    + (size_t)NR_ * C4_ / 2;
constexpr size_t OFF_M2      = OFF_M1LO    + (size_t)NR_ * C4_ / 2;  // f32 [2][NR,C]
constexpr size_t SCRATCH_TOTAL = OFF_M2    + 2 * (size_t)NR_ * C_;
} // namespace

__device__ __align__(256) float d_scratch[SCRATCH_TOTAL];

// ============================================================================
// PTX helpers — sm_80-era only (mma.sync / ldmatrix / cp.async).
// ============================================================================
__device__ __forceinline__ uint32_t smem_to_u32(const void* p) {
    uint32_t a;
    asm("{ .reg .u64 t; cvta.to.shared.u64 t, %1; cvt.u32.u64 %0, t; }" : "=r"(a) : "l"(p));
    return a;
}
__device__ __forceinline__ void ldmat4(uint32_t (&r)[4], uint32_t addr) {
    asm volatile("ldmatrix.sync.aligned.m8n8.x4.shared.b16 {%0,%1,%2,%3}, [%4];"
                 : "=r"(r[0]), "=r"(r[1]), "=r"(r[2]), "=r"(r[3]) : "r"(addr));
}
__device__ __forceinline__ void mma16816(float (&d)[4], const uint32_t (&a)[4], const uint32_t b0, const uint32_t b1) {
    asm volatile("mma.sync.aligned.m16n8k16.row.col.f32.bf16.bf16.f32 "
                 "{%0,%1,%2,%3}, {%4,%5,%6,%7}, {%8,%9}, {%0,%1,%2,%3};"
                 : "+f"(d[0]), "+f"(d[1]), "+f"(d[2]), "+f"(d[3])
                 : "r"(a[0]), "r"(a[1]), "r"(a[2]), "r"(a[3]), "r"(b0), "r"(b1));
}
__device__ __forceinline__ void cp16(uint32_t saddr, const void* g) {
    asm volatile("cp.async.cg.shared.global [%0], [%1], 16;" :: "r"(saddr), "l"(g));
}
#define CP_COMMIT() asm volatile("cp.async.commit_group;" ::: "memory")
template <int N>
__device__ __forceinline__ void cp_wait() {
    asm volatile("cp.async.wait_group %0;" :: "n"(N) : "memory");
}

namespace {

__device__ __forceinline__ float warpSum(float v) {
#pragma unroll
    for (int o = 16; o; o >>= 1) v += __shfl_xor_sync(0xffffffffu, v, o);
    return v;
}
__device__ __forceinline__ float warpMax(float v) {
#pragma unroll
    for (int o = 16; o; o >>= 1) v = fmaxf(v, __shfl_xor_sync(0xffffffffu, v, o));
    return v;
}
__device__ __forceinline__ float mishf(float v) {
    float sp = fmaxf(v, 0.f) + log1pf(__expf(-fabsf(v)));
    return v * tanhf(sp);
}

// ============================================================================
// bf16-split tensor-core GEMM, multistage cp.async pipeline.
// NT: A [M,K] K-contig (lda) hi/lo ; B [N,K] K-contig (ldb) hi/lo
// D = Ahi·Bhi^T + Ahi·Blo^T + Alo·Bhi^T (fp32 accum)
// v = scale*D (+ biasN on split 0); ACT=1 -> mish; OUTFMT 0: fp32; 1: bf16.
// z layout: [FUSE sel | b] with low bit = split when SPLITK==2.
// SPLITK==2: each split handles K/2, writes to out + split*sSplit.
// ============================================================================
template <int BN, int OUTFMT, int ACT, int FUSE, int STAGES, int KB, int SPLITK>
__global__ void __launch_bounds__(256) gemm_mma(
    const __nv_bfloat16* __restrict__ Ahi, const __nv_bfloat16* __restrict__ Alo,
    const __nv_bfloat16* __restrict__ Bhi, const __nv_bfloat16* __restrict__ Blo,
    const float* __restrict__ biasN,
    float* __restrict__ outF,
    __nv_bfloat16* __restrict__ outHi, __nv_bfloat16* __restrict__ outLo,
    int K, int lda, int ldb, int ldOut,
    size_t sA, size_t sB, size_t sO, size_t selB, size_t selO, size_t sSplit,
    float scale)
{
    constexpr int BM = 128;
    constexpr int SROW = KB * 2 + 16;        // bytes/row: data + 16B pad
    constexpr int CHR = KB / 8;              // 16B chunks per row
    constexpr int ATILE = BM * SROW;
    constexpr int BTILE = BN * SROW;
    constexpr int STAGE = 2 * ATILE + 2 * BTILE;
    constexpr int WN = BN / 4;
    constexpr int NFRAG = WN / 8;
    constexpr int NKS = KB / 16;             // k16 steps per chunk

    extern __shared__ char smem[];
    const uint32_t sb = smem_to_u32(smem);
    const int tid = threadIdx.x, lane = tid & 31, wid = tid >> 5;
    const int wm = wid & 1, wn = wid >> 1;
    const int m0 = blockIdx.y * BM, n0 = blockIdx.x * BN;
    const int zz = blockIdx.z;
    const int split = (SPLITK > 1) ? (zz & 1) : 0;
    const int zr = (SPLITK > 1) ? (zz >> 1) : zz;
    const int b = FUSE ? (zr & 7) : zr;
    const int sel = FUSE ? (zr >> 3) : 0;
    const int Keff = K / SPLITK;
    const int kOff = split * Keff;

    Ahi += (size_t)b * sA + kOff; Alo += (size_t)b * sA + kOff;
    Bhi += (size_t)b * sB + (size_t)sel * selB + kOff;
    Blo += (size_t)b * sB + (size_t)sel * selB + kOff;
    if (OUTFMT == 0) outF += (size_t)b * sO + (size_t)sel * selO + (size_t)split * sSplit;
    else {
        outHi += (size_t)b * sO + (size_t)sel * selO;
        outLo += (size_t)b * sO + (size_t)sel * selO;
    }

    float acc[4][NFRAG][4];
#pragma unroll
    for (int i = 0; i < 4; i++)
#pragma unroll
        for (int j = 0; j < NFRAG; j++)
#pragma unroll
            for (int q = 0; q < 4; q++) acc[i][j][q] = 0.f;

    auto load_stage = [&](int ch, int st) {
        const int k0 = ch * KB;
        const uint32_t base = sb + st * STAGE;
#pragma unroll
        for (int c = tid; c < BM * CHR; c += 256) {
            int r = c / CHR, cc = c % CHR;
            size_t go = (size_t)(m0 + r) * lda + k0 + cc * 8;
            uint32_t so = base + r * SROW + cc * 16;
            cp16(so, Ahi + go);
            cp16(so + ATILE, Alo + go);
        }
#pragma unroll
        for (int c = tid; c < BN * CHR; c += 256) {
            int r = c / CHR, cc = c % CHR;
            size_t go = (size_t)(n0 + r) * ldb + k0 + cc * 8;
            uint32_t so = base + 2 * ATILE + r * SROW + cc * 16;
            cp16(so, Bhi + go);
            cp16(so + BTILE, Blo + go);
        }
        CP_COMMIT();
    };

    const int nch = Keff / KB;
#pragma unroll
    for (int s = 0; s < STAGES - 1; s++) load_stage(s, s);

    int cs = 0;
    int ps = (STAGES - 1) % STAGES;
    for (int ch = 0; ch < nch; ch++) {
        cp_wait<STAGES - 2>();
        __syncthreads();
        const int pf = ch + STAGES - 1;
        if (pf < nch) load_stage(pf, ps);
        else CP_COMMIT();

        const uint32_t aBase = sb + cs * STAGE;
        const uint32_t bBase = aBase + 2 * ATILE;
#pragma unroll
        for (int ks = 0; ks < NKS; ks++) {
            const uint32_t colOff = (uint32_t)(ks * 2 + (lane >> 4)) * 16;
            uint32_t a_hi[4][4], a_lo[4][4];
#pragma unroll
            for (int mi = 0; mi < 4; mi++) {
                uint32_t addr = aBase + (uint32_t)(wm * 64 + mi * 16 + (lane & 15)) * SROW + colOff;
                ldmat4(a_hi[mi], addr);
                ldmat4(a_lo[mi], addr + ATILE);
            }
#pragma unroll
            for (int nt = 0; nt < NFRAG / 2; nt++) {
                uint32_t addr = bBase + (uint32_t)(wn * WN + nt * 16 + (lane & 15)) * SROW + colOff;
                uint32_t bh[4], bl[4];
                ldmat4(bh, addr);
                ldmat4(bl, addr + BTILE);
#pragma unroll
                for (int half = 0; half < 2; half++) {
                    const int ni = nt * 2 + half;
#pragma unroll
                    for (int mi = 0; mi < 4; mi++) {
                        mma16816(acc[mi][ni], a_hi[mi], bh[half], bh[2 + half]);
                        mma16816(acc[mi][ni], a_hi[mi], bl[half], bl[2 + half]);
                        mma16816(acc[mi][ni], a_lo[mi], bh[half], bh[2 + half]);
                    }
                }
            }
        }
        cs = (cs + 1 == STAGES) ? 0 : cs + 1;
        ps = (ps + 1 == STAGES) ? 0 : ps + 1;
    }

    // ---------------- epilogue ----------------
    const int g = lane >> 2, tg = lane & 3;
    const bool doBias = (biasN != nullptr) && (split == 0);
#pragma unroll
    for (int mi = 0; mi < 4; mi++) {
#pragma unroll
        for (int ni = 0; ni < NFRAG; ni++) {
            const int col = n0 + wn * WN + ni * 8 + tg * 2;
            const float b0 = doBias ? biasN[col] : 0.f;
            const float b1 = doBias ? biasN[col + 1] : 0.f;
#pragma unroll
            for (int h = 0; h < 2; h++) {
                const int row = m0 + wm * 64 + mi * 16 + g + h * 8;
                float v0 = acc[mi][ni][h * 2 + 0] * scale + b0;
                float v1 = acc[mi][ni][h * 2 + 1] * scale + b1;
                if (ACT == 1) { v0 = mishf(v0); v1 = mishf(v1); }
                const size_t o = (size_t)row * ldOut + col;
                if (OUTFMT == 1) {
                    __nv_bfloat16 h0 = __float2bfloat16(v0);
                    __nv_bfloat16 h1 = __float2bfloat16(v1);
                    __nv_bfloat162 hp; hp.x = h0; hp.y = h1;
                    __nv_bfloat162 lp;
                    lp.x = __float2bfloat16(v0 - __bfloat162float(h0));
                    lp.y = __float2bfloat16(v1 - __bfloat162float(h1));
                    *(__nv_bfloat162*)(outHi + o) = hp;
                    *(__nv_bfloat162*)(outLo + o) = lp;
                } else {
                    float2 fp; fp.x = v0; fp.y = v1;
                    *(float2*)(outF + o) = fp;
                }
            }
        }
    }
}

// ============================================================================
// prep_all: ONE launch = all weight splits + qkv bias concat + x transpose.
// ============================================================================
constexpr int PREP_SPLIT_TOTAL = 3 * C_ * C_ + C_ * C_ + C4_ * C_ + C_ * C4_ + C3_;
constexpr int PREP_NSPLIT = (PREP_SPLIT_TOTAL + 255) / 256;
constexpr int PREP_NT = (L_ / 32) * (C_ / 32) * B_;

__global__ void prep_all(const float* __restrict__ x,
                         const float* __restrict__ tw, const float* __restrict__ pw,
                         const float* __restrict__ gw, const float* __restrict__ wgw,
                         const float* __restrict__ c1w, const float* __restrict__ c2w,
                         const float* __restrict__ tb, const float* __restrict__ pb,
                         const float* __restrict__ gb,
                         __nv_bfloat16* __restrict__ qkvHi, __nv_bfloat16* __restrict__ qkvLo,
                         __nv_bfloat16* __restrict__ wgHi, __nv_bfloat16* __restrict__ wgLo,
                         __nv_bfloat16* __restrict__ c1Hi, __nv_bfloat16* __restrict__ c1Lo,
                         __nv_bfloat16* __restrict__ c2Hi, __nv_bfloat16* __restrict__ c2Lo,
                         float* __restrict__ qkvb,
                         __nv_bfloat16* __restrict__ xtHi, __nv_bfloat16* __restrict__ xtLo)
{
    __shared__ float t[32][33];
    const int bid = blockIdx.x;
    if (bid < PREP_NSPLIT) {
        constexpr int NW = C_ * C_;
        constexpr int N1 = 3 * NW;
        constexpr int N2 = N1 + NW;
        constexpr int N3 = N2 + C4_ * C_;
        constexpr int N4 = N3 + C_ * C4_;
        const int i = bid * 256 + threadIdx.x;
        float v;
        __nv_bfloat16 *hi, *lo;
        int j;
        if (i < N1) {
            j = i & (NW - 1);
            const float* src = (i < NW) ? tw : (i < 2 * NW ? pw : gw);
            v = src[j]; hi = qkvHi + i; lo = qkvLo + i;
        } else if (i < N2) {
            j = i - N1; v = wgw[j]; hi = wgHi + j; lo = wgLo + j;
        } else if (i < N3) {
            j = i - N2; v = c1w[j]; hi = c1Hi + j; lo = c1Lo + j;
        } else if (i < N4) {
            j = i - N3; v = c2w[j]; hi = c2Hi + j; lo = c2Lo + j;
        } else if (i < N4 + C3_) {
            j = i - N4;
            qkvb[j] = (j < C_) ? tb[j] : (j < 2 * C_ ? pb[j - C_] : gb[j - 2 * C_]);
            return;
        } else return;
        __nv_bfloat16 h = __float2bfloat16(v);
        *hi = h;
        *lo = __float2bfloat16(v - __bfloat162float(h));
    } else {
        const int tI = bid - PREP_NSPLIT;
        const int b = tI >> 7;
        const int rem = tI & 127;
        const int c0 = (rem & 15) * 32;
        const int l0 = (rem >> 4) * 32;
        const int tx = threadIdx.x & 31, ty = threadIdx.x >> 5;
        const float* xb = x + (size_t)b * CL_;
#pragma unroll
        for (int j = 0; j < 4; j++)
            t[ty + j * 8][tx] = xb[(size_t)(c0 + ty + j * 8) * L_ + l0 + tx];
        __syncthreads();
#pragma unroll
        for (int j = 0; j < 4; j++) {
            int l = l0 + ty + j * 8;
            float v = t[tx][ty + j * 8];
            __nv_bfloat16 h = __float2bfloat16(v);
            size_t o = ((size_t)b * L_ + l) * C_ + c0 + tx;
            xtHi[o] = h;
            xtLo[o] = __float2bfloat16(v - __bfloat162float(h));
        }
    }
}

// ============================================================================
// transpose_g + gbar in ONE kernel. grid (L/32, B), 256 threads.
// ============================================================================
__global__ void gtrans_gbar(const __nv_bfloat16* __restrict__ inHi,
                            const __nv_bfloat16* __restrict__ inLo,
                            __nv_bfloat16* __restrict__ outHi,
                            __nv_bfloat16* __restrict__ outLo,
                            float* __restrict__ gbar)
{
    __shared__ __nv_bfloat16 th[32][34];
    __shared__ __nv_bfloat16 tl[32][34];
    const int b = blockIdx.y;
    const int l0 = blockIdx.x * 32;
    const int tx = threadIdx.x & 31, ty = threadIdx.x >> 5;

    for (int ct = 0; ct < 16; ct++) {
        const int c0 = ct * 32;
#pragma unroll
        for (int j = 0; j < 4; j++) {
            size_t idx = ((size_t)b * L_ + l0 + ty + j * 8) * C3_ + 2 * C_ + c0 + tx;
            th[ty + j * 8][tx] = inHi[idx];
            tl[ty + j * 8][tx] = inLo[idx];
        }
        __syncthreads();
#pragma unroll
        for (int j = 0; j < 4; j++) {
            int c = c0 + ty + j * 8;
            size_t o = ((size_t)b * C_ + c) * L_ + l0 + tx;
            outHi[o] = th[tx][ty + j * 8];
            outLo[o] = tl[tx][ty + j * 8];
        }
        __syncthreads();
    }

    const int w = threadIdx.x >> 5, lane = threadIdx.x & 31;
#pragma unroll
    for (int i = 0; i < 4; i++) {
        const int l = l0 + w * 4 + i;
        const size_t base = ((size_t)b * L_ + l) * C3_ + 2 * C_;
        float s = 0.f;
#pragma unroll
        for (int c = lane; c < C_; c += 32)
            s += __bfloat162float(inHi[base + c]) + __bfloat162float(inLo[base + c]);
        s = warpSum(s);
        if (lane == 0) gbar[b * L_ + l] = s * (1.f / C_);
    }
}

// ============================================================================
// Fused: softmax(SgA+SgB row) -> gp hi/lo  AND  banded gate from SlA+SlB row.
// ============================================================================
__global__ void softmax_gate(const float* __restrict__ SgA, const float* __restrict__ SgB,
                             const float* __restrict__ SlA, const float* __restrict__ SlB,
                             const float* __restrict__ gbar,
                             const float* __restrict__ wlw,
                             const float* __restrict__ wlb,
                             __nv_bfloat16* __restrict__ pHi,
                             __nv_bfloat16* __restrict__ pLo,
                             float* __restrict__ gate)
{
    __shared__ float sm[16];
    const int l = blockIdx.x, b = blockIdx.y, tid = threadIdx.x;
    const int lane = tid & 31, w = tid >> 5;
    const size_t row = (size_t)b * L_ + l;

    float v = SgA[row * L_ + tid] + SgB[row * L_ + tid];
    float m = warpMax(v);
    if (lane == 0) sm[w] = m;
    __syncthreads();
    float M = -1e30f;
#pragma unroll
    for (int i = 0; i < 8; i++) M = fmaxf(M, sm[i]);
    float e = __expf(v - M);
    float s = warpSum(e);
    if (lane == 0) sm[8 + w] = s;
    __syncthreads();
    float T = 0.f;
#pragma unroll
    for (int i = 0; i < 8; i++) T += sm[8 + i];
    float p = e / T;
    __nv_bfloat16 h = __float2bfloat16(p);
    pHi[row * L_ + tid] = h;
    pLo[row * L_ + tid] = __float2bfloat16(p - __bfloat162float(h));

    if (w == 0) {
        const float* sa = SlA + row * L_;
        const float* sbp = SlB + row * L_;
        const float* gb = gbar + (size_t)b * L_;
        int m0 = l + lane - 32;
        int m1 = l + lane;
        bool v0 = (m0 >= 0) && (m0 < L_);
        bool v1 = (m1 >= 0) && (m1 < L_);
        float s0 = v0 ? (sa[m0] + sbp[m0]) : 0.f;
        float s1 = v1 ? (sa[m1] + sbp[m1]) : 0.f;
        float g0 = v0 ? gb[m0] : 0.f;
        float g1 = v1 ? gb[m1] : 0.f;
        float mx = warpMax(fmaxf(s0, s1));
        float e0 = __expf(s0 - mx), e1 = __expf(s1 - mx);
        float num = warpSum(e0 * g0 + e1 * g1);
        float den = warpSum(e0 + e1);
        if (lane == 0) {
            float pooled = num / den;
            float z = wlw[0] * pooled + wlb[0];
            gate[b * L_ + l] = 1.f / (1.f + __expf(-z));
        }
    }
}

// ============================================================================
// LN1: h = (g2a+g2b)*gate + x ; h1 fp32 + bf16 hi/lo at row (l*B+b), [*,C]
// ============================================================================
__global__ void ln1_kernel(const float* __restrict__ g2a, const float* __restrict__ g2b,
                           const float* __restrict__ gate,
                           const float* __restrict__ x,
                           const float* __restrict__ g1, const float* __restrict__ b1,
                           float* __restrict__ h1,
                           __nv_bfloat16* __restrict__ h1hi,
                           __nv_bfloat16* __restrict__ h1lo)
{
    __shared__ float sm[16];
    int l = blockIdx.x, b = blockIdx.y, tid = threadIdx.x;
    int lane = tid & 31, w = tid >> 5;
    float gt = gate[b * L_ + l];
    size_t gbase = ((size_t)b * L_ + l) * C_;
    size_t xbase = (size_t)b * CL_ + l;
    float v0 = fmaf(g2a[gbase + tid] + g2b[gbase + tid], gt, x[xbase + (size_t)tid * L_]);
    float v1 = fmaf(g2a[gbase + tid + 256] + g2b[gbase + tid + 256], gt,
                    x[xbase + (size_t)(tid + 256) * L_]);
    float s = warpSum(v0 + v1);
    float q = warpSum(v0 * v0 + v1 * v1);
    if (lane == 0) { sm[w] = s; sm[8 + w] = q; }
    __syncthreads();
    float S = 0.f, Q = 0.f;
#pragma unroll
    for (int i = 0; i < 8; i++) { S += sm[i]; Q += sm[8 + i]; }
    float mean = S * (1.f / C_);
    float var = Q * (1.f / C_) - mean * mean;
    float r = rsqrtf(var + 1e-5f);
    size_t o = ((size_t)l * B_ + b) * C_;
    float y0 = (v0 - mean) * r * g1[tid] + b1[tid];
    float y1 = (v1 - mean) * r * g1[tid + 256] + b1[tid + 256];
    h1[o + tid] = y0;
    h1[o + tid + 256] = y1;
    __nv_bfloat16 h0b = __float2bfloat16(y0);
    __nv_bfloat16 h1b = __float2bfloat16(y1);
    h1hi[o + tid] = h0b;
    h1hi[o + tid + 256] = h1b;
    h1lo[o + tid] = __float2bfloat16(y0 - __bfloat162float(h0b));
    h1lo[o + tid + 256] = __float2bfloat16(y1 - __bfloat162float(h1b));
}

// ============================================================================
// LN2 + output transpose (sums the two MLP2 split-K partials)
// ============================================================================
__global__ void ln2_kernel(const float* __restrict__ m2a, const float* __restrict__ m2b,
                           const float* __restrict__ h1,
                           const float* __restrict__ g2, const float* __restrict__ b2,
                           float* __restrict__ out)
{
    __shared__ float sm[16];
    int row = blockIdx.x, tid = threadIdx.x;
    int lane = tid & 31, w = tid >> 5;
    int l = row / B_, b = row % B_;
    size_t base = (size_t)row * C_;
    float v0 = m2a[base + tid] + m2b[base + tid] + h1[base + tid];
    float v1 = m2a[base + tid + 256] + m2b[base + tid + 256] + h1[base + tid + 256];
    float s = warpSum(v0 + v1);
    float q = warpSum(v0 * v0 + v1 * v1);
    if (lane == 0) { sm[w] = s; sm[8 + w] = q; }
    __syncthreads();
    float S = 0.f, Q = 0.f;
#pragma unroll
    for (int i = 0; i < 8; i++) { S += sm[i]; Q += sm[8 + i]; }
    float mean = S * (1.f / C_);
    float var = Q * (1.f / C_) - mean * mean;
    float r = rsqrtf(var + 1e-5f);
    size_t ob = (size_t)b * CL_ + l;
    out[ob + (size_t)tid * L_]         = (v0 - mean) * r * g2[tid] + b2[tid];
    out[ob + (size_t)(tid + 256) * L_] = (v1 - mean) * r * g2[tid + 256] + b2[tid + 256];
}

} // namespace

// ============================================================================
// Host launcher
// ============================================================================
extern "C" void kernel_launch(void* const* d_in, const int* in_sizes, int n_in,
                              void* d_out, int out_size)
{
    (void)in_sizes; (void)n_in; (void)out_size;
    float* scratch = nullptr;
    cudaGetSymbolAddress((void**)&scratch, d_scratch);

    const float* x       = (const float*)d_in[0];
    const float* theta_w = (const float*)d_in[1];
    const float* theta_b = (const float*)d_in[2];
    const float* phi_w   = (const float*)d_in[3];
    const float* phi_b   = (const float*)d_in[4];
    const float* g_w     = (const float*)d_in[5];
    const float* g_b     = (const float*)d_in[6];
    const float* wl_w    = (const float*)d_in[7];
    const float* wl_b    = (const float*)d_in[8];
    const float* wg_w    = (const float*)d_in[9];
    const float* wg_b    = (const float*)d_in[10];
    const float* conv1_w = (const float*)d_in[11];
    const float* conv1_b = (const float*)d_in[12];
    const float* conv2_w = (const float*)d_in[13];
    const float* conv2_b = (const float*)d_in[14];
    const float* ln1_g   = (const float*)d_in[15];
    const float* ln1_b   = (const float*)d_in[16];
    const float* ln2_g   = (const float*)d_in[17];
    const float* ln2_b   = (const float*)d_in[18];
    float* out = (float*)d_out;

    __nv_bfloat16* xtHi   = (__nv_bfloat16*)(scratch + OFF_XT_HI);
    __nv_bfloat16* xtLo   = (__nv_bfloat16*)(scratch + OFF_XT_LO);
    __nv_bfloat16* wqkvHi = (__nv_bfloat16*)(scratch + OFF_WQKV_HI);
    __nv_bfloat16* wqkvLo = (__nv_bfloat16*)(scratch + OFF_WQKV_LO);
    float* qkv_b          = scratch + OFF_QKV_B;
    __nv_bfloat16* wwgHi  = (__nv_bfloat16*)(scratch + OFF_WWG_HI);
    __nv_bfloat16* wwgLo  = (__nv_bfloat16*)(scratch + OFF_WWG_LO);
    __nv_bfloat16* c1wHi  = (__nv_bfloat16*)(scratch + OFF_C1WHI);
    __nv_bfloat16* c1wLo  = (__nv_bfloat16*)(scratch + OFF_C1WLO);
    __nv_bfloat16* c2wHi  = (__nv_bfloat16*)(scratch + OFF_C2WHI);
    __nv_bfloat16* c2wLo  = (__nv_bfloat16*)(scratch + OFF_C2WLO);
    __nv_bfloat16* qkvHi  = (__nv_bfloat16*)(scratch + OFF_QKVT_HI);
    __nv_bfloat16* qkvLo  = (__nv_bfloat16*)(scratch + OFF_QKVT_LO);
    float* Sbase = scratch + OFF_SG;                 // [split][sel][b][L][L]
    __nv_bfloat16* gpHi   = (__nv_bfloat16*)(scratch + OFF_GP_HI);
    __nv_bfloat16* gpLo   = (__nv_bfloat16*)(scratch + OFF_GP_LO);
    __nv_bfloat16* gg2Hi  = (__nv_bfloat16*)(scratch + OFF_GG2_HI);
    __nv_bfloat16* gg2Lo  = (__nv_bfloat16*)(scratch + OFF_GG2_LO);
    float* gbar  = scratch + OFF_GBAR;
    float* gate  = scratch + OFF_GATE;
    __nv_bfloat16* goHi   = (__nv_bfloat16*)(scratch + OFF_GOUTT_HI);
    __nv_bfloat16* goLo   = (__nv_bfloat16*)(scratch + OFF_GOUTT_LO);
    float* gout2T = scratch + OFF_GOUT2T;            // [2][B,L,C]
    float* h1    = scratch + OFF_H1;
    __nv_bfloat16* h1Hi   = (__nv_bfloat16*)(scratch + OFF_H1HI);
    __nv_bfloat16* h1Lo   = (__nv_bfloat16*)(scratch + OFF_H1LO);
    __nv_bfloat16* m1Hi   = (__nv_bfloat16*)(scratch + OFF_M1HI);
    __nv_bfloat16* m1Lo   = (__nv_bfloat16*)(scratch + OFF_M1LO);
    float* m2    = scratch + OFF_M2;                 // [2][NR,C]

    // BN=64, KB=64, 2 stages: SROW=144, stage=55296, total 110592 -> 2 CTAs/SM
    constexpr int SMEM64_K64_S2 = 110592;
    // BN=128, KB=32, 2 stages: 81920 -> 2 CTAs/SM
    constexpr int SMEM128_K32   = 81920;
    cudaFuncSetAttribute(gemm_mma<64, 0, 0, 1, 2, 64, 2>,  cudaFuncAttributeMaxDynamicSharedMemorySize, SMEM64_K64_S2);
    cudaFuncSetAttribute(gemm_mma<64, 1, 0, 0, 2, 64, 1>,  cudaFuncAttributeMaxDynamicSharedMemorySize, SMEM64_K64_S2);
    cudaFuncSetAttribute(gemm_mma<64, 0, 0, 0, 2, 64, 2>,  cudaFuncAttributeMaxDynamicSharedMemorySize, SMEM64_K64_S2);
    cudaFuncSetAttribute(gemm_mma<128, 1, 0, 0, 2, 32, 1>, cudaFuncAttributeMaxDynamicSharedMemorySize, SMEM128_K32);
    cudaFuncSetAttribute(gemm_mma<128, 1, 1, 0, 2, 32, 1>, cudaFuncAttributeMaxDynamicSharedMemorySize, SMEM128_K32);

    // 0) prep: splits + bias concat + x transpose
    prep_all<<<PREP_NSPLIT + PREP_NT, 256>>>(
        x, theta_w, phi_w, g_w, wg_w, conv1_w, conv2_w, theta_b, phi_b, g_b,
        wqkvHi, wqkvLo, wwgHi, wwgLo, c1wHi, c1wLo, c2wHi, c2wLo, qkv_b, xtHi, xtLo);

    // 1) fused qkv (BN=128)
    {
        dim3 grid(C3_ / 128, L_ / 128, B_);
        gemm_mma<128, 1, 0, 0, 2, 32, 1><<<grid, 256, SMEM128_K32>>>(
            xtHi, xtLo, wqkvHi, wqkvLo, qkv_b, nullptr, qkvHi, qkvLo,
            C_, C_, C_, C3_, (size_t)L_ * C_, 0, (size_t)L_ * C3_, 0, 0, 0, 1.f);
    }

    // 2) g transpose + gbar
    gtrans_gbar<<<dim3(L_ / 32, B_), 256>>>(qkvHi, qkvLo, gg2Hi, gg2Lo, gbar);

    // 3) Sg & Sl, split-K=2, ONE launch: grid z = 32 (split | sel | b)
    {
        dim3 grid(L_ / 64, L_ / 128, 4 * B_);
        gemm_mma<64, 0, 0, 1, 2, 64, 2><<<grid, 256, SMEM64_K64_S2>>>(
            qkvHi + C_, qkvLo + C_, qkvHi, qkvLo, nullptr, Sbase, nullptr, nullptr,
            C_, C3_, C3_, L_, (size_t)L_ * C3_, (size_t)L_ * C3_, (size_t)L_ * L_,
            (size_t)(2 * C_), BLL_, 2 * BLL_, SCALE_);
    }

    // 4) fused softmax + local gate (sums split partials)
    softmax_gate<<<dim3(L_, B_), 256>>>(
        Sbase, Sbase + 2 * BLL_,            // SgA, SgB
        Sbase + BLL_, Sbase + 3 * BLL_,     // SlA, SlB
        gbar, wl_w, wl_b, gpHi, gpLo, gate);

    // 5) goutT = gp @ gg2^T (hi/lo) ; gout2T = goutT @ wg^T + wg_b (split-K=2)
    {
        dim3 grid(C_ / 64, L_ / 128, B_);
        gemm_mma<64, 1, 0, 0, 2, 64, 1><<<grid, 256, SMEM64_K64_S2>>>(
            gpHi, gpLo, gg2Hi, gg2Lo, nullptr, nullptr, goHi, goLo,
            L_, L_, L_, C_, (size_t)L_ * L_, (size_t)CL_, (size_t)L_ * C_, 0, 0, 0, 1.f);
        dim3 grid2(C_ / 64, L_ / 128, 2 * B_);
        gemm_mma<64, 0, 0, 0, 2, 64, 2><<<grid2, 256, SMEM64_K64_S2>>>(
            goHi, goLo, wwgHi, wwgLo, wg_b, gout2T, nullptr, nullptr,
            C_, C_, C_, C_, (size_t)L_ * C_, 0, (size_t)L_ * C_, 0, 0,
            (size_t)B_ * CL_, 1.f);
    }

    // 6) LN1 -> h1 (sums wg partials)
    ln1_kernel<<<dim3(L_, B_), 256>>>(gout2T, gout2T + (size_t)B_ * CL_,
                                      gate, x, ln1_g, ln1_b, h1, h1Hi, h1Lo);

    // 7) MLP1
    {
        dim3 grid(C4_ / 128, NR_ / 128, 1);
        gemm_mma<128, 1, 1, 0, 2, 32, 1><<<grid, 256, SMEM128_K32>>>(
            h1Hi, h1Lo, c1wHi, c1wLo, conv1_b, nullptr, m1Hi, m1Lo,
            C_, C_, C_, C4_, 0, 0, 0, 0, 0, 0, 1.f);
    }

    // 8) MLP2, split-K=2
    {
        dim3 grid(C_ / 64, NR_ / 128, 2);
        gemm_mma<64, 0, 0, 0, 2, 64, 2><<<grid, 256, SMEM64_K64_S2>>>(
            m1Hi, m1Lo, c2wHi, c2wLo, conv2_b, m2, nullptr, nullptr,
            C4_, C4_, C4_, C_, 0, 0, 0, 0, 0, (size_t)NR_ * C_, 1.f);
    }

    // 9) LN2 + transpose out (sums MLP2 partials)
    ln2_kernel<<<NR_, 256>>>(m2, m2 + (size_t)NR_ * C_, h1, ln2_g, ln2_b, out);
}

// round 9
// speedup vs baseline: 1.0309x; 1.0309x over previous
#include <cuda_runtime.h>
#include <cuda_bf16.h>
#include <math.h>
#include <stdint.h>

// ============================================================================
// Problem constants
// ============================================================================
namespace {
constexpr int B_ = 8, C_ = 512, L_ = 256;
constexpr int CL_ = C_ * L_;           // 131072
constexpr int C3_ = 3 * C_;            // 1536
constexpr int C4_ = 4 * C_;            // 2048
constexpr int NR_ = L_ * B_;           // 2048
constexpr size_t BLL_ = (size_t)B_ * L_ * L_;
constexpr float SCALE_ = 0.044194173824159216f; // 512^-0.5

// ---------------- scratch offsets (float units) ----------------
constexpr size_t OFF_XT_HI   = 0;                                    // bf16 [B,L,C]
constexpr size_t OFF_XT_LO   = OFF_XT_HI   + (size_t)B_ * CL_ / 2;
constexpr size_t OFF_WQKV_HI = OFF_XT_LO   + (size_t)B_ * CL_ / 2;   // bf16 [3C,C]
constexpr size_t OFF_WQKV_LO = OFF_WQKV_HI + (size_t)C3_ * C_ / 2;
constexpr size_t OFF_QKV_B   = OFF_WQKV_LO + (size_t)C3_ * C_ / 2;   // f32 [1536]
constexpr size_t OFF_WWG_HI  = OFF_QKV_B   + 1536;
constexpr size_t OFF_WWG_LO  = OFF_WWG_HI  + (size_t)C_ * C_ / 2;
constexpr size_t OFF_C1WHI   = OFF_WWG_LO  + (size_t)C_ * C_ / 2;
constexpr size_t OFF_C1WLO   = OFF_C1WHI   + (size_t)C4_ * C_ / 2;
constexpr size_t OFF_C2WHI   = OFF_C1WLO   + (size_t)C4_ * C_ / 2;
constexpr size_t OFF_C2WLO   = OFF_C2WHI   + (size_t)C_ * C4_ / 2;
constexpr size_t OFF_QKVT_HI = OFF_C2WLO   + (size_t)C_ * C4_ / 2;   // bf16 [B,L,3C]
constexpr size_t OFF_QKVT_LO = OFF_QKVT_HI + (size_t)B_ * L_ * C3_ / 2;
constexpr size_t OFF_SG      = OFF_QKVT_LO + (size_t)B_ * L_ * C3_ / 2; // f32 [2][B,L,L]
constexpr size_t OFF_GP_HI   = OFF_SG      + 2 * BLL_;               // bf16 [B,L,L]
constexpr size_t OFF_GP_LO   = OFF_GP_HI   + BLL_ / 2;
constexpr size_t OFF_GG2_HI  = OFF_GP_LO   + BLL_ / 2;               // bf16 [B,C,L]
constexpr size_t OFF_GG2_LO  = OFF_GG2_HI  + (size_t)B_ * CL_ / 2;
constexpr size_t OFF_GBAR    = OFF_GG2_LO  + (size_t)B_ * CL_ / 2;
constexpr size_t OFF_GATE    = OFF_GBAR    + (size_t)B_ * L_;
constexpr size_t OFF_GOUTT_HI= OFF_GATE    + (size_t)B_ * L_;        // bf16 [B,L,C]
constexpr size_t OFF_GOUTT_LO= OFF_GOUTT_HI+ (size_t)B_ * CL_ / 2;
constexpr size_t OFF_GOUT2T  = OFF_GOUTT_LO+ (size_t)B_ * CL_ / 2;   // f32 [B,L,C]
constexpr size_t OFF_H1      = OFF_GOUT2T  + (size_t)B_ * CL_;       // f32 [NR,C]
constexpr size_t OFF_H1HI    = OFF_H1      + (size_t)NR_ * C_;
constexpr size_t OFF_H1LO    = OFF_H1HI    + (size_t)NR_ * C_ / 2;
constexpr size_t OFF_M1HI    = OFF_H1LO    + (size_t)NR_ * C_ / 2;   // bf16 [NR,C4]
constexpr size_t OFF_M1LO    = OFF_M1HI    + (size_t)NR_ * C4_ / 2;
constexpr size_t OFF_M2      = OFF_M1LO    + (size_t)NR_ * C4_ / 2;  // f32 [NR,C]
constexpr size_t SCRATCH_TOTAL = OFF_M2    + (size_t)NR_ * C_;
} // namespace

__device__ __align__(256) float d_scratch[SCRATCH_TOTAL];

// ============================================================================
// PTX helpers — sm_80-era only (mma.sync / ldmatrix / cp.async).
// ============================================================================
__device__ __forceinline__ uint32_t smem_to_u32(const void* p) {
    uint32_t a;
    asm("{ .reg .u64 t; cvta.to.shared.u64 t, %1; cvt.u32.u64 %0, t; }" : "=r"(a) : "l"(p));
    return a;
}
__device__ __forceinline__ void ldmat4(uint32_t (&r)[4], uint32_t addr) {
    asm volatile("ldmatrix.sync.aligned.m8n8.x4.shared.b16 {%0,%1,%2,%3}, [%4];"
                 : "=r"(r[0]), "=r"(r[1]), "=r"(r[2]), "=r"(r[3]) : "r"(addr));
}
__device__ __forceinline__ void mma16816(float (&d)[4], const uint32_t (&a)[4], const uint32_t b0, const uint32_t b1) {
    asm volatile("mma.sync.aligned.m16n8k16.row.col.f32.bf16.bf16.f32 "
                 "{%0,%1,%2,%3}, {%4,%5,%6,%7}, {%8,%9}, {%0,%1,%2,%3};"
                 : "+f"(d[0]), "+f"(d[1]), "+f"(d[2]), "+f"(d[3])
                 : "r"(a[0]), "r"(a[1]), "r"(a[2]), "r"(a[3]), "r"(b0), "r"(b1));
}
__device__ __forceinline__ void cp16(uint32_t saddr, const void* g) {
    asm volatile("cp.async.cg.shared.global [%0], [%1], 16;" :: "r"(saddr), "l"(g));
}
#define CP_COMMIT() asm volatile("cp.async.commit_group;" ::: "memory")
template <int N>
__device__ __forceinline__ void cp_wait() {
    asm volatile("cp.async.wait_group %0;" :: "n"(N) : "memory");
}

namespace {

__device__ __forceinline__ float warpSum(float v) {
#pragma unroll
    for (int o = 16; o; o >>= 1) v += __shfl_xor_sync(0xffffffffu, v, o);
    return v;
}
__device__ __forceinline__ float warpMax(float v) {
#pragma unroll
    for (int o = 16; o; o >>= 1) v = fmaxf(v, __shfl_xor_sync(0xffffffffu, v, o));
    return v;
}
__device__ __forceinline__ float mishf(float v) {
    float sp = fmaxf(v, 0.f) + log1pf(__expf(-fabsf(v)));
    return v * tanhf(sp);
}

// ============================================================================
// bf16-split tensor-core GEMM, multistage cp.async pipeline.
// NT: A [M,K] K-contig (lda) hi/lo ; B [N,K] K-contig (ldb) hi/lo
// D = Ahi·Bhi^T + Ahi·Blo^T + Alo·Bhi^T (fp32 accum)
// v = scale*D (+ biasN); ACT=1 -> mish; OUTFMT 0: fp32; 1: bf16 hi/lo.
// FUSE=1: z encodes (sel = z>>3, b = z&7); B += sel*selB, out += sel*selO.
// WM = warps along M (2 -> 256 thr, warp tile 64xWN; 4 -> 512 thr, 32xWN).
// ============================================================================
template <int BN, int OUTFMT, int ACT, int FUSE, int STAGES, int KB, int WM>
__global__ void __launch_bounds__(WM * 128) gemm_mma(
    const __nv_bfloat16* __restrict__ Ahi, const __nv_bfloat16* __restrict__ Alo,
    const __nv_bfloat16* __restrict__ Bhi, const __nv_bfloat16* __restrict__ Blo,
    const float* __restrict__ biasN,
    float* __restrict__ outF,
    __nv_bfloat16* __restrict__ outHi, __nv_bfloat16* __restrict__ outLo,
    int K, int lda, int ldb, int ldOut,
    size_t sA, size_t sB, size_t sO, size_t selB, size_t selO, float scale)
{
    constexpr int BM = 128;
    constexpr int TPB = WM * 128;            // 4 warps in N always
    constexpr int MI = BM / (WM * 16);       // m16 frags per warp (4 or 2)
    constexpr int SROW = KB * 2 + 16;        // bytes/row: data + 16B pad
    constexpr int CHR = KB / 8;              // 16B chunks per row
    constexpr int ATILE = BM * SROW;
    constexpr int BTILE = BN * SROW;
    constexpr int STAGE = 2 * ATILE + 2 * BTILE;
    constexpr int WN = BN / 4;
    constexpr int NFRAG = WN / 8;
    constexpr int NKS = KB / 16;             // k16 steps per chunk

    extern __shared__ char smem[];
    const uint32_t sb = smem_to_u32(smem);
    const int tid = threadIdx.x, lane = tid & 31, wid = tid >> 5;
    const int wm = wid & (WM - 1), wn = wid / WM;
    const int m0 = blockIdx.y * BM, n0 = blockIdx.x * BN;
    const int z = blockIdx.z;
    const int b = FUSE ? (z & 7) : z;
    const int sel = FUSE ? (z >> 3) : 0;

    Ahi += (size_t)b * sA; Alo += (size_t)b * sA;
    Bhi += (size_t)b * sB + (size_t)sel * selB;
    Blo += (size_t)b * sB + (size_t)sel * selB;
    if (OUTFMT == 0) outF += (size_t)b * sO + (size_t)sel * selO;
    else { outHi += (size_t)b * sO + (size_t)sel * selO; outLo += (size_t)b * sO + (size_t)sel * selO; }

    float acc[MI][NFRAG][4];
#pragma unroll
    for (int i = 0; i < MI; i++)
#pragma unroll
        for (int j = 0; j < NFRAG; j++)
#pragma unroll
            for (int q = 0; q < 4; q++) acc[i][j][q] = 0.f;

    auto load_stage = [&](int ch, int st) {
        const int k0 = ch * KB;
        const uint32_t base = sb + st * STAGE;
#pragma unroll
        for (int c = tid; c < BM * CHR; c += TPB) {
            int r = c / CHR, cc = c % CHR;
            size_t go = (size_t)(m0 + r) * lda + k0 + cc * 8;
            uint32_t so = base + r * SROW + cc * 16;
            cp16(so, Ahi + go);
            cp16(so + ATILE, Alo + go);
        }
#pragma unroll
        for (int c = tid; c < BN * CHR; c += TPB) {
            int r = c / CHR, cc = c % CHR;
            size_t go = (size_t)(n0 + r) * ldb + k0 + cc * 8;
            uint32_t so = base + 2 * ATILE + r * SROW + cc * 16;
            cp16(so, Bhi + go);
            cp16(so + BTILE, Blo + go);
        }
        CP_COMMIT();
    };

    const int nch = K / KB;
#pragma unroll
    for (int s = 0; s < STAGES - 1; s++) load_stage(s, s);

    int cs = 0;
    int ps = (STAGES - 1) % STAGES;
    for (int ch = 0; ch < nch; ch++) {
        cp_wait<STAGES - 2>();
        __syncthreads();
        const int pf = ch + STAGES - 1;
        if (pf < nch) load_stage(pf, ps);
        else CP_COMMIT();

        const uint32_t aBase = sb + cs * STAGE;
        const uint32_t bBase = aBase + 2 * ATILE;
#pragma unroll
        for (int ks = 0; ks < NKS; ks++) {
            const uint32_t colOff = (uint32_t)(ks * 2 + (lane >> 4)) * 16;
            uint32_t a_hi[MI][4], a_lo[MI][4];
#pragma unroll
            for (int mi = 0; mi < MI; mi++) {
                uint32_t addr = aBase + (uint32_t)(wm * (MI * 16) + mi * 16 + (lane & 15)) * SROW + colOff;
                ldmat4(a_hi[mi], addr);
                ldmat4(a_lo[mi], addr + ATILE);
            }
#pragma unroll
            for (int nt = 0; nt < NFRAG / 2; nt++) {
                uint32_t addr = bBase + (uint32_t)(wn * WN + nt * 16 + (lane & 15)) * SROW + colOff;
                uint32_t bh[4], bl[4];
                ldmat4(bh, addr);
                ldmat4(bl, addr + BTILE);
#pragma unroll
                for (int half = 0; half < 2; half++) {
                    const int ni = nt * 2 + half;
#pragma unroll
                    for (int mi = 0; mi < MI; mi++) {
                        mma16816(acc[mi][ni], a_hi[mi], bh[half], bh[2 + half]);
                        mma16816(acc[mi][ni], a_hi[mi], bl[half], bl[2 + half]);
                        mma16816(acc[mi][ni], a_lo[mi], bh[half], bh[2 + half]);
                    }
                }
            }
        }
        cs = (cs + 1 == STAGES) ? 0 : cs + 1;
        ps = (ps + 1 == STAGES) ? 0 : ps + 1;
    }

    // ---------------- epilogue ----------------
    const int g = lane >> 2, tg = lane & 3;
#pragma unroll
    for (int mi = 0; mi < MI; mi++) {
#pragma unroll
        for (int ni = 0; ni < NFRAG; ni++) {
            const int col = n0 + wn * WN + ni * 8 + tg * 2;
            const float b0 = biasN ? biasN[col] : 0.f;
            const float b1 = biasN ? biasN[col + 1] : 0.f;
#pragma unroll
            for (int h = 0; h < 2; h++) {
                const int row = m0 + wm * (MI * 16) + mi * 16 + g + h * 8;
                float v0 = acc[mi][ni][h * 2 + 0] * scale + b0;
                float v1 = acc[mi][ni][h * 2 + 1] * scale + b1;
                if (ACT == 1) { v0 = mishf(v0); v1 = mishf(v1); }
                const size_t o = (size_t)row * ldOut + col;
                if (OUTFMT == 1) {
                    __nv_bfloat16 h0 = __float2bfloat16(v0);
                    __nv_bfloat16 h1 = __float2bfloat16(v1);
                    __nv_bfloat162 hp; hp.x = h0; hp.y = h1;
                    __nv_bfloat162 lp;
                    lp.x = __float2bfloat16(v0 - __bfloat162float(h0));
                    lp.y = __float2bfloat16(v1 - __bfloat162float(h1));
                    *(__nv_bfloat162*)(outHi + o) = hp;
                    *(__nv_bfloat162*)(outLo + o) = lp;
                } else {
                    float2 fp; fp.x = v0; fp.y = v1;
                    *(float2*)(outF + o) = fp;
                }
            }
        }
    }
}

// ============================================================================
// prep_all: ONE launch = all weight splits + qkv bias concat + x transpose.
// ============================================================================
constexpr int PREP_SPLIT_TOTAL = 3 * C_ * C_ + C_ * C_ + C4_ * C_ + C_ * C4_ + C3_;
constexpr int PREP_NSPLIT = (PREP_SPLIT_TOTAL + 255) / 256;
constexpr int PREP_NT = (L_ / 32) * (C_ / 32) * B_;

__global__ void prep_all(const float* __restrict__ x,
                         const float* __restrict__ tw, const float* __restrict__ pw,
                         const float* __restrict__ gw, const float* __restrict__ wgw,
                         const float* __restrict__ c1w, const float* __restrict__ c2w,
                         const float* __restrict__ tb, const float* __restrict__ pb,
                         const float* __restrict__ gb,
                         __nv_bfloat16* __restrict__ qkvHi, __nv_bfloat16* __restrict__ qkvLo,
                         __nv_bfloat16* __restrict__ wgHi, __nv_bfloat16* __restrict__ wgLo,
                         __nv_bfloat16* __restrict__ c1Hi, __nv_bfloat16* __restrict__ c1Lo,
                         __nv_bfloat16* __restrict__ c2Hi, __nv_bfloat16* __restrict__ c2Lo,
                         float* __restrict__ qkvb,
                         __nv_bfloat16* __restrict__ xtHi, __nv_bfloat16* __restrict__ xtLo)
{
    __shared__ float t[32][33];
    const int bid = blockIdx.x;
    if (bid < PREP_NSPLIT) {
        constexpr int NW = C_ * C_;
        constexpr int N1 = 3 * NW;
        constexpr int N2 = N1 + NW;
        constexpr int N3 = N2 + C4_ * C_;
        constexpr int N4 = N3 + C_ * C4_;
        const int i = bid * 256 + threadIdx.x;
        float v;
        __nv_bfloat16 *hi, *lo;
        int j;
        if (i < N1) {
            j = i & (NW - 1);
            const float* src = (i < NW) ? tw : (i < 2 * NW ? pw : gw);
            v = src[j]; hi = qkvHi + i; lo = qkvLo + i;
        } else if (i < N2) {
            j = i - N1; v = wgw[j]; hi = wgHi + j; lo = wgLo + j;
        } else if (i < N3) {
            j = i - N2; v = c1w[j]; hi = c1Hi + j; lo = c1Lo + j;
        } else if (i < N4) {
            j = i - N3; v = c2w[j]; hi = c2Hi + j; lo = c2Lo + j;
        } else if (i < N4 + C3_) {
            j = i - N4;
            qkvb[j] = (j < C_) ? tb[j] : (j < 2 * C_ ? pb[j - C_] : gb[j - 2 * C_]);
            return;
        } else return;
        __nv_bfloat16 h = __float2bfloat16(v);
        *hi = h;
        *lo = __float2bfloat16(v - __bfloat162float(h));
    } else {
        const int tI = bid - PREP_NSPLIT;
        const int b = tI >> 7;
        const int rem = tI & 127;
        const int c0 = (rem & 15) * 32;
        const int l0 = (rem >> 4) * 32;
        const int tx = threadIdx.x & 31, ty = threadIdx.x >> 5;
        const float* xb = x + (size_t)b * CL_;
#pragma unroll
        for (int j = 0; j < 4; j++)
            t[ty + j * 8][tx] = xb[(size_t)(c0 + ty + j * 8) * L_ + l0 + tx];
        __syncthreads();
#pragma unroll
        for (int j = 0; j < 4; j++) {
            int l = l0 + ty + j * 8;
            float v = t[tx][ty + j * 8];
            __nv_bfloat16 h = __float2bfloat16(v);
            size_t o = ((size_t)b * L_ + l) * C_ + c0 + tx;
            xtHi[o] = h;
            xtLo[o] = __float2bfloat16(v - __bfloat162float(h));
        }
    }
}

// ============================================================================
// transpose_g + gbar in ONE kernel. grid (L/32, B), 256 threads.
// ============================================================================
__global__ void gtrans_gbar(const __nv_bfloat16* __restrict__ inHi,
                            const __nv_bfloat16* __restrict__ inLo,
                            __nv_bfloat16* __restrict__ outHi,
                            __nv_bfloat16* __restrict__ outLo,
                            float* __restrict__ gbar)
{
    __shared__ __nv_bfloat16 th[32][34];
    __shared__ __nv_bfloat16 tl[32][34];
    const int b = blockIdx.y;
    const int l0 = blockIdx.x * 32;
    const int tx = threadIdx.x & 31, ty = threadIdx.x >> 5;

    for (int ct = 0; ct < 16; ct++) {
        const int c0 = ct * 32;
#pragma unroll
        for (int j = 0; j < 4; j++) {
            size_t idx = ((size_t)b * L_ + l0 + ty + j * 8) * C3_ + 2 * C_ + c0 + tx;
            th[ty + j * 8][tx] = inHi[idx];
            tl[ty + j * 8][tx] = inLo[idx];
        }
        __syncthreads();
#pragma unroll
        for (int j = 0; j < 4; j++) {
            int c = c0 + ty + j * 8;
            size_t o = ((size_t)b * C_ + c) * L_ + l0 + tx;
            outHi[o] = th[tx][ty + j * 8];
            outLo[o] = tl[tx][ty + j * 8];
        }
        __syncthreads();
    }

    const int w = threadIdx.x >> 5, lane = threadIdx.x & 31;
#pragma unroll
    for (int i = 0; i < 4; i++) {
        const int l = l0 + w * 4 + i;
        const size_t base = ((size_t)b * L_ + l) * C3_ + 2 * C_;
        float s = 0.f;
#pragma unroll
        for (int c = lane; c < C_; c += 32)
            s += __bfloat162float(inHi[base + c]) + __bfloat162float(inLo[base + c]);
        s = warpSum(s);
        if (lane == 0) gbar[b * L_ + l] = s * (1.f / C_);
    }
}

// ============================================================================
// Fused: softmax(Sg row) -> gp hi/lo  AND  banded local gate from Sl row.
// ============================================================================
__global__ void softmax_gate(const float* __restrict__ Sg,
                             const float* __restrict__ Sl,
                             const float* __restrict__ gbar,
                             const float* __restrict__ wlw,
                             const float* __restrict__ wlb,
                             __nv_bfloat16* __restrict__ pHi,
                             __nv_bfloat16* __restrict__ pLo,
                             float* __restrict__ gate)
{
    __shared__ float sm[16];
    const int l = blockIdx.x, b = blockIdx.y, tid = threadIdx.x;
    const int lane = tid & 31, w = tid >> 5;
    const size_t row = (size_t)b * L_ + l;

    float v = Sg[row * L_ + tid];
    float m = warpMax(v);
    if (lane == 0) sm[w] = m;
    __syncthreads();
    float M = -1e30f;
#pragma unroll
    for (int i = 0; i < 8; i++) M = fmaxf(M, sm[i]);
    float e = __expf(v - M);
    float s = warpSum(e);
    if (lane == 0) sm[8 + w] = s;
    __syncthreads();
    float T = 0.f;
#pragma unroll
    for (int i = 0; i < 8; i++) T += sm[8 + i];
    float p = e / T;
    __nv_bfloat16 h = __float2bfloat16(p);
    pHi[row * L_ + tid] = h;
    pLo[row * L_ + tid] = __float2bfloat16(p - __bfloat162float(h));

    if (w == 0) {
        const float* srow = Sl + row * L_;
        const float* gb = gbar + (size_t)b * L_;
        int m0 = l + lane - 32;
        int m1 = l + lane;
        bool v0 = (m0 >= 0) && (m0 < L_);
        bool v1 = (m1 >= 0) && (m1 < L_);
        float s0 = v0 ? srow[m0] : 0.f;
        float s1 = v1 ? srow[m1] : 0.f;
        float g0 = v0 ? gb[m0] : 0.f;
        float g1 = v1 ? gb[m1] : 0.f;
        float mx = warpMax(fmaxf(s0, s1));
        float e0 = __expf(s0 - mx), e1 = __expf(s1 - mx);
        float num = warpSum(e0 * g0 + e1 * g1);
        float den = warpSum(e0 + e1);
        if (lane == 0) {
            float pooled = num / den;
            float z = wlw[0] * pooled + wlb[0];
            gate[b * L_ + l] = 1.f / (1.f + __expf(-z));
        }
    }
}

// ============================================================================
// LN1: h = gout2T*gate + x ; h1 fp32 + bf16 hi/lo at row (l*B+b), [*,C]
// ============================================================================
__global__ void ln1_kernel(const float* __restrict__ gout2T,
                           const float* __restrict__ gate,
                           const float* __restrict__ x,
                           const float* __restrict__ g1, const float* __restrict__ b1,
                           float* __restrict__ h1,
                           __nv_bfloat16* __restrict__ h1hi,
                           __nv_bfloat16* __restrict__ h1lo)
{
    __shared__ float sm[16];
    int l = blockIdx.x, b = blockIdx.y, tid = threadIdx.x;
    int lane = tid & 31, w = tid >> 5;
    float gt = gate[b * L_ + l];
    size_t gbase = ((size_t)b * L_ + l) * C_;
    size_t xbase = (size_t)b * CL_ + l;
    float v0 = fmaf(gout2T[gbase + tid], gt, x[xbase + (size_t)tid * L_]);
    float v1 = fmaf(gout2T[gbase + tid + 256], gt, x[xbase + (size_t)(tid + 256) * L_]);
    float s = warpSum(v0 + v1);
    float q = warpSum(v0 * v0 + v1 * v1);
    if (lane == 0) { sm[w] = s; sm[8 + w] = q; }
    __syncthreads();
    float S = 0.f, Q = 0.f;
#pragma unroll
    for (int i = 0; i < 8; i++) { S += sm[i]; Q += sm[8 + i]; }
    float mean = S * (1.f / C_);
    float var = Q * (1.f / C_) - mean * mean;
    float r = rsqrtf(var + 1e-5f);
    size_t o = ((size_t)l * B_ + b) * C_;
    float y0 = (v0 - mean) * r * g1[tid] + b1[tid];
    float y1 = (v1 - mean) * r * g1[tid + 256] + b1[tid + 256];
    h1[o + tid] = y0;
    h1[o + tid + 256] = y1;
    __nv_bfloat16 h0b = __float2bfloat16(y0);
    __nv_bfloat16 h1b = __float2bfloat16(y1);
    h1hi[o + tid] = h0b;
    h1hi[o + tid + 256] = h1b;
    h1lo[o + tid] = __float2bfloat16(y0 - __bfloat162float(h0b));
    h1lo[o + tid + 256] = __float2bfloat16(y1 - __bfloat162float(h1b));
}

// ============================================================================
// LN2 + output transpose
// ============================================================================
__global__ void ln2_kernel(const float* __restrict__ m2,
                           const float* __restrict__ h1,
                           const float* __restrict__ g2, const float* __restrict__ b2,
                           float* __restrict__ out)
{
    __shared__ float sm[16];
    int row = blockIdx.x, tid = threadIdx.x;
    int lane = tid & 31, w = tid >> 5;
    int l = row / B_, b = row % B_;
    size_t base = (size_t)row * C_;
    float v0 = m2[base + tid] + h1[base + tid];
    float v1 = m2[base + tid + 256] + h1[base + tid + 256];
    float s = warpSum(v0 + v1);
    float q = warpSum(v0 * v0 + v1 * v1);
    if (lane == 0) { sm[w] = s; sm[8 + w] = q; }
    __syncthreads();
    float S = 0.f, Q = 0.f;
#pragma unroll
    for (int i = 0; i < 8; i++) { S += sm[i]; Q += sm[8 + i]; }
    float mean = S * (1.f / C_);
    float var = Q * (1.f / C_) - mean * mean;
    float r = rsqrtf(var + 1e-5f);
    size_t ob = (size_t)b * CL_ + l;
    out[ob + (size_t)tid * L_]         = (v0 - mean) * r * g2[tid] + b2[tid];
    out[ob + (size_t)(tid + 256) * L_] = (v1 - mean) * r * g2[tid + 256] + b2[tid + 256];
}

} // namespace

// ============================================================================
// Host launcher
// ============================================================================
extern "C" void kernel_launch(void* const* d_in, const int* in_sizes, int n_in,
                              void* d_out, int out_size)
{
    (void)in_sizes; (void)n_in; (void)out_size;
    float* scratch = nullptr;
    cudaGetSymbolAddress((void**)&scratch, d_scratch);

    const float* x       = (const float*)d_in[0];
    const float* theta_w = (const float*)d_in[1];
    const float* theta_b = (const float*)d_in[2];
    const float* phi_w   = (const float*)d_in[3];
    const float* phi_b   = (const float*)d_in[4];
    const float* g_w     = (const float*)d_in[5];
    const float* g_b     = (const float*)d_in[6];
    const float* wl_w    = (const float*)d_in[7];
    const float* wl_b    = (const float*)d_in[8];
    const float* wg_w    = (const float*)d_in[9];
    const float* wg_b    = (const float*)d_in[10];
    const float* conv1_w = (const float*)d_in[11];
    const float* conv1_b = (const float*)d_in[12];
    const float* conv2_w = (const float*)d_in[13];
    const float* conv2_b = (const float*)d_in[14];
    const float* ln1_g   = (const float*)d_in[15];
    const float* ln1_b   = (const float*)d_in[16];
    const float* ln2_g   = (const float*)d_in[17];
    const float* ln2_b   = (const float*)d_in[18];
    float* out = (float*)d_out;

    __nv_bfloat16* xtHi   = (__nv_bfloat16*)(scratch + OFF_XT_HI);
    __nv_bfloat16* xtLo   = (__nv_bfloat16*)(scratch + OFF_XT_LO);
    __nv_bfloat16* wqkvHi = (__nv_bfloat16*)(scratch + OFF_WQKV_HI);
    __nv_bfloat16* wqkvLo = (__nv_bfloat16*)(scratch + OFF_WQKV_LO);
    float* qkv_b          = scratch + OFF_QKV_B;
    __nv_bfloat16* wwgHi  = (__nv_bfloat16*)(scratch + OFF_WWG_HI);
    __nv_bfloat16* wwgLo  = (__nv_bfloat16*)(scratch + OFF_WWG_LO);
    __nv_bfloat16* c1wHi  = (__nv_bfloat16*)(scratch + OFF_C1WHI);
    __nv_bfloat16* c1wLo  = (__nv_bfloat16*)(scratch + OFF_C1WLO);
    __nv_bfloat16* c2wHi  = (__nv_bfloat16*)(scratch + OFF_C2WHI);
    __nv_bfloat16* c2wLo  = (__nv_bfloat16*)(scratch + OFF_C2WLO);
    __nv_bfloat16* qkvHi  = (__nv_bfloat16*)(scratch + OFF_QKVT_HI);
    __nv_bfloat16* qkvLo  = (__nv_bfloat16*)(scratch + OFF_QKVT_LO);
    float* Sg    = scratch + OFF_SG;
    __nv_bfloat16* gpHi   = (__nv_bfloat16*)(scratch + OFF_GP_HI);
    __nv_bfloat16* gpLo   = (__nv_bfloat16*)(scratch + OFF_GP_LO);
    __nv_bfloat16* gg2Hi  = (__nv_bfloat16*)(scratch + OFF_GG2_HI);
    __nv_bfloat16* gg2Lo  = (__nv_bfloat16*)(scratch + OFF_GG2_LO);
    float* gbar  = scratch + OFF_GBAR;
    float* gate  = scratch + OFF_GATE;
    __nv_bfloat16* goHi   = (__nv_bfloat16*)(scratch + OFF_GOUTT_HI);
    __nv_bfloat16* goLo   = (__nv_bfloat16*)(scratch + OFF_GOUTT_LO);
    float* gout2T = scratch + OFF_GOUT2T;
    float* h1    = scratch + OFF_H1;
    __nv_bfloat16* h1Hi   = (__nv_bfloat16*)(scratch + OFF_H1HI);
    __nv_bfloat16* h1Lo   = (__nv_bfloat16*)(scratch + OFF_H1LO);
    __nv_bfloat16* m1Hi   = (__nv_bfloat16*)(scratch + OFF_M1HI);
    __nv_bfloat16* m1Lo   = (__nv_bfloat16*)(scratch + OFF_M1LO);
    float* m2    = scratch + OFF_M2;

    // BN=64, KB=64, 3 stages, WM=4 (512 thr): SROW=144, stage=55296, x3
    constexpr int SMEM64_K64  = 165888;
    // BN=128, KB=32, 2 stages, WM=2 (256 thr): stage=40960, x2 -> 2 CTAs/SM
    constexpr int SMEM128_K32 = 81920;
    cudaFuncSetAttribute(gemm_mma<64, 0, 0, 1, 3, 64, 4>,  cudaFuncAttributeMaxDynamicSharedMemorySize, SMEM64_K64);
    cudaFuncSetAttribute(gemm_mma<64, 1, 0, 0, 3, 64, 4>,  cudaFuncAttributeMaxDynamicSharedMemorySize, SMEM64_K64);
    cudaFuncSetAttribute(gemm_mma<64, 0, 0, 0, 3, 64, 4>,  cudaFuncAttributeMaxDynamicSharedMemorySize, SMEM64_K64);
    cudaFuncSetAttribute(gemm_mma<128, 1, 0, 0, 2, 32, 2>, cudaFuncAttributeMaxDynamicSharedMemorySize, SMEM128_K32);
    cudaFuncSetAttribute(gemm_mma<128, 1, 1, 0, 2, 32, 2>, cudaFuncAttributeMaxDynamicSharedMemorySize, SMEM128_K32);

    // 0) prep: splits + bias concat + x transpose
    prep_all<<<PREP_NSPLIT + PREP_NT, 256>>>(
        x, theta_w, phi_w, g_w, wg_w, conv1_w, conv2_w, theta_b, phi_b, g_b,
        wqkvHi, wqkvLo, wwgHi, wwgLo, c1wHi, c1wLo, c2wHi, c2wLo, qkv_b, xtHi, xtLo);

    // 1) fused qkv (BN=128, 256 thr, 2 CTAs/SM)
    {
        dim3 grid(C3_ / 128, L_ / 128, B_);
        gemm_mma<128, 1, 0, 0, 2, 32, 2><<<grid, 256, SMEM128_K32>>>(
            xtHi, xtLo, wqkvHi, wqkvLo, qkv_b, nullptr, qkvHi, qkvLo,
            C_, C_, C_, C3_, (size_t)L_ * C_, 0, (size_t)L_ * C3_, 0, 0, 1.f);
    }

    // 2) g transpose + gbar
    gtrans_gbar<<<dim3(L_ / 32, B_), 256>>>(qkvHi, qkvLo, gg2Hi, gg2Lo, gbar);

    // 3) Sg & Sl in ONE launch (512 thr, 16 warps/CTA)
    {
        dim3 grid(L_ / 64, L_ / 128, 2 * B_);
        gemm_mma<64, 0, 0, 1, 3, 64, 4><<<grid, 512, SMEM64_K64>>>(
            qkvHi + C_, qkvLo + C_, qkvHi, qkvLo, nullptr, Sg, nullptr, nullptr,
            C_, C3_, C3_, L_, (size_t)L_ * C3_, (size_t)L_ * C3_, (size_t)L_ * L_,
            (size_t)(2 * C_), BLL_, SCALE_);
    }

    // 4) fused softmax + local gate
    softmax_gate<<<dim3(L_, B_), 256>>>(Sg, Sg + BLL_, gbar,
                                        wl_w, wl_b, gpHi, gpLo, gate);

    // 5) goutT = gp @ gg2^T (hi/lo) ; gout2T = goutT @ wg^T + wg_b (fp32)
    {
        dim3 grid(C_ / 64, L_ / 128, B_);
        gemm_mma<64, 1, 0, 0, 3, 64, 4><<<grid, 512, SMEM64_K64>>>(
            gpHi, gpLo, gg2Hi, gg2Lo, nullptr, nullptr, goHi, goLo,
            L_, L_, L_, C_, (size_t)L_ * L_, (size_t)CL_, (size_t)L_ * C_, 0, 0, 1.f);
        gemm_mma<64, 0, 0, 0, 3, 64, 4><<<grid, 512, SMEM64_K64>>>(
            goHi, goLo, wwgHi, wwgLo, wg_b, gout2T, nullptr, nullptr,
            C_, C_, C_, C_, (size_t)L_ * C_, 0, (size_t)L_ * C_, 0, 0, 1.f);
    }

    // 6) LN1 -> h1 (fp32 + hi/lo)
    ln1_kernel<<<dim3(L_, B_), 256>>>(gout2T, gate, x, ln1_g, ln1_b, h1, h1Hi, h1Lo);

    // 7) MLP1 (BN=128, 256 thr)
    {
        dim3 grid(C4_ / 128, NR_ / 128, 1);
        gemm_mma<128, 1, 1, 0, 2, 32, 2><<<grid, 256, SMEM128_K32>>>(
            h1Hi, h1Lo, c1wHi, c1wLo, conv1_b, nullptr, m1Hi, m1Lo,
            C_, C_, C_, C4_, 0, 0, 0, 0, 0, 1.f);
    }

    // 8) MLP2 (512 thr, 16 warps/CTA)
    {
        dim3 grid(C_ / 64, NR_ / 128, 1);
        gemm_mma<64, 0, 0, 0, 3, 64, 4><<<grid, 512, SMEM64_K64>>>(
            m1Hi, m1Lo, c2wHi, c2wLo, conv2_b, m2, nullptr, nullptr,
            C4_, C4_, C4_, C_, 0, 0, 0, 0, 0, 1.f);
    }

    // 9) LN2 + transpose out
    ln2_kernel<<<NR_, 256>>>(m2, h1, ln2_g, ln2_b, out);
}

// round 10
// speedup vs baseline: 1.3026x; 1.2637x over previous
#include <cuda_runtime.h>
#include <cuda_fp16.h>
#include <math.h>
#include <stdint.h>

// ============================================================================
// Problem constants
// ============================================================================
namespace {
constexpr int B_ = 8, C_ = 512, L_ = 256;
constexpr int CL_ = C_ * L_;           // 131072
constexpr int C3_ = 3 * C_;            // 1536
constexpr int C4_ = 4 * C_;            // 2048
constexpr int NR_ = L_ * B_;           // 2048
constexpr size_t BLL_ = (size_t)B_ * L_ * L_;
constexpr float SCALE_ = 0.044194173824159216f; // 512^-0.5
constexpr float WSC_ = 64.f;            // weight pre-scale (fp16 subnormal guard)
constexpr float WINV_ = 0.015625f;      // 1/64

// ---------------- scratch offsets (float units) ----------------
constexpr size_t OFF_XT_HI   = 0;                                    // f16 [B,L,C]
constexpr size_t OFF_WQKV_HI = OFF_XT_HI   + (size_t)B_ * CL_ / 2;   // f16 [3C,C]
constexpr size_t OFF_WQKV_LO = OFF_WQKV_HI + (size_t)C3_ * C_ / 2;
constexpr size_t OFF_QKV_B   = OFF_WQKV_LO + (size_t)C3_ * C_ / 2;   // f32 [1536]
constexpr size_t OFF_WWG_HI  = OFF_QKV_B   + 1536;
constexpr size_t OFF_WWG_LO  = OFF_WWG_HI  + (size_t)C_ * C_ / 2;
constexpr size_t OFF_C1WHI   = OFF_WWG_LO  + (size_t)C_ * C_ / 2;
constexpr size_t OFF_C1WLO   = OFF_C1WHI   + (size_t)C4_ * C_ / 2;
constexpr size_t OFF_C2WHI   = OFF_C1WLO   + (size_t)C4_ * C_ / 2;
constexpr size_t OFF_C2WLO   = OFF_C2WHI   + (size_t)C_ * C4_ / 2;
constexpr size_t OFF_QKVT_HI = OFF_C2WLO   + (size_t)C_ * C4_ / 2;   // f16 [B,L,3C]
constexpr size_t OFF_QKVT_LO = OFF_QKVT_HI + (size_t)B_ * L_ * C3_ / 2;
constexpr size_t OFF_SG      = OFF_QKVT_LO + (size_t)B_ * L_ * C3_ / 2; // f32 [2][B,L,L]
constexpr size_t OFF_GP_HI   = OFF_SG      + 2 * BLL_;               // f16 [B,L,L]
constexpr size_t OFF_GG2_HI  = OFF_GP_HI   + BLL_ / 2;               // f16 [B,C,L]
constexpr size_t OFF_GG2_LO  = OFF_GG2_HI  + (size_t)B_ * CL_ / 2;
constexpr size_t OFF_GBAR    = OFF_GG2_LO  + (size_t)B_ * CL_ / 2;
constexpr size_t OFF_GATE    = OFF_GBAR    + (size_t)B_ * L_;
constexpr size_t OFF_GOUTT_HI= OFF_GATE    + (size_t)B_ * L_;        // f16 [B,L,C]
constexpr size_t OFF_GOUT2T  = OFF_GOUTT_HI+ (size_t)B_ * CL_ / 2;   // f32 [B,L,C]
constexpr size_t OFF_H1      = OFF_GOUT2T  + (size_t)B_ * CL_;       // f32 [NR,C]
constexpr size_t OFF_H1HI    = OFF_H1      + (size_t)NR_ * C_;       // f16 [NR,C]
constexpr size_t OFF_M1HI    = OFF_H1HI    + (size_t)NR_ * C_ / 2;   // f16 [NR,C4]
constexpr size_t OFF_M2      = OFF_M1HI    + (size_t)NR_ * C4_ / 2;  // f32 [NR,C]
constexpr size_t SCRATCH_TOTAL = OFF_M2    + (size_t)NR_ * C_;
} // namespace

__device__ __align__(256) float d_scratch[SCRATCH_TOTAL];

// ============================================================================
// PTX helpers — sm_80-era only (mma.sync / ldmatrix / cp.async).
// ============================================================================
__device__ __forceinline__ uint32_t smem_to_u32(const void* p) {
    uint32_t a;
    asm("{ .reg .u64 t; cvta.to.shared.u64 t, %1; cvt.u32.u64 %0, t; }" : "=r"(a) : "l"(p));
    return a;
}
__device__ __forceinline__ void ldmat4(uint32_t (&r)[4], uint32_t addr) {
    asm volatile("ldmatrix.sync.aligned.m8n8.x4.shared.b16 {%0,%1,%2,%3}, [%4];"
                 : "=r"(r[0]), "=r"(r[1]), "=r"(r[2]), "=r"(r[3]) : "r"(addr));
}
__device__ __forceinline__ void mma16816(float (&d)[4], const uint32_t (&a)[4], const uint32_t b0, const uint32_t b1) {
    asm volatile("mma.sync.aligned.m16n8k16.row.col.f32.f16.f16.f32 "
                 "{%0,%1,%2,%3}, {%4,%5,%6,%7}, {%8,%9}, {%0,%1,%2,%3};"
                 : "+f"(d[0]), "+f"(d[1]), "+f"(d[2]), "+f"(d[3])
                 : "r"(a[0]), "r"(a[1]), "r"(a[2]), "r"(a[3]), "r"(b0), "r"(b1));
}
__device__ __forceinline__ void cp16(uint32_t saddr, const void* g) {
    asm volatile("cp.async.cg.shared.global [%0], [%1], 16;" :: "r"(saddr), "l"(g));
}
#define CP_COMMIT() asm volatile("cp.async.commit_group;" ::: "memory")
template <int N>
__device__ __forceinline__ void cp_wait() {
    asm volatile("cp.async.wait_group %0;" :: "n"(N) : "memory");
}

namespace {

__device__ __forceinline__ float warpSum(float v) {
#pragma unroll
    for (int o = 16; o; o >>= 1) v += __shfl_xor_sync(0xffffffffu, v, o);
    return v;
}
__device__ __forceinline__ float warpMax(float v) {
#pragma unroll
    for (int o = 16; o; o >>= 1) v = fmaxf(v, __shfl_xor_sync(0xffffffffu, v, o));
    return v;
}
__device__ __forceinline__ float mishf(float v) {
    float sp = fmaxf(v, 0.f) + log1pf(__expf(-fabsf(v)));
    return v * tanhf(sp);
}

// ============================================================================
// fp16-split tensor-core GEMM, multistage cp.async pipeline.
// NT: A [M,K] K-contig (lda) ; B [N,K] K-contig (ldb)
// PASSES==3: D = Ahi·Bhi^T + Ahi·Blo^T + Alo·Bhi^T
// PASSES==2: D = Ahi·Bhi^T + Ahi·Blo^T            (Alo unused/not loaded)
// v = scale*D (+ biasN); ACT=1 -> mish.
// OUTFMT 0: f32 ; 1: f16 hi+lo ; 2: f16 hi only.
// FUSE=1: z encodes (sel = z>>3, b = z&7); B += sel*selB, out += sel*selO.
// WM = warps along M (2 -> 256 thr; 4 -> 512 thr). 4 warps along N always.
// ============================================================================
template <int BN, int OUTFMT, int ACT, int FUSE, int STAGES, int KB, int WM, int PASSES>
__global__ void __launch_bounds__(WM * 128) gemm_mma(
    const __half* __restrict__ Ahi, const __half* __restrict__ Alo,
    const __half* __restrict__ Bhi, const __half* __restrict__ Blo,
    const float* __restrict__ biasN,
    float* __restrict__ outF,
    __half* __restrict__ outHi, __half* __restrict__ outLo,
    int K, int lda, int ldb, int ldOut,
    size_t sA, size_t sB, size_t sO, size_t selB, size_t selO, float scale)
{
    constexpr int BM = 128;
    constexpr int TPB = WM * 128;
    constexpr int MI = BM / (WM * 16);       // m16 frags per warp
    constexpr int SROW = KB * 2 + 16;        // bytes/row: data + 16B pad
    constexpr int CHR = KB / 8;              // 16B chunks per row
    constexpr int ATILE = BM * SROW;
    constexpr int BTILE = BN * SROW;
    constexpr int AP = (PASSES == 3) ? 2 : 1;
    constexpr int STAGE = AP * ATILE + 2 * BTILE;
    constexpr int WN = BN / 4;
    constexpr int NFRAG = WN / 8;
    constexpr int NKS = KB / 16;

    extern __shared__ char smem[];
    const uint32_t sb = smem_to_u32(smem);
    const int tid = threadIdx.x, lane = tid & 31, wid = tid >> 5;
    const int wm = wid & (WM - 1), wn = wid / WM;
    const int m0 = blockIdx.y * BM, n0 = blockIdx.x * BN;
    const int z = blockIdx.z;
    const int b = FUSE ? (z & 7) : z;
    const int sel = FUSE ? (z >> 3) : 0;

    Ahi += (size_t)b * sA;
    if (PASSES == 3) Alo += (size_t)b * sA;
    Bhi += (size_t)b * sB + (size_t)sel * selB;
    Blo += (size_t)b * sB + (size_t)sel * selB;
    if (OUTFMT == 0) outF += (size_t)b * sO + (size_t)sel * selO;
    else {
        outHi += (size_t)b * sO + (size_t)sel * selO;
        if (OUTFMT == 1) outLo += (size_t)b * sO + (size_t)sel * selO;
    }

    float acc[MI][NFRAG][4];
#pragma unroll
    for (int i = 0; i < MI; i++)
#pragma unroll
        for (int j = 0; j < NFRAG; j++)
#pragma unroll
            for (int q = 0; q < 4; q++) acc[i][j][q] = 0.f;

    auto load_stage = [&](int ch, int st) {
        const int k0 = ch * KB;
        const uint32_t base = sb + st * STAGE;
#pragma unroll
        for (int c = tid; c < BM * CHR; c += TPB) {
            int r = c / CHR, cc = c % CHR;
            size_t go = (size_t)(m0 + r) * lda + k0 + cc * 8;
            uint32_t so = base + r * SROW + cc * 16;
            cp16(so, Ahi + go);
            if (PASSES == 3) cp16(so + ATILE, Alo + go);
        }
#pragma unroll
        for (int c = tid; c < BN * CHR; c += TPB) {
            int r = c / CHR, cc = c % CHR;
            size_t go = (size_t)(n0 + r) * ldb + k0 + cc * 8;
            uint32_t so = base + AP * ATILE + r * SROW + cc * 16;
            cp16(so, Bhi + go);
            cp16(so + BTILE, Blo + go);
        }
        CP_COMMIT();
    };

    const int nch = K / KB;
#pragma unroll
    for (int s = 0; s < STAGES - 1; s++) load_stage(s, s);

    int cs = 0;
    int ps = (STAGES - 1) % STAGES;
    for (int ch = 0; ch < nch; ch++) {
        cp_wait<STAGES - 2>();
        __syncthreads();
        const int pf = ch + STAGES - 1;
        if (pf < nch) load_stage(pf, ps);
        else CP_COMMIT();

        const uint32_t aBase = sb + cs * STAGE;
        const uint32_t bBase = aBase + AP * ATILE;
#pragma unroll
        for (int ks = 0; ks < NKS; ks++) {
            const uint32_t colOff = (uint32_t)(ks * 2 + (lane >> 4)) * 16;
            uint32_t a_hi[MI][4], a_lo[MI][4];
#pragma unroll
            for (int mi = 0; mi < MI; mi++) {
                uint32_t addr = aBase + (uint32_t)(wm * (MI * 16) + mi * 16 + (lane & 15)) * SROW + colOff;
                ldmat4(a_hi[mi], addr);
                if (PASSES == 3) ldmat4(a_lo[mi], addr + ATILE);
            }
#pragma unroll
            for (int nt = 0; nt < NFRAG / 2; nt++) {
                uint32_t addr = bBase + (uint32_t)(wn * WN + nt * 16 + (lane & 15)) * SROW + colOff;
                uint32_t bh[4], bl[4];
                ldmat4(bh, addr);
                ldmat4(bl, addr + BTILE);
#pragma unroll
                for (int half = 0; half < 2; half++) {
                    const int ni = nt * 2 + half;
#pragma unroll
                    for (int mi = 0; mi < MI; mi++) {
                        mma16816(acc[mi][ni], a_hi[mi], bh[half], bh[2 + half]);
                        mma16816(acc[mi][ni], a_hi[mi], bl[half], bl[2 + half]);
                        if (PASSES == 3)
                            mma16816(acc[mi][ni], a_lo[mi], bh[half], bh[2 + half]);
                    }
                }
            }
        }
        cs = (cs + 1 == STAGES) ? 0 : cs + 1;
        ps = (ps + 1 == STAGES) ? 0 : ps + 1;
    }

    // ---------------- epilogue ----------------
    const int g = lane >> 2, tg = lane & 3;
#pragma unroll
    for (int mi = 0; mi < MI; mi++) {
#pragma unroll
        for (int ni = 0; ni < NFRAG; ni++) {
            const int col = n0 + wn * WN + ni * 8 + tg * 2;
            const float b0 = biasN ? biasN[col] : 0.f;
            const float b1 = biasN ? biasN[col + 1] : 0.f;
#pragma unroll
            for (int h = 0; h < 2; h++) {
                const int row = m0 + wm * (MI * 16) + mi * 16 + g + h * 8;
                float v0 = acc[mi][ni][h * 2 + 0] * scale + b0;
                float v1 = acc[mi][ni][h * 2 + 1] * scale + b1;
                if (ACT == 1) { v0 = mishf(v0); v1 = mishf(v1); }
                const size_t o = (size_t)row * ldOut + col;
                if (OUTFMT == 0) {
                    float2 fp; fp.x = v0; fp.y = v1;
                    *(float2*)(outF + o) = fp;
                } else {
                    __half h0 = __float2half_rn(v0);
                    __half h1 = __float2half_rn(v1);
                    __half2 hp; hp.x = h0; hp.y = h1;
                    *(__half2*)(outHi + o) = hp;
                    if (OUTFMT == 1) {
                        __half2 lp;
                        lp.x = __float2half_rn(v0 - __half2float(h0));
                        lp.y = __float2half_rn(v1 - __half2float(h1));
                        *(__half2*)(outLo + o) = lp;
                    }
                }
            }
        }
    }
}

// ============================================================================
// prep_all: ONE launch = weight splits (x64 pre-scale) + qkv bias + x transpose
// ============================================================================
constexpr int PREP_SPLIT_TOTAL = 3 * C_ * C_ + C_ * C_ + C4_ * C_ + C_ * C4_ + C3_;
constexpr int PREP_NSPLIT = (PREP_SPLIT_TOTAL + 255) / 256;
constexpr int PREP_NT = (L_ / 32) * (C_ / 32) * B_;

__global__ void prep_all(const float* __restrict__ x,
                         const float* __restrict__ tw, const float* __restrict__ pw,
                         const float* __restrict__ gw, const float* __restrict__ wgw,
                         const float* __restrict__ c1w, const float* __restrict__ c2w,
                         const float* __restrict__ tb, const float* __restrict__ pb,
                         const float* __restrict__ gb,
                         __half* __restrict__ qkvHi, __half* __restrict__ qkvLo,
                         __half* __restrict__ wgHi, __half* __restrict__ wgLo,
                         __half* __restrict__ c1Hi, __half* __restrict__ c1Lo,
                         __half* __restrict__ c2Hi, __half* __restrict__ c2Lo,
                         float* __restrict__ qkvb,
                         __half* __restrict__ xtHi)
{
    __shared__ float t[32][33];
    const int bid = blockIdx.x;
    if (bid < PREP_NSPLIT) {
        constexpr int NW = C_ * C_;
        constexpr int N1 = 3 * NW;
        constexpr int N2 = N1 + NW;
        constexpr int N3 = N2 + C4_ * C_;
        constexpr int N4 = N3 + C_ * C4_;
        const int i = bid * 256 + threadIdx.x;
        float v;
        __half *hi, *lo;
        int j;
        if (i < N1) {
            j = i & (NW - 1);
            const float* src = (i < NW) ? tw : (i < 2 * NW ? pw : gw);
            v = src[j]; hi = qkvHi + i; lo = qkvLo + i;
        } else if (i < N2) {
            j = i - N1; v = wgw[j]; hi = wgHi + j; lo = wgLo + j;
        } else if (i < N3) {
            j = i - N2; v = c1w[j]; hi = c1Hi + j; lo = c1Lo + j;
        } else if (i < N4) {
            j = i - N3; v = c2w[j]; hi = c2Hi + j; lo = c2Lo + j;
        } else if (i < N4 + C3_) {
            j = i - N4;
            qkvb[j] = (j < C_) ? tb[j] : (j < 2 * C_ ? pb[j - C_] : gb[j - 2 * C_]);
            return;
        } else return;
        v *= WSC_;                            // pre-scale: keeps lo out of fp16 subnormals
        __half h = __float2half_rn(v);
        *hi = h;
        *lo = __float2half_rn(v - __half2float(h));
    } else {
        const int tI = bid - PREP_NSPLIT;
        const int b = tI >> 7;
        const int rem = tI & 127;
        const int c0 = (rem & 15) * 32;
        const int l0 = (rem >> 4) * 32;
        const int tx = threadIdx.x & 31, ty = threadIdx.x >> 5;
        const float* xb = x + (size_t)b * CL_;
#pragma unroll
        for (int j = 0; j < 4; j++)
            t[ty + j * 8][tx] = xb[(size_t)(c0 + ty + j * 8) * L_ + l0 + tx];
        __syncthreads();
#pragma unroll
        for (int j = 0; j < 4; j++) {
            int l = l0 + ty + j * 8;
            size_t o = ((size_t)b * L_ + l) * C_ + c0 + tx;
            xtHi[o] = __float2half_rn(t[tx][ty + j * 8]);
        }
    }
}

// ============================================================================
// transpose_g + gbar in ONE kernel. grid (L/32, B), 256 threads.
// ============================================================================
__global__ void gtrans_gbar(const __half* __restrict__ inHi,
                            const __half* __restrict__ inLo,
                            __half* __restrict__ outHi,
                            __half* __restrict__ outLo,
                            float* __restrict__ gbar)
{
    __shared__ __half th[32][34];
    __shared__ __half tl[32][34];
    const int b = blockIdx.y;
    const int l0 = blockIdx.x * 32;
    const int tx = threadIdx.x & 31, ty = threadIdx.x >> 5;

    for (int ct = 0; ct < 16; ct++) {
        const int c0 = ct * 32;
#pragma unroll
        for (int j = 0; j < 4; j++) {
            size_t idx = ((size_t)b * L_ + l0 + ty + j * 8) * C3_ + 2 * C_ + c0 + tx;
            th[ty + j * 8][tx] = inHi[idx];
            tl[ty + j * 8][tx] = inLo[idx];
        }
        __syncthreads();
#pragma unroll
        for (int j = 0; j < 4; j++) {
            int c = c0 + ty + j * 8;
            size_t o = ((size_t)b * C_ + c) * L_ + l0 + tx;
            outHi[o] = th[tx][ty + j * 8];
            outLo[o] = tl[tx][ty + j * 8];
        }
        __syncthreads();
    }

    const int w = threadIdx.x >> 5, lane = threadIdx.x & 31;
#pragma unroll
    for (int i = 0; i < 4; i++) {
        const int l = l0 + w * 4 + i;
        const size_t base = ((size_t)b * L_ + l) * C3_ + 2 * C_;
        float s = 0.f;
#pragma unroll
        for (int c = lane; c < C_; c += 32)
            s += __half2float(inHi[base + c]) + __half2float(inLo[base + c]);
        s = warpSum(s);
        if (lane == 0) gbar[b * L_ + l] = s * (1.f / C_);
    }
}

// ============================================================================
// Fused: softmax(Sg row) -> gp hi  AND  banded local gate from Sl row.
// ============================================================================
__global__ void softmax_gate(const float* __restrict__ Sg,
                             const float* __restrict__ Sl,
                             const float* __restrict__ gbar,
                             const float* __restrict__ wlw,
                             const float* __restrict__ wlb,
                             __half* __restrict__ pHi,
                             float* __restrict__ gate)
{
    __shared__ float sm[16];
    const int l = blockIdx.x, b = blockIdx.y, tid = threadIdx.x;
    const int lane = tid & 31, w = tid >> 5;
    const size_t row = (size_t)b * L_ + l;

    float v = Sg[row * L_ + tid];
    float m = warpMax(v);
    if (lane == 0) sm[w] = m;
    __syncthreads();
    float M = -1e30f;
#pragma unroll
    for (int i = 0; i < 8; i++) M = fmaxf(M, sm[i]);
    float e = __expf(v - M);
    float s = warpSum(e);
    if (lane == 0) sm[8 + w] = s;
    __syncthreads();
    float T = 0.f;
#pragma unroll
    for (int i = 0; i < 8; i++) T += sm[8 + i];
    pHi[row * L_ + tid] = __float2half_rn(e / T);

    if (w == 0) {
        const float* srow = Sl + row * L_;
        const float* gb = gbar + (size_t)b * L_;
        int m0 = l + lane - 32;
        int m1 = l + lane;
        bool v0 = (m0 >= 0) && (m0 < L_);
        bool v1 = (m1 >= 0) && (m1 < L_);
        float s0 = v0 ? srow[m0] : 0.f;
        float s1 = v1 ? srow[m1] : 0.f;
        float g0 = v0 ? gb[m0] : 0.f;
        float g1 = v1 ? gb[m1] : 0.f;
        float mx = warpMax(fmaxf(s0, s1));
        float e0 = __expf(s0 - mx), e1 = __expf(s1 - mx);
        float num = warpSum(e0 * g0 + e1 * g1);
        float den = warpSum(e0 + e1);
        if (lane == 0) {
            float pooled = num / den;
            float z = wlw[0] * pooled + wlb[0];
            gate[b * L_ + l] = 1.f / (1.f + __expf(-z));
        }
    }
}

// ============================================================================
// LN1: h = gout2T*gate + x ; h1 f32 + f16 hi at row (l*B+b), [*,C]
// ============================================================================
__global__ void ln1_kernel(const float* __restrict__ gout2T,
                           const float* __restrict__ gate,
                           const float* __restrict__ x,
                           const float* __restrict__ g1, const float* __restrict__ b1,
                           float* __restrict__ h1,
                           __half* __restrict__ h1hi)
{
    __shared__ float sm[16];
    int l = blockIdx.x, b = blockIdx.y, tid = threadIdx.x;
    int lane = tid & 31, w = tid >> 5;
    float gt = gate[b * L_ + l];
    size_t gbase = ((size_t)b * L_ + l) * C_;
    size_t xbase = (size_t)b * CL_ + l;
    float v0 = fmaf(gout2T[gbase + tid], gt, x[xbase + (size_t)tid * L_]);
    float v1 = fmaf(gout2T[gbase + tid + 256], gt, x[xbase + (size_t)(tid + 256) * L_]);
    float s = warpSum(v0 + v1);
    float q = warpSum(v0 * v0 + v1 * v1);
    if (lane == 0) { sm[w] = s; sm[8 + w] = q; }
    __syncthreads();
    float S = 0.f, Q = 0.f;
#pragma unroll
    for (int i = 0; i < 8; i++) { S += sm[i]; Q += sm[8 + i]; }
    float mean = S * (1.f / C_);
    float var = Q * (1.f / C_) - mean * mean;
    float r = rsqrtf(var + 1e-5f);
    size_t o = ((size_t)l * B_ + b) * C_;
    float y0 = (v0 - mean) * r * g1[tid] + b1[tid];
    float y1 = (v1 - mean) * r * g1[tid + 256] + b1[tid + 256];
    h1[o + tid] = y0;
    h1[o + tid + 256] = y1;
    h1hi[o + tid] = __float2half_rn(y0);
    h1hi[o + tid + 256] = __float2half_rn(y1);
}

// ============================================================================
// LN2 + output transpose
// ============================================================================
__global__ void ln2_kernel(const float* __restrict__ m2,
                           const float* __restrict__ h1,
                           const float* __restrict__ g2, const float* __restrict__ b2,
                           float* __restrict__ out)
{
    __shared__ float sm[16];
    int row = blockIdx.x, tid = threadIdx.x;
    int lane = tid & 31, w = tid >> 5;
    int l = row / B_, b = row % B_;
    size_t base = (size_t)row * C_;
    float v0 = m2[base + tid] + h1[base + tid];
    float v1 = m2[base + tid + 256] + h1[base + tid + 256];
    float s = warpSum(v0 + v1);
    float q = warpSum(v0 * v0 + v1 * v1);
    if (lane == 0) { sm[w] = s; sm[8 + w] = q; }
    __syncthreads();
    float S = 0.f, Q = 0.f;
#pragma unroll
    for (int i = 0; i < 8; i++) { S += sm[i]; Q += sm[8 + i]; }
    float mean = S * (1.f / C_);
    float var = Q * (1.f / C_) - mean * mean;
    float r = rsqrtf(var + 1e-5f);
    size_t ob = (size_t)b * CL_ + l;
    out[ob + (size_t)tid * L_]         = (v0 - mean) * r * g2[tid] + b2[tid];
    out[ob + (size_t)(tid + 256) * L_] = (v1 - mean) * r * g2[tid + 256] + b2[tid + 256];
}

} // namespace

// ============================================================================
// Host launcher
// ============================================================================
extern "C" void kernel_launch(void* const* d_in, const int* in_sizes, int n_in,
                              void* d_out, int out_size)
{
    (void)in_sizes; (void)n_in; (void)out_size;
    float* scratch = nullptr;
    cudaGetSymbolAddress((void**)&scratch, d_scratch);

    const float* x       = (const float*)d_in[0];
    const float* theta_w = (const float*)d_in[1];
    const float* theta_b = (const float*)d_in[2];
    const float* phi_w   = (const float*)d_in[3];
    const float* phi_b   = (const float*)d_in[4];
    const float* g_w     = (const float*)d_in[5];
    const float* g_b     = (const float*)d_in[6];
    const float* wl_w    = (const float*)d_in[7];
    const float* wl_b    = (const float*)d_in[8];
    const float* wg_w    = (const float*)d_in[9];
    const float* wg_b    = (const float*)d_in[10];
    const float* conv1_w = (const float*)d_in[11];
    const float* conv1_b = (const float*)d_in[12];
    const float* conv2_w = (const float*)d_in[13];
    const float* conv2_b = (const float*)d_in[14];
    const float* ln1_g   = (const float*)d_in[15];
    const float* ln1_b   = (const float*)d_in[16];
    const float* ln2_g   = (const float*)d_in[17];
    const float* ln2_b   = (const float*)d_in[18];
    float* out = (float*)d_out;

    __half* xtHi   = (__half*)(scratch + OFF_XT_HI);
    __half* wqkvHi = (__half*)(scratch + OFF_WQKV_HI);
    __half* wqkvLo = (__half*)(scratch + OFF_WQKV_LO);
    float* qkv_b   = scratch + OFF_QKV_B;
    __half* wwgHi  = (__half*)(scratch + OFF_WWG_HI);
    __half* wwgLo  = (__half*)(scratch + OFF_WWG_LO);
    __half* c1wHi  = (__half*)(scratch + OFF_C1WHI);
    __half* c1wLo  = (__half*)(scratch + OFF_C1WLO);
    __half* c2wHi  = (__half*)(scratch + OFF_C2WHI);
    __half* c2wLo  = (__half*)(scratch + OFF_C2WLO);
    __half* qkvHi  = (__half*)(scratch + OFF_QKVT_HI);
    __half* qkvLo  = (__half*)(scratch + OFF_QKVT_LO);
    float* Sg      = scratch + OFF_SG;
    __half* gpHi   = (__half*)(scratch + OFF_GP_HI);
    __half* gg2Hi  = (__half*)(scratch + OFF_GG2_HI);
    __half* gg2Lo  = (__half*)(scratch + OFF_GG2_LO);
    float* gbar    = scratch + OFF_GBAR;
    float* gate    = scratch + OFF_GATE;
    __half* goHi   = (__half*)(scratch + OFF_GOUTT_HI);
    float* gout2T  = scratch + OFF_GOUT2T;
    float* h1      = scratch + OFF_H1;
    __half* h1Hi   = (__half*)(scratch + OFF_H1HI);
    __half* m1Hi   = (__half*)(scratch + OFF_M1HI);
    float* m2      = scratch + OFF_M2;

    // SMEM budgets
    // BN=64 KB=64 3st: P3 stage=2*18432+2*9216=55296 -> 165888 ; P2 stage=18432+2*9216=36864 -> 110592
    // BN=128 KB=32 2st P2: stage=10240+2*10240=30720 -> 61440 (2+ CTAs/SM)
    constexpr int SM_SGSL = 165888;
    constexpr int SM_64P2 = 110592;
    constexpr int SM_128P2 = 61440;
    cudaFuncSetAttribute(gemm_mma<64, 0, 0, 1, 3, 64, 4, 3>,  cudaFuncAttributeMaxDynamicSharedMemorySize, SM_SGSL);
    cudaFuncSetAttribute(gemm_mma<64, 2, 0, 0, 3, 64, 4, 2>,  cudaFuncAttributeMaxDynamicSharedMemorySize, SM_64P2);
    cudaFuncSetAttribute(gemm_mma<64, 0, 0, 0, 3, 64, 4, 2>,  cudaFuncAttributeMaxDynamicSharedMemorySize, SM_64P2);
    cudaFuncSetAttribute(gemm_mma<128, 1, 0, 0, 2, 32, 2, 2>, cudaFuncAttributeMaxDynamicSharedMemorySize, SM_128P2);
    cudaFuncSetAttribute(gemm_mma<128, 2, 1, 0, 2, 32, 2, 2>, cudaFuncAttributeMaxDynamicSharedMemorySize, SM_128P2);

    // 0) prep: weight splits (x64) + bias concat + x transpose (hi only)
    prep_all<<<PREP_NSPLIT + PREP_NT, 256>>>(
        x, theta_w, phi_w, g_w, wg_w, conv1_w, conv2_w, theta_b, phi_b, g_b,
        wqkvHi, wqkvLo, wwgHi, wwgLo, c1wHi, c1wLo, c2wHi, c2wLo, qkv_b, xtHi);

    // 1) fused qkv (2-pass, weights x64 -> scale 1/64): qkvT hi+lo out
    {
        dim3 grid(C3_ / 128, L_ / 128, B_);
        gemm_mma<128, 1, 0, 0, 2, 32, 2, 2><<<grid, 256, SM_128P2>>>(
            xtHi, nullptr, wqkvHi, wqkvLo, qkv_b, nullptr, qkvHi, qkvLo,
            C_, C_, C_, C3_, (size_t)L_ * C_, 0, (size_t)L_ * C3_, 0, 0, WINV_);
    }

    // 2) g transpose + gbar
    gtrans_gbar<<<dim3(L_ / 32, B_), 256>>>(qkvHi, qkvLo, gg2Hi, gg2Lo, gbar);

    // 3) Sg & Sl in ONE launch (3-pass fp16, activations: no weight scale)
    {
        dim3 grid(L_ / 64, L_ / 128, 2 * B_);
        gemm_mma<64, 0, 0, 1, 3, 64, 4, 3><<<grid, 512, SM_SGSL>>>(
            qkvHi + C_, qkvLo + C_, qkvHi, qkvLo, nullptr, Sg, nullptr, nullptr,
            C_, C3_, C3_, L_, (size_t)L_ * C3_, (size_t)L_ * C3_, (size_t)L_ * L_,
            (size_t)(2 * C_), BLL_, SCALE_);
    }

    // 4) fused softmax + local gate
    softmax_gate<<<dim3(L_, B_), 256>>>(Sg, Sg + BLL_, gbar,
                                        wl_w, wl_b, gpHi, gate);

    // 5) goutT = gp @ gg2^T (2-pass, hi out) ; gout2T = goutT @ wg^T + b (2-pass, 1/64)
    {
        dim3 grid(C_ / 64, L_ / 128, B_);
        gemm_mma<64, 2, 0, 0, 3, 64, 4, 2><<<grid, 512, SM_64P2>>>(
            gpHi, nullptr, gg2Hi, gg2Lo, nullptr, nullptr, goHi, nullptr,
            L_, L_, L_, C_, (size_t)L_ * L_, (size_t)CL_, (size_t)L_ * C_, 0, 0, 1.f);
        gemm_mma<64, 0, 0, 0, 3, 64, 4, 2><<<grid, 512, SM_64P2>>>(
            goHi, nullptr, wwgHi, wwgLo, wg_b, gout2T, nullptr, nullptr,
            C_, C_, C_, C_, (size_t)L_ * C_, 0, (size_t)L_ * C_, 0, 0, WINV_);
    }

    // 6) LN1 -> h1 (f32 + f16 hi)
    ln1_kernel<<<dim3(L_, B_), 256>>>(gout2T, gate, x, ln1_g, ln1_b, h1, h1Hi);

    // 7) MLP1: m1 = Mish(h1 @ conv1^T * 1/64 + b) -> f16 hi (2-pass)
    {
        dim3 grid(C4_ / 128, NR_ / 128, 1);
        gemm_mma<128, 2, 1, 0, 2, 32, 2, 2><<<grid, 256, SM_128P2>>>(
            h1Hi, nullptr, c1wHi, c1wLo, conv1_b, nullptr, m1Hi, nullptr,
            C_, C_, C_, C4_, 0, 0, 0, 0, 0, WINV_);
    }

    // 8) MLP2: m2 = m1 @ conv2^T * 1/64 + b -> f32 (2-pass)
    {
        dim3 grid(C_ / 64, NR_ / 128, 1);
        gemm_mma<64, 0, 0, 0, 3, 64, 4, 2><<<grid, 512, SM_64P2>>>(
            m1Hi, nullptr, c2wHi, c2wLo, conv2_b, m2, nullptr, nullptr,
            C4_, C4_, C4_, C_, 0, 0, 0, 0, 0, WINV_);
    }

    // 9) LN2 + transpose out
    ln2_kernel<<<NR_, 256>>>(m2, h1, ln2_g, ln2_b, out);
}

// round 11
// speedup vs baseline: 1.4911x; 1.1446x over previous
#include <cuda_runtime.h>
#include <cuda_fp16.h>
#include <math.h>
#include <stdint.h>

// ============================================================================
// Problem constants
// ============================================================================
namespace {
constexpr int B_ = 8, C_ = 512, L_ = 256;
constexpr int CL_ = C_ * L_;           // 131072
constexpr int C3_ = 3 * C_;            // 1536
constexpr int C4_ = 4 * C_;            // 2048
constexpr int NR_ = L_ * B_;           // 2048
constexpr size_t BLL_ = (size_t)B_ * L_ * L_;
constexpr float SCALE_ = 0.044194173824159216f; // 512^-0.5
constexpr float WSC_ = 64.f;            // weight pre-scale (fp16 subnormal guard)
constexpr float WINV_ = 0.015625f;      // 1/64

// ---------------- scratch offsets (float units) ----------------
constexpr size_t OFF_XT_HI   = 0;                                    // f16 [B,L,C]
constexpr size_t OFF_XT32    = OFF_XT_HI   + (size_t)B_ * CL_ / 2;   // f32 [B,L,C]
constexpr size_t OFF_WQKV_HI = OFF_XT32    + (size_t)B_ * CL_;       // f16 [3C,C]
constexpr size_t OFF_WQKV_LO = OFF_WQKV_HI + (size_t)C3_ * C_ / 2;
constexpr size_t OFF_QKV_B   = OFF_WQKV_LO + (size_t)C3_ * C_ / 2;   // f32 [1536]
constexpr size_t OFF_WWG_HI  = OFF_QKV_B   + 1536;
constexpr size_t OFF_WWG_LO  = OFF_WWG_HI  + (size_t)C_ * C_ / 2;
constexpr size_t OFF_C1WHI   = OFF_WWG_LO  + (size_t)C_ * C_ / 2;
constexpr size_t OFF_C1WLO   = OFF_C1WHI   + (size_t)C4_ * C_ / 2;
constexpr size_t OFF_C2WHI   = OFF_C1WLO   + (size_t)C4_ * C_ / 2;
constexpr size_t OFF_C2WLO   = OFF_C2WHI   + (size_t)C_ * C4_ / 2;
constexpr size_t OFF_QKVT_HI = OFF_C2WLO   + (size_t)C_ * C4_ / 2;   // f16 [B,L,3C]
constexpr size_t OFF_QKVT_LO = OFF_QKVT_HI + (size_t)B_ * L_ * C3_ / 2;
constexpr size_t OFF_SG      = OFF_QKVT_LO + (size_t)B_ * L_ * C3_ / 2; // f32 [2][B,L,L]
constexpr size_t OFF_GP_HI   = OFF_SG      + 2 * BLL_;               // f16 [B,L,L]
constexpr size_t OFF_GG2_HI  = OFF_GP_HI   + BLL_ / 2;               // f16 [B,C,L]
constexpr size_t OFF_GG2_LO  = OFF_GG2_HI  + (size_t)B_ * CL_ / 2;
constexpr size_t OFF_GBAR    = OFF_GG2_LO  + (size_t)B_ * CL_ / 2;
constexpr size_t OFF_GATE    = OFF_GBAR    + (size_t)B_ * L_;
constexpr size_t OFF_GOUTT_HI= OFF_GATE    + (size_t)B_ * L_;        // f16 [B,L,C]
constexpr size_t OFF_GOUT2T  = OFF_GOUTT_HI+ (size_t)B_ * CL_ / 2;   // f32 [B,L,C]
constexpr size_t OFF_H1      = OFF_GOUT2T  + (size_t)B_ * CL_;       // f32 [NR,C]
constexpr size_t OFF_H1HI    = OFF_H1      + (size_t)NR_ * C_;       // f16 [NR,C]
constexpr size_t OFF_M1HI    = OFF_H1HI    + (size_t)NR_ * C_ / 2;   // f16 [NR,C4]
constexpr size_t OFF_M2      = OFF_M1HI    + (size_t)NR_ * C4_ / 2;  // f32 [NR,C]
constexpr size_t SCRATCH_TOTAL = OFF_M2    + (size_t)NR_ * C_;
} // namespace

__device__ __align__(256) float d_scratch[SCRATCH_TOTAL];

// ============================================================================
// PTX helpers — sm_80-era only (mma.sync / ldmatrix / cp.async).
// ============================================================================
__device__ __forceinline__ uint32_t smem_to_u32(const void* p) {
    uint32_t a;
    asm("{ .reg .u64 t; cvta.to.shared.u64 t, %1; cvt.u32.u64 %0, t; }" : "=r"(a) : "l"(p));
    return a;
}
__device__ __forceinline__ void ldmat4(uint32_t (&r)[4], uint32_t addr) {
    asm volatile("ldmatrix.sync.aligned.m8n8.x4.shared.b16 {%0,%1,%2,%3}, [%4];"
                 : "=r"(r[0]), "=r"(r[1]), "=r"(r[2]), "=r"(r[3]) : "r"(addr));
}
__device__ __forceinline__ void mma16816(float (&d)[4], const uint32_t (&a)[4], const uint32_t b0, const uint32_t b1) {
    asm volatile("mma.sync.aligned.m16n8k16.row.col.f32.f16.f16.f32 "
                 "{%0,%1,%2,%3}, {%4,%5,%6,%7}, {%8,%9}, {%0,%1,%2,%3};"
                 : "+f"(d[0]), "+f"(d[1]), "+f"(d[2]), "+f"(d[3])
                 : "r"(a[0]), "r"(a[1]), "r"(a[2]), "r"(a[3]), "r"(b0), "r"(b1));
}
__device__ __forceinline__ void cp16(uint32_t saddr, const void* g) {
    asm volatile("cp.async.cg.shared.global [%0], [%1], 16;" :: "r"(saddr), "l"(g));
}
#define CP_COMMIT() asm volatile("cp.async.commit_group;" ::: "memory")
template <int N>
__device__ __forceinline__ void cp_wait() {
    asm volatile("cp.async.wait_group %0;" :: "n"(N) : "memory");
}

namespace {

__device__ __forceinline__ float warpSum(float v) {
#pragma unroll
    for (int o = 16; o; o >>= 1) v += __shfl_xor_sync(0xffffffffu, v, o);
    return v;
}
__device__ __forceinline__ float warpMax(float v) {
#pragma unroll
    for (int o = 16; o; o >>= 1) v = fmaxf(v, __shfl_xor_sync(0xffffffffu, v, o));
    return v;
}
__device__ __forceinline__ float mishf(float v) {
    float sp = fmaxf(v, 0.f) + log1pf(__expf(-fabsf(v)));
    return v * tanhf(sp);
}

// ============================================================================
// fp16-split tensor-core GEMM body (device function; shared by kernels).
// NT: A [M,K] K-contig (lda) ; B [N,K] K-contig (ldb)
// PASSES==3: D = Ahi·Bhi^T + Ahi·Blo^T + Alo·Bhi^T
// PASSES==2: D = Ahi·Bhi^T + Ahi·Blo^T            (Alo unused/not loaded)
// v = scale*D (+ biasN); ACT=1 -> mish.
// OUTFMT 0: f32 ; 1: f16 hi+lo ; 2: f16 hi only.
// FUSE=1: z encodes (sel = z>>3, b = z&7); B += sel*selB, out += sel*selO.
// WM = warps along M (2 -> 256 thr; 4 -> 512 thr). 4 warps along N always.
// ============================================================================
template <int BN, int OUTFMT, int ACT, int FUSE, int STAGES, int KB, int WM, int PASSES>
__device__ __forceinline__ void gemm_body(
    const __half* __restrict__ Ahi, const __half* __restrict__ Alo,
    const __half* __restrict__ Bhi, const __half* __restrict__ Blo,
    const float* __restrict__ biasN,
    float* __restrict__ outF,
    __half* __restrict__ outHi, __half* __restrict__ outLo,
    int K, int lda, int ldb, int ldOut,
    size_t sA, size_t sB, size_t sO, size_t selB, size_t selO, float scale,
    char* smem)
{
    constexpr int BM = 128;
    constexpr int TPB = WM * 128;
    constexpr int MI = BM / (WM * 16);
    constexpr int SROW = KB * 2 + 16;
    constexpr int CHR = KB / 8;
    constexpr int ATILE = BM * SROW;
    constexpr int BTILE = BN * SROW;
    constexpr int AP = (PASSES == 3) ? 2 : 1;
    constexpr int STAGE = AP * ATILE + 2 * BTILE;
    constexpr int WN = BN / 4;
    constexpr int NFRAG = WN / 8;
    constexpr int NKS = KB / 16;

    const uint32_t sb = smem_to_u32(smem);
    const int tid = threadIdx.x, lane = tid & 31, wid = tid >> 5;
    const int wm = wid & (WM - 1), wn = wid / WM;
    const int m0 = blockIdx.y * BM, n0 = blockIdx.x * BN;
    const int z = blockIdx.z;
    const int b = FUSE ? (z & 7) : z;
    const int sel = FUSE ? (z >> 3) : 0;

    Ahi += (size_t)b * sA;
    if (PASSES == 3) Alo += (size_t)b * sA;
    Bhi += (size_t)b * sB + (size_t)sel * selB;
    Blo += (size_t)b * sB + (size_t)sel * selB;
    if (OUTFMT == 0) outF += (size_t)b * sO + (size_t)sel * selO;
    else {
        outHi += (size_t)b * sO + (size_t)sel * selO;
        if (OUTFMT == 1) outLo += (size_t)b * sO + (size_t)sel * selO;
    }

    float acc[MI][NFRAG][4];
#pragma unroll
    for (int i = 0; i < MI; i++)
#pragma unroll
        for (int j = 0; j < NFRAG; j++)
#pragma unroll
            for (int q = 0; q < 4; q++) acc[i][j][q] = 0.f;

    auto load_stage = [&](int ch, int st) {
        const int k0 = ch * KB;
        const uint32_t base = sb + st * STAGE;
#pragma unroll
        for (int c = tid; c < BM * CHR; c += TPB) {
            int r = c / CHR, cc = c % CHR;
            size_t go = (size_t)(m0 + r) * lda + k0 + cc * 8;
            uint32_t so = base + r * SROW + cc * 16;
            cp16(so, Ahi + go);
            if (PASSES == 3) cp16(so + ATILE, Alo + go);
        }
#pragma unroll
        for (int c = tid; c < BN * CHR; c += TPB) {
            int r = c / CHR, cc = c % CHR;
            size_t go = (size_t)(n0 + r) * ldb + k0 + cc * 8;
            uint32_t so = base + AP * ATILE + r * SROW + cc * 16;
            cp16(so, Bhi + go);
            cp16(so + BTILE, Blo + go);
        }
        CP_COMMIT();
    };

    const int nch = K / KB;
#pragma unroll
    for (int s = 0; s < STAGES - 1; s++) load_stage(s, s);

    int cs = 0;
    int ps = (STAGES - 1) % STAGES;
    for (int ch = 0; ch < nch; ch++) {
        cp_wait<STAGES - 2>();
        __syncthreads();
        const int pf = ch + STAGES - 1;
        if (pf < nch) load_stage(pf, ps);
        else CP_COMMIT();

        const uint32_t aBase = sb + cs * STAGE;
        const uint32_t bBase = aBase + AP * ATILE;
#pragma unroll
        for (int ks = 0; ks < NKS; ks++) {
            const uint32_t colOff = (uint32_t)(ks * 2 + (lane >> 4)) * 16;
            uint32_t a_hi[MI][4], a_lo[MI][4];
#pragma unroll
            for (int mi = 0; mi < MI; mi++) {
                uint32_t addr = aBase + (uint32_t)(wm * (MI * 16) + mi * 16 + (lane & 15)) * SROW + colOff;
                ldmat4(a_hi[mi], addr);
                if (PASSES == 3) ldmat4(a_lo[mi], addr + ATILE);
            }
#pragma unroll
            for (int nt = 0; nt < NFRAG / 2; nt++) {
                uint32_t addr = bBase + (uint32_t)(wn * WN + nt * 16 + (lane & 15)) * SROW + colOff;
                uint32_t bh[4], bl[4];
                ldmat4(bh, addr);
                ldmat4(bl, addr + BTILE);
#pragma unroll
                for (int half = 0; half < 2; half++) {
                    const int ni = nt * 2 + half;
#pragma unroll
                    for (int mi = 0; mi < MI; mi++) {
                        mma16816(acc[mi][ni], a_hi[mi], bh[half], bh[2 + half]);
                        mma16816(acc[mi][ni], a_hi[mi], bl[half], bl[2 + half]);
                        if (PASSES == 3)
                            mma16816(acc[mi][ni], a_lo[mi], bh[half], bh[2 + half]);
                    }
                }
            }
        }
        cs = (cs + 1 == STAGES) ? 0 : cs + 1;
        ps = (ps + 1 == STAGES) ? 0 : ps + 1;
    }

    // ---------------- epilogue ----------------
    const int g = lane >> 2, tg = lane & 3;
#pragma unroll
    for (int mi = 0; mi < MI; mi++) {
#pragma unroll
        for (int ni = 0; ni < NFRAG; ni++) {
            const int col = n0 + wn * WN + ni * 8 + tg * 2;
            const float b0 = biasN ? biasN[col] : 0.f;
            const float b1 = biasN ? biasN[col + 1] : 0.f;
#pragma unroll
            for (int h = 0; h < 2; h++) {
                const int row = m0 + wm * (MI * 16) + mi * 16 + g + h * 8;
                float v0 = acc[mi][ni][h * 2 + 0] * scale + b0;
                float v1 = acc[mi][ni][h * 2 + 1] * scale + b1;
                if (ACT == 1) { v0 = mishf(v0); v1 = mishf(v1); }
                const size_t o = (size_t)row * ldOut + col;
                if (OUTFMT == 0) {
                    float2 fp; fp.x = v0; fp.y = v1;
                    *(float2*)(outF + o) = fp;
                } else {
                    __half h0 = __float2half_rn(v0);
                    __half h1 = __float2half_rn(v1);
                    __half2 hp; hp.x = h0; hp.y = h1;
                    *(__half2*)(outHi + o) = hp;
                    if (OUTFMT == 1) {
                        __half2 lp;
                        lp.x = __float2half_rn(v0 - __half2float(h0));
                        lp.y = __float2half_rn(v1 - __half2float(h1));
                        *(__half2*)(outLo + o) = lp;
                    }
                }
            }
        }
    }
}

template <int BN, int OUTFMT, int ACT, int FUSE, int STAGES, int KB, int WM, int PASSES>
__global__ void __launch_bounds__(WM * 128) gemm_mma(
    const __half* __restrict__ Ahi, const __half* __restrict__ Alo,
    const __half* __restrict__ Bhi, const __half* __restrict__ Blo,
    const float* __restrict__ biasN,
    float* __restrict__ outF,
    __half* __restrict__ outHi, __half* __restrict__ outLo,
    int K, int lda, int ldb, int ldOut,
    size_t sA, size_t sB, size_t sO, size_t selB, size_t selO, float scale)
{
    extern __shared__ char smem[];
    gemm_body<BN, OUTFMT, ACT, FUSE, STAGES, KB, WM, PASSES>(
        Ahi, Alo, Bhi, Blo, biasN, outF, outHi, outLo,
        K, lda, ldb, ldOut, sA, sB, sO, selB, selO, scale, smem);
}

// ============================================================================
// Fused Sg/Sl GEMM (z<16) + g-transpose/gbar (z>=16) in ONE launch.
// Grid (4, 2, 24), 512 threads, dynamic smem 110592.
// z in [16,24): vb = (z-16)*8 + by*4 + bx in [0,64): b = vb>>3, l0 = (vb&7)*32.
// ============================================================================
__global__ void __launch_bounds__(512) sgsl_gtrans(
    const __half* __restrict__ qkvHi, const __half* __restrict__ qkvLo,
    float* __restrict__ Sg,
    __half* __restrict__ gg2Hi, __half* __restrict__ gg2Lo,
    float* __restrict__ gbar)
{
    extern __shared__ char smem[];
    if (blockIdx.z < 16) {
        gemm_body<64, 0, 0, 1, 3, 64, 4, 2>(
            qkvHi + C_, qkvLo + C_, qkvHi, qkvLo, nullptr, Sg, nullptr, nullptr,
            C_, C3_, C3_, L_, (size_t)L_ * C3_, (size_t)L_ * C3_, (size_t)L_ * L_,
            (size_t)(2 * C_), BLL_, SCALE_, smem);
        return;
    }
    // ---- transpose + gbar path (all 512 threads) ----
    __half (*th)[34] = (__half(*)[34])smem;
    __half (*tl)[34] = (__half(*)[34])(smem + 32 * 34 * 2);
    const int vb = (blockIdx.z - 16) * 8 + blockIdx.y * 4 + blockIdx.x;
    const int b = vb >> 3;
    const int l0 = (vb & 7) * 32;
    const int tid = threadIdx.x;
    const int tx = tid & 31, ty = tid >> 5;            // ty in 0..15

    for (int ct = 0; ct < 16; ct++) {
        const int c0 = ct * 32;
#pragma unroll
        for (int j = 0; j < 2; j++) {
            size_t idx = ((size_t)b * L_ + l0 + ty + j * 16) * C3_ + 2 * C_ + c0 + tx;
            th[ty + j * 16][tx] = qkvHi[idx];
            tl[ty + j * 16][tx] = qkvLo[idx];
        }
        __syncthreads();
#pragma unroll
        for (int j = 0; j < 2; j++) {
            int c = c0 + ty + j * 16;
            size_t o = ((size_t)b * C_ + c) * L_ + l0 + tx;
            gg2Hi[o] = th[tx][ty + j * 16];
            gg2Lo[o] = tl[tx][ty + j * 16];
        }
        __syncthreads();
    }
    // gbar: 16 warps, each handles 2 l values
#pragma unroll
    for (int i = 0; i < 2; i++) {
        const int l = l0 + ty * 2 + i;
        const size_t base = ((size_t)b * L_ + l) * C3_ + 2 * C_;
        float s = 0.f;
#pragma unroll
        for (int c = tx; c < C_; c += 32)
            s += __half2float(qkvHi[base + c]) + __half2float(qkvLo[base + c]);
        s = warpSum(s);
        if (tx == 0) gbar[b * L_ + l] = s * (1.f / C_);
    }
}

// ============================================================================
// prep_all: ONE launch = vectorized weight splits (x64) + qkv bias + x transpose
// Block layout: [0,NW4): float4 weight split; [NW4,NW4+6): bias; rest transpose.
// ============================================================================
constexpr int PREP_WELEMS = 3 * C_ * C_ + C_ * C_ + C4_ * C_ + C_ * C4_;  // 3145728
constexpr int PREP_NW4 = PREP_WELEMS / 4 / 256;       // 3072 blocks
constexpr int PREP_NB = 6;                            // bias blocks
constexpr int PREP_NT = (L_ / 32) * (C_ / 32) * B_;   // 1024 transpose blocks

__global__ void prep_all(const float* __restrict__ x,
                         const float* __restrict__ tw, const float* __restrict__ pw,
                         const float* __restrict__ gw, const float* __restrict__ wgw,
                         const float* __restrict__ c1w, const float* __restrict__ c2w,
                         const float* __restrict__ tb, const float* __restrict__ pb,
                         const float* __restrict__ gb,
                         __half* __restrict__ qkvHi, __half* __restrict__ qkvLo,
                         __half* __restrict__ wgHi, __half* __restrict__ wgLo,
                         __half* __restrict__ c1Hi, __half* __restrict__ c1Lo,
                         __half* __restrict__ c2Hi, __half* __restrict__ c2Lo,
                         float* __restrict__ qkvb,
                         __half* __restrict__ xtHi, float* __restrict__ xt32)
{
    __shared__ float t[32][33];
    const int bid = blockIdx.x;
    if (bid < PREP_NW4) {
        constexpr int NW = C_ * C_;
        constexpr int N1 = 3 * NW;
        constexpr int N2 = N1 + NW;
        constexpr int N3 = N2 + C4_ * C_;
        const int i = (bid * 256 + threadIdx.x) * 4;     // element index, 16B aligned
        const float* src;
        __half *hi, *lo;
        int j;
        if (i < N1) {
            j = i & (NW - 1);
            src = (i < NW) ? tw : (i < 2 * NW ? pw : gw);
            hi = qkvHi + i; lo = qkvLo + i;
        } else if (i < N2) {
            j = i - N1; src = wgw; hi = wgHi + j; lo = wgLo + j;
        } else if (i < N3) {
            j = i - N2; src = c1w; hi = c1Hi + j; lo = c1Lo + j;
        } else {
            j = i - N3; src = c2w; hi = c2Hi + j; lo = c2Lo + j;
        }
        float4 v4 = *(const float4*)(src + j);
        float v[4] = {v4.x, v4.y, v4.z, v4.w};
        __half2 hp[2], lp[2];
#pragma unroll
        for (int q = 0; q < 4; q++) {
            float v2 = v[q] * WSC_;                      // keep lo out of subnormals
            __half h = __float2half_rn(v2);
            ((__half*)hp)[q] = h;
            ((__half*)lp)[q] = __float2half_rn(v2 - __half2float(h));
        }
        *(__half2*)(hi)     = hp[0];
        *(__half2*)(hi + 2) = hp[1];
        *(__half2*)(lo)     = lp[0];
        *(__half2*)(lo + 2) = lp[1];
    } else if (bid < PREP_NW4 + PREP_NB) {
        const int j = (bid - PREP_NW4) * 256 + threadIdx.x;
        if (j < C3_)
            qkvb[j] = (j < C_) ? tb[j] : (j < 2 * C_ ? pb[j - C_] : gb[j - 2 * C_]);
    } else {
        const int tI = bid - PREP_NW4 - PREP_NB;
        const int b = tI >> 7;
        const int rem = tI & 127;
        const int c0 = (rem & 15) * 32;
        const int l0 = (rem >> 4) * 32;
        const int tx = threadIdx.x & 31, ty = threadIdx.x >> 5;
        const float* xb = x + (size_t)b * CL_;
#pragma unroll
        for (int j = 0; j < 4; j++)
            t[ty + j * 8][tx] = xb[(size_t)(c0 + ty + j * 8) * L_ + l0 + tx];
        __syncthreads();
#pragma unroll
        for (int j = 0; j < 4; j++) {
            int l = l0 + ty + j * 8;
            float v = t[tx][ty + j * 8];
            size_t o = ((size_t)b * L_ + l) * C_ + c0 + tx;
            xtHi[o] = __float2half_rn(v);
            xt32[o] = v;
        }
    }
}

// ============================================================================
// Fused: softmax(Sg row) -> gp hi  AND  banded local gate from Sl row.
// ============================================================================
__global__ void softmax_gate(const float* __restrict__ Sg,
                             const float* __restrict__ Sl,
                             const float* __restrict__ gbar,
                             const float* __restrict__ wlw,
                             const float* __restrict__ wlb,
                             __half* __restrict__ pHi,
                             float* __restrict__ gate)
{
    __shared__ float sm[16];
    const int l = blockIdx.x, b = blockIdx.y, tid = threadIdx.x;
    const int lane = tid & 31, w = tid >> 5;
    const size_t row = (size_t)b * L_ + l;

    float v = Sg[row * L_ + tid];
    float m = warpMax(v);
    if (lane == 0) sm[w] = m;
    __syncthreads();
    float M = -1e30f;
#pragma unroll
    for (int i = 0; i < 8; i++) M = fmaxf(M, sm[i]);
    float e = __expf(v - M);
    float s = warpSum(e);
    if (lane == 0) sm[8 + w] = s;
    __syncthreads();
    float T = 0.f;
#pragma unroll
    for (int i = 0; i < 8; i++) T += sm[8 + i];
    pHi[row * L_ + tid] = __float2half_rn(e / T);

    if (w == 0) {
        const float* srow = Sl + row * L_;
        const float* gb = gbar + (size_t)b * L_;
        int m0 = l + lane - 32;
        int m1 = l + lane;
        bool v0 = (m0 >= 0) && (m0 < L_);
        bool v1 = (m1 >= 0) && (m1 < L_);
        float s0 = v0 ? srow[m0] : 0.f;
        float s1 = v1 ? srow[m1] : 0.f;
        float g0 = v0 ? gb[m0] : 0.f;
        float g1 = v1 ? gb[m1] : 0.f;
        float mx = warpMax(fmaxf(s0, s1));
        float e0 = __expf(s0 - mx), e1 = __expf(s1 - mx);
        float num = warpSum(e0 * g0 + e1 * g1);
        float den = warpSum(e0 + e1);
        if (lane == 0) {
            float pooled = num / den;
            float z = wlw[0] * pooled + wlb[0];
            gate[b * L_ + l] = 1.f / (1.f + __expf(-z));
        }
    }
}

// ============================================================================
// LN1: h = gout2T*gate + xT32 ; h1 f32 + f16 hi at row (l*B+b), [*,C]
// All reads coalesced (xT32 is [B,L,C]).
// ============================================================================
__global__ void ln1_kernel(const float* __restrict__ gout2T,
                           const float* __restrict__ gate,
                           const float* __restrict__ xt32,
                           const float* __restrict__ g1, const float* __restrict__ b1,
                           float* __restrict__ h1,
                           __half* __restrict__ h1hi)
{
    __shared__ float sm[16];
    int l = blockIdx.x, b = blockIdx.y, tid = threadIdx.x;
    int lane = tid & 31, w = tid >> 5;
    float gt = gate[b * L_ + l];
    size_t gbase = ((size_t)b * L_ + l) * C_;
    float v0 = fmaf(gout2T[gbase + tid], gt, xt32[gbase + tid]);
    float v1 = fmaf(gout2T[gbase + tid + 256], gt, xt32[gbase + tid + 256]);
    float s = warpSum(v0 + v1);
    float q = warpSum(v0 * v0 + v1 * v1);
    if (lane == 0) { sm[w] = s; sm[8 + w] = q; }
    __syncthreads();
    float S = 0.f, Q = 0.f;
#pragma unroll
    for (int i = 0; i < 8; i++) { S += sm[i]; Q += sm[8 + i]; }
    float mean = S * (1.f / C_);
    float var = Q * (1.f / C_) - mean * mean;
    float r = rsqrtf(var + 1e-5f);
    size_t o = ((size_t)l * B_ + b) * C_;
    float y0 = (v0 - mean) * r * g1[tid] + b1[tid];
    float y1 = (v1 - mean) * r * g1[tid + 256] + b1[tid + 256];
    h1[o + tid] = y0;
    h1[o + tid + 256] = y1;
    h1hi[o + tid] = __float2half_rn(y0);
    h1hi[o + tid + 256] = __float2half_rn(y1);
}

// ============================================================================
// LN2 + output transpose
// ============================================================================
__global__ void ln2_kernel(const float* __restrict__ m2,
                           const float* __restrict__ h1,
                           const float* __restrict__ g2, const float* __restrict__ b2,
                           float* __restrict__ out)
{
    __shared__ float sm[16];
    int row = blockIdx.x, tid = threadIdx.x;
    int lane = tid & 31, w = tid >> 5;
    int l = row / B_, b = row % B_;
    size_t base = (size_t)row * C_;
    float v0 = m2[base + tid] + h1[base + tid];
    float v1 = m2[base + tid + 256] + h1[base + tid + 256];
    float s = warpSum(v0 + v1);
    float q = warpSum(v0 * v0 + v1 * v1);
    if (lane == 0) { sm[w] = s; sm[8 + w] = q; }
    __syncthreads();
    float S = 0.f, Q = 0.f;
#pragma unroll
    for (int i = 0; i < 8; i++) { S += sm[i]; Q += sm[8 + i]; }
    float mean = S * (1.f / C_);
    float var = Q * (1.f / C_) - mean * mean;
    float r = rsqrtf(var + 1e-5f);
    size_t ob = (size_t)b * CL_ + l;
    out[ob + (size_t)tid * L_]         = (v0 - mean) * r * g2[tid] + b2[tid];
    out[ob + (size_t)(tid + 256) * L_] = (v1 - mean) * r * g2[tid + 256] + b2[tid + 256];
}

} // namespace

// ============================================================================
// Host launcher
// ============================================================================
extern "C" void kernel_launch(void* const* d_in, const int* in_sizes, int n_in,
                              void* d_out, int out_size)
{
    (void)in_sizes; (void)n_in; (void)out_size;
    float* scratch = nullptr;
    cudaGetSymbolAddress((void**)&scratch, d_scratch);

    const float* x       = (const float*)d_in[0];
    const float* theta_w = (const float*)d_in[1];
    const float* theta_b = (const float*)d_in[2];
    const float* phi_w   = (const float*)d_in[3];
    const float* phi_b   = (const float*)d_in[4];
    const float* g_w     = (const float*)d_in[5];
    const float* g_b     = (const float*)d_in[6];
    const float* wl_w    = (const float*)d_in[7];
    const float* wl_b    = (const float*)d_in[8];
    const float* wg_w    = (const float*)d_in[9];
    const float* wg_b    = (const float*)d_in[10];
    const float* conv1_w = (const float*)d_in[11];
    const float* conv1_b = (const float*)d_in[12];
    const float* conv2_w = (const float*)d_in[13];
    const float* conv2_b = (const float*)d_in[14];
    const float* ln1_g   = (const float*)d_in[15];
    const float* ln1_b   = (const float*)d_in[16];
    const float* ln2_g   = (const float*)d_in[17];
    const float* ln2_b   = (const float*)d_in[18];
    float* out = (float*)d_out;

    __half* xtHi   = (__half*)(scratch + OFF_XT_HI);
    float* xt32    = scratch + OFF_XT32;
    __half* wqkvHi = (__half*)(scratch + OFF_WQKV_HI);
    __half* wqkvLo = (__half*)(scratch + OFF_WQKV_LO);
    float* qkv_b   = scratch + OFF_QKV_B;
    __half* wwgHi  = (__half*)(scratch + OFF_WWG_HI);
    __half* wwgLo  = (__half*)(scratch + OFF_WWG_LO);
    __half* c1wHi  = (__half*)(scratch + OFF_C1WHI);
    __half* c1wLo  = (__half*)(scratch + OFF_C1WLO);
    __half* c2wHi  = (__half*)(scratch + OFF_C2WHI);
    __half* c2wLo  = (__half*)(scratch + OFF_C2WLO);
    __half* qkvHi  = (__half*)(scratch + OFF_QKVT_HI);
    __half* qkvLo  = (__half*)(scratch + OFF_QKVT_LO);
    float* Sg      = scratch + OFF_SG;
    __half* gpHi   = (__half*)(scratch + OFF_GP_HI);
    __half* gg2Hi  = (__half*)(scratch + OFF_GG2_HI);
    __half* gg2Lo  = (__half*)(scratch + OFF_GG2_LO);
    float* gbar    = scratch + OFF_GBAR;
    float* gate    = scratch + OFF_GATE;
    __half* goHi   = (__half*)(scratch + OFF_GOUTT_HI);
    float* gout2T  = scratch + OFF_GOUT2T;
    float* h1      = scratch + OFF_H1;
    __half* h1Hi   = (__half*)(scratch + OFF_H1HI);
    __half* m1Hi   = (__half*)(scratch + OFF_M1HI);
    float* m2      = scratch + OFF_M2;

    // SMEM budgets
    // BN=64 KB=64 3st P2: stage = 18432 + 2*9216 = 36864 -> x3 = 110592 (2/SM)
    // BN=128 KB=32 2st P2: stage = 10240 + 2*10240 = 30720 -> x2 = 61440
    constexpr int SM_64P2  = 110592;
    constexpr int SM_128P2 = 61440;
    cudaFuncSetAttribute(sgsl_gtrans,                         cudaFuncAttributeMaxDynamicSharedMemorySize, SM_64P2);
    cudaFuncSetAttribute(gemm_mma<64, 2, 0, 0, 3, 64, 4, 2>,  cudaFuncAttributeMaxDynamicSharedMemorySize, SM_64P2);
    cudaFuncSetAttribute(gemm_mma<64, 0, 0, 0, 3, 64, 4, 2>,  cudaFuncAttributeMaxDynamicSharedMemorySize, SM_64P2);
    cudaFuncSetAttribute(gemm_mma<128, 1, 0, 0, 2, 32, 2, 2>, cudaFuncAttributeMaxDynamicSharedMemorySize, SM_128P2);
    cudaFuncSetAttribute(gemm_mma<128, 2, 1, 0, 2, 32, 2, 2>, cudaFuncAttributeMaxDynamicSharedMemorySize, SM_128P2);

    // 0) prep: vectorized weight splits (x64) + bias concat + x transpose (f16+f32)
    prep_all<<<PREP_NW4 + PREP_NB + PREP_NT, 256>>>(
        x, theta_w, phi_w, g_w, wg_w, conv1_w, conv2_w, theta_b, phi_b, g_b,
        wqkvHi, wqkvLo, wwgHi, wwgLo, c1wHi, c1wLo, c2wHi, c2wLo, qkv_b, xtHi, xt32);

    // 1) fused qkv (2-pass, weights x64 -> scale 1/64): qkvT hi+lo out
    {
        dim3 grid(C3_ / 128, L_ / 128, B_);
        gemm_mma<128, 1, 0, 0, 2, 32, 2, 2><<<grid, 256, SM_128P2>>>(
            xtHi, nullptr, wqkvHi, wqkvLo, qkv_b, nullptr, qkvHi, qkvLo,
            C_, C_, C_, C3_, (size_t)L_ * C_, 0, (size_t)L_ * C3_, 0, 0, WINV_);
    }

    // 2) Sg & Sl (2-pass) + g-transpose + gbar, ONE launch
    {
        dim3 grid(L_ / 64, L_ / 128, 16 + 8);
        sgsl_gtrans<<<grid, 512, SM_64P2>>>(qkvHi, qkvLo, Sg, gg2Hi, gg2Lo, gbar);
    }

    // 3) fused softmax + local gate
    softmax_gate<<<dim3(L_, B_), 256>>>(Sg, Sg + BLL_, gbar,
                                        wl_w, wl_b, gpHi, gate);

    // 4) goutT = gp @ gg2^T (2-pass, hi out) ; gout2T = goutT @ wg^T + b (2-pass, 1/64)
    {
        dim3 grid(C_ / 64, L_ / 128, B_);
        gemm_mma<64, 2, 0, 0, 3, 64, 4, 2><<<grid, 512, SM_64P2>>>(
            gpHi, nullptr, gg2Hi, gg2Lo, nullptr, nullptr, goHi, nullptr,
            L_, L_, L_, C_, (size_t)L_ * L_, (size_t)CL_, (size_t)L_ * C_, 0, 0, 1.f);
        gemm_mma<64, 0, 0, 0, 3, 64, 4, 2><<<grid, 512, SM_64P2>>>(
            goHi, nullptr, wwgHi, wwgLo, wg_b, gout2T, nullptr, nullptr,
            C_, C_, C_, C_, (size_t)L_ * C_, 0, (size_t)L_ * C_, 0, 0, WINV_);
    }

    // 5) LN1 -> h1 (f32 + f16 hi), fully coalesced
    ln1_kernel<<<dim3(L_, B_), 256>>>(gout2T, gate, xt32, ln1_g, ln1_b, h1, h1Hi);

    // 6) MLP1: m1 = Mish(h1 @ conv1^T * 1/64 + b) -> f16 hi (2-pass)
    {
        dim3 grid(C4_ / 128, NR_ / 128, 1);
        gemm_mma<128, 2, 1, 0, 2, 32, 2, 2><<<grid, 256, SM_128P2>>>(
            h1Hi, nullptr, c1wHi, c1wLo, conv1_b, nullptr, m1Hi, nullptr,
            C_, C_, C_, C4_, 0, 0, 0, 0, 0, WINV_);
    }

    // 7) MLP2: m2 = m1 @ conv2^T * 1/64 + b -> f32 (2-pass)
    {
        dim3 grid(C_ / 64, NR_ / 128, 1);
        gemm_mma<64, 0, 0, 0, 3, 64, 4, 2><<<grid, 512, SM_64P2>>>(
            m1Hi, nullptr, c2wHi, c2wLo, conv2_b, m2, nullptr, nullptr,
            C4_, C4_, C4_, C_, 0, 0, 0, 0, 0, WINV_);
    }

    // 8) LN2 + transpose out
    ln2_kernel<<<NR_, 256>>>(m2, h1, ln2_g, ln2_b, out);
}

// round 12
// speedup vs baseline: 2.0026x; 1.3431x over previous
#include <cuda_runtime.h>
#include <cuda_fp16.h>
#include <math.h>
#include <stdint.h>

// ============================================================================
// Problem constants
// ============================================================================
namespace {
constexpr int B_ = 8, C_ = 512, L_ = 256;
constexpr int CL_ = C_ * L_;           // 131072
constexpr int C3_ = 3 * C_;            // 1536
constexpr int C4_ = 4 * C_;            // 2048
constexpr int NR_ = L_ * B_;           // 2048
constexpr size_t BLL_ = (size_t)B_ * L_ * L_;
constexpr float SCALE_ = 0.044194173824159216f; // 512^-0.5

// ---------------- scratch offsets (float units) ----------------
constexpr size_t OFF_XT_HI   = 0;                                    // f16 [B,L,C]
constexpr size_t OFF_XT32    = OFF_XT_HI   + (size_t)B_ * CL_ / 2;   // f32 [B,L,C]
constexpr size_t OFF_WQKV_HI = OFF_XT32    + (size_t)B_ * CL_;       // f16 [3C,C]
constexpr size_t OFF_QKV_B   = OFF_WQKV_HI + (size_t)C3_ * C_ / 2;   // f32 [1536]
constexpr size_t OFF_WWG_HI  = OFF_QKV_B   + 1536;
constexpr size_t OFF_C1WHI   = OFF_WWG_HI  + (size_t)C_ * C_ / 2;
constexpr size_t OFF_C2WHI   = OFF_C1WHI   + (size_t)C4_ * C_ / 2;
constexpr size_t OFF_QKVT_HI = OFF_C2WHI   + (size_t)C_ * C4_ / 2;   // f16 [B,L,3C]
constexpr size_t OFF_SG      = OFF_QKVT_HI + (size_t)B_ * L_ * C3_ / 2; // f32 [2][B,L,L]
constexpr size_t OFF_GP_HI   = OFF_SG      + 2 * BLL_;               // f16 [B,L,L]
constexpr size_t OFF_GG2_HI  = OFF_GP_HI   + BLL_ / 2;               // f16 [B,C,L]
constexpr size_t OFF_GBAR    = OFF_GG2_HI  + (size_t)B_ * CL_ / 2;
constexpr size_t OFF_GATE    = OFF_GBAR    + (size_t)B_ * L_;
constexpr size_t OFF_GOUTT_HI= OFF_GATE    + (size_t)B_ * L_;        // f16 [B,L,C]
constexpr size_t OFF_GOUT2T  = OFF_GOUTT_HI+ (size_t)B_ * CL_ / 2;   // f32 [B,L,C]
constexpr size_t OFF_H1      = OFF_GOUT2T  + (size_t)B_ * CL_;       // f32 [NR,C]
constexpr size_t OFF_H1HI    = OFF_H1      + (size_t)NR_ * C_;       // f16 [NR,C]
constexpr size_t OFF_M1HI    = OFF_H1HI    + (size_t)NR_ * C_ / 2;   // f16 [NR,C4]
constexpr size_t OFF_M2      = OFF_M1HI    + (size_t)NR_ * C4_ / 2;  // f32 [NR,C]
constexpr size_t SCRATCH_TOTAL = OFF_M2    + (size_t)NR_ * C_;
} // namespace

__device__ __align__(256) float d_scratch[SCRATCH_TOTAL];

// ============================================================================
// PTX helpers — sm_80-era only (mma.sync / ldmatrix / cp.async).
// ============================================================================
__device__ __forceinline__ uint32_t smem_to_u32(const void* p) {
    uint32_t a;
    asm("{ .reg .u64 t; cvta.to.shared.u64 t, %1; cvt.u32.u64 %0, t; }" : "=r"(a) : "l"(p));
    return a;
}
__device__ __forceinline__ void ldmat4(uint32_t (&r)[4], uint32_t addr) {
    asm volatile("ldmatrix.sync.aligned.m8n8.x4.shared.b16 {%0,%1,%2,%3}, [%4];"
                 : "=r"(r[0]), "=r"(r[1]), "=r"(r[2]), "=r"(r[3]) : "r"(addr));
}
__device__ __forceinline__ void mma16816(float (&d)[4], const uint32_t (&a)[4], const uint32_t b0, const uint32_t b1) {
    asm volatile("mma.sync.aligned.m16n8k16.row.col.f32.f16.f16.f32 "
                 "{%0,%1,%2,%3}, {%4,%5,%6,%7}, {%8,%9}, {%0,%1,%2,%3};"
                 : "+f"(d[0]), "+f"(d[1]), "+f"(d[2]), "+f"(d[3])
                 : "r"(a[0]), "r"(a[1]), "r"(a[2]), "r"(a[3]), "r"(b0), "r"(b1));
}
__device__ __forceinline__ void cp16(uint32_t saddr, const void* g) {
    asm volatile("cp.async.cg.shared.global [%0], [%1], 16;" :: "r"(saddr), "l"(g));
}
#define CP_COMMIT() asm volatile("cp.async.commit_group;" ::: "memory")
template <int N>
__device__ __forceinline__ void cp_wait() {
    asm volatile("cp.async.wait_group %0;" :: "n"(N) : "memory");
}

namespace {

__device__ __forceinline__ float warpSum(float v) {
#pragma unroll
    for (int o = 16; o; o >>= 1) v += __shfl_xor_sync(0xffffffffu, v, o);
    return v;
}
__device__ __forceinline__ float warpMax(float v) {
#pragma unroll
    for (int o = 16; o; o >>= 1) v = fmaxf(v, __shfl_xor_sync(0xffffffffu, v, o));
    return v;
}
__device__ __forceinline__ float mishf(float v) {
    float sp = fmaxf(v, 0.f) + log1pf(__expf(-fabsf(v)));
    return v * tanhf(sp);
}

// ============================================================================
// fp16 tensor-core GEMM body (device function; shared by kernels).
// NT: A [M,K] K-contig (lda) ; B [N,K] K-contig (ldb). Plain 1-pass fp16:
//   D = A·B^T (fp32 accum), v = scale*D (+ biasN); ACT=1 -> mish.
// OUTFMT 0: f32 ; 2: f16.
// FUSE=1: z encodes (sel = z>>3, b = z&7); B += sel*selB, out += sel*selO.
// WM = warps along M (2 -> 256 thr; 4 -> 512 thr). 4 warps along N always.
// ============================================================================
template <int BN, int OUTFMT, int ACT, int FUSE, int STAGES, int KB, int WM>
__device__ __forceinline__ void gemm_body(
    const __half* __restrict__ A, const __half* __restrict__ Bm,
    const float* __restrict__ biasN,
    float* __restrict__ outF, __half* __restrict__ outH,
    int K, int lda, int ldb, int ldOut,
    size_t sA, size_t sB, size_t sO, size_t selB, size_t selO, float scale,
    char* smem)
{
    constexpr int BM = 128;
    constexpr int TPB = WM * 128;
    constexpr int MI = BM / (WM * 16);
    constexpr int SROW = KB * 2 + 16;
    constexpr int CHR = KB / 8;
    constexpr int ATILE = BM * SROW;
    constexpr int BTILE = BN * SROW;
    constexpr int STAGE = ATILE + BTILE;
    constexpr int WN = BN / 4;
    constexpr int NFRAG = WN / 8;
    constexpr int NKS = KB / 16;

    const uint32_t sb = smem_to_u32(smem);
    const int tid = threadIdx.x, lane = tid & 31, wid = tid >> 5;
    const int wm = wid & (WM - 1), wn = wid / WM;
    const int m0 = blockIdx.y * BM, n0 = blockIdx.x * BN;
    const int z = blockIdx.z;
    const int b = FUSE ? (z & 7) : z;
    const int sel = FUSE ? (z >> 3) : 0;

    A += (size_t)b * sA;
    Bm += (size_t)b * sB + (size_t)sel * selB;
    if (OUTFMT == 0) outF += (size_t)b * sO + (size_t)sel * selO;
    else             outH += (size_t)b * sO + (size_t)sel * selO;

    float acc[MI][NFRAG][4];
#pragma unroll
    for (int i = 0; i < MI; i++)
#pragma unroll
        for (int j = 0; j < NFRAG; j++)
#pragma unroll
            for (int q = 0; q < 4; q++) acc[i][j][q] = 0.f;

    auto load_stage = [&](int ch, int st) {
        const int k0 = ch * KB;
        const uint32_t base = sb + st * STAGE;
#pragma unroll
        for (int c = tid; c < BM * CHR; c += TPB) {
            int r = c / CHR, cc = c % CHR;
            cp16(base + r * SROW + cc * 16, A + (size_t)(m0 + r) * lda + k0 + cc * 8);
        }
#pragma unroll
        for (int c = tid; c < BN * CHR; c += TPB) {
            int r = c / CHR, cc = c % CHR;
            cp16(base + ATILE + r * SROW + cc * 16, Bm + (size_t)(n0 + r) * ldb + k0 + cc * 8);
        }
        CP_COMMIT();
    };

    const int nch = K / KB;
#pragma unroll
    for (int s = 0; s < STAGES - 1; s++) load_stage(s, s);

    int cs = 0;
    int ps = (STAGES - 1) % STAGES;
    for (int ch = 0; ch < nch; ch++) {
        cp_wait<STAGES - 2>();
        __syncthreads();
        const int pf = ch + STAGES - 1;
        if (pf < nch) load_stage(pf, ps);
        else CP_COMMIT();

        const uint32_t aBase = sb + cs * STAGE;
        const uint32_t bBase = aBase + ATILE;
#pragma unroll
        for (int ks = 0; ks < NKS; ks++) {
            const uint32_t colOff = (uint32_t)(ks * 2 + (lane >> 4)) * 16;
            uint32_t a_f[MI][4];
#pragma unroll
            for (int mi = 0; mi < MI; mi++) {
                uint32_t addr = aBase + (uint32_t)(wm * (MI * 16) + mi * 16 + (lane & 15)) * SROW + colOff;
                ldmat4(a_f[mi], addr);
            }
#pragma unroll
            for (int nt = 0; nt < NFRAG / 2; nt++) {
                uint32_t addr = bBase + (uint32_t)(wn * WN + nt * 16 + (lane & 15)) * SROW + colOff;
                uint32_t bf[4];
                ldmat4(bf, addr);
#pragma unroll
                for (int half = 0; half < 2; half++) {
                    const int ni = nt * 2 + half;
#pragma unroll
                    for (int mi = 0; mi < MI; mi++)
                        mma16816(acc[mi][ni], a_f[mi], bf[half], bf[2 + half]);
                }
            }
        }
        cs = (cs + 1 == STAGES) ? 0 : cs + 1;
        ps = (ps + 1 == STAGES) ? 0 : ps + 1;
    }

    // ---------------- epilogue ----------------
    const int g = lane >> 2, tg = lane & 3;
#pragma unroll
    for (int mi = 0; mi < MI; mi++) {
#pragma unroll
        for (int ni = 0; ni < NFRAG; ni++) {
            const int col = n0 + wn * WN + ni * 8 + tg * 2;
            const float b0 = biasN ? biasN[col] : 0.f;
            const float b1 = biasN ? biasN[col + 1] : 0.f;
#pragma unroll
            for (int h = 0; h < 2; h++) {
                const int row = m0 + wm * (MI * 16) + mi * 16 + g + h * 8;
                float v0 = acc[mi][ni][h * 2 + 0] * scale + b0;
                float v1 = acc[mi][ni][h * 2 + 1] * scale + b1;
                if (ACT == 1) { v0 = mishf(v0); v1 = mishf(v1); }
                const size_t o = (size_t)row * ldOut + col;
                if (OUTFMT == 0) {
                    float2 fp; fp.x = v0; fp.y = v1;
                    *(float2*)(outF + o) = fp;
                } else {
                    __half2 hp;
                    hp.x = __float2half_rn(v0);
                    hp.y = __float2half_rn(v1);
                    *(__half2*)(outH + o) = hp;
                }
            }
        }
    }
}

template <int BN, int OUTFMT, int ACT, int FUSE, int STAGES, int KB, int WM>
__global__ void __launch_bounds__(WM * 128) gemm_mma(
    const __half* __restrict__ A, const __half* __restrict__ Bm,
    const float* __restrict__ biasN,
    float* __restrict__ outF, __half* __restrict__ outH,
    int K, int lda, int ldb, int ldOut,
    size_t sA, size_t sB, size_t sO, size_t selB, size_t selO, float scale)
{
    extern __shared__ char smem[];
    gemm_body<BN, OUTFMT, ACT, FUSE, STAGES, KB, WM>(
        A, Bm, biasN, outF, outH,
        K, lda, ldb, ldOut, sA, sB, sO, selB, selO, scale, smem);
}

// ============================================================================
// Fused Sg/Sl GEMM (z<16) + g-transpose/gbar (z>=16) in ONE launch.
// Grid (4, 2, 24), 512 threads.
// z in [16,24): vb = (z-16)*8 + by*4 + bx in [0,64): b = vb>>3, l0 = (vb&7)*32.
// ============================================================================
__global__ void __launch_bounds__(512) sgsl_gtrans(
    const __half* __restrict__ qkvHi,
    float* __restrict__ Sg,
    __half* __restrict__ gg2Hi,
    float* __restrict__ gbar)
{
    extern __shared__ char smem[];
    if (blockIdx.z < 16) {
        gemm_body<64, 0, 0, 1, 3, 64, 4>(
            qkvHi + C_, qkvHi, nullptr, Sg, nullptr,
            C_, C3_, C3_, L_, (size_t)L_ * C3_, (size_t)L_ * C3_, (size_t)L_ * L_,
            (size_t)(2 * C_), BLL_, SCALE_, smem);
        return;
    }
    // ---- transpose + gbar path (all 512 threads) ----
    __half (*th)[34] = (__half(*)[34])smem;
    const int vb = (blockIdx.z - 16) * 8 + blockIdx.y * 4 + blockIdx.x;
    const int b = vb >> 3;
    const int l0 = (vb & 7) * 32;
    const int tid = threadIdx.x;
    const int tx = tid & 31, ty = tid >> 5;            // ty in 0..15

    for (int ct = 0; ct < 16; ct++) {
        const int c0 = ct * 32;
#pragma unroll
        for (int j = 0; j < 2; j++) {
            size_t idx = ((size_t)b * L_ + l0 + ty + j * 16) * C3_ + 2 * C_ + c0 + tx;
            th[ty + j * 16][tx] = qkvHi[idx];
        }
        __syncthreads();
#pragma unroll
        for (int j = 0; j < 2; j++) {
            int c = c0 + ty + j * 16;
            size_t o = ((size_t)b * C_ + c) * L_ + l0 + tx;
            gg2Hi[o] = th[tx][ty + j * 16];
        }
        __syncthreads();
    }
    // gbar: 16 warps, each handles 2 l values
#pragma unroll
    for (int i = 0; i < 2; i++) {
        const int l = l0 + ty * 2 + i;
        const size_t base = ((size_t)b * L_ + l) * C3_ + 2 * C_;
        float s = 0.f;
#pragma unroll
        for (int c = tx; c < C_; c += 32)
            s += __half2float(qkvHi[base + c]);
        s = warpSum(s);
        if (tx == 0) gbar[b * L_ + l] = s * (1.f / C_);
    }
}

// ============================================================================
// prep_all: ONE launch = vectorized fp16 weight conversion + qkv bias + x transpose
// ============================================================================
constexpr int PREP_WELEMS = 3 * C_ * C_ + C_ * C_ + C4_ * C_ + C_ * C4_;  // 3145728
constexpr int PREP_NW4 = PREP_WELEMS / 4 / 256;       // 3072 blocks
constexpr int PREP_NB = 6;
constexpr int PREP_NT = (L_ / 32) * (C_ / 32) * B_;   // 1024 blocks

__global__ void prep_all(const float* __restrict__ x,
                         const float* __restrict__ tw, const float* __restrict__ pw,
                         const float* __restrict__ gw, const float* __restrict__ wgw,
                         const float* __restrict__ c1w, const float* __restrict__ c2w,
                         const float* __restrict__ tb, const float* __restrict__ pb,
                         const float* __restrict__ gb,
                         __half* __restrict__ qkvW, __half* __restrict__ wgW,
                         __half* __restrict__ c1W, __half* __restrict__ c2W,
                         float* __restrict__ qkvb,
                         __half* __restrict__ xtHi, float* __restrict__ xt32)
{
    __shared__ float t[32][33];
    const int bid = blockIdx.x;
    if (bid < PREP_NW4) {
        constexpr int NW = C_ * C_;
        constexpr int N1 = 3 * NW;
        constexpr int N2 = N1 + NW;
        constexpr int N3 = N2 + C4_ * C_;
        const int i = (bid * 256 + threadIdx.x) * 4;
        const float* src;
        __half* dst;
        int j;
        if (i < N1) {
            j = i & (NW - 1);
            src = (i < NW) ? tw : (i < 2 * NW ? pw : gw);
            dst = qkvW + i;
        } else if (i < N2) {
            j = i - N1; src = wgw; dst = wgW + j;
        } else if (i < N3) {
            j = i - N2; src = c1w; dst = c1W + j;
        } else {
            j = i - N3; src = c2w; dst = c2W + j;
        }
        float4 v4 = *(const float4*)(src + j);
        __half2 h0, h1;
        h0.x = __float2half_rn(v4.x); h0.y = __float2half_rn(v4.y);
        h1.x = __float2half_rn(v4.z); h1.y = __float2half_rn(v4.w);
        *(__half2*)(dst)     = h0;
        *(__half2*)(dst + 2) = h1;
    } else if (bid < PREP_NW4 + PREP_NB) {
        const int j = (bid - PREP_NW4) * 256 + threadIdx.x;
        if (j < C3_)
            qkvb[j] = (j < C_) ? tb[j] : (j < 2 * C_ ? pb[j - C_] : gb[j - 2 * C_]);
    } else {
        const int tI = bid - PREP_NW4 - PREP_NB;
        const int b = tI >> 7;
        const int rem = tI & 127;
        const int c0 = (rem & 15) * 32;
        const int l0 = (rem >> 4) * 32;
        const int tx = threadIdx.x & 31, ty = threadIdx.x >> 5;
        const float* xb = x + (size_t)b * CL_;
#pragma unroll
        for (int j = 0; j < 4; j++)
            t[ty + j * 8][tx] = xb[(size_t)(c0 + ty + j * 8) * L_ + l0 + tx];
        __syncthreads();
#pragma unroll
        for (int j = 0; j < 4; j++) {
            int l = l0 + ty + j * 8;
            float v = t[tx][ty + j * 8];
            size_t o = ((size_t)b * L_ + l) * C_ + c0 + tx;
            xtHi[o] = __float2half_rn(v);
            xt32[o] = v;
        }
    }
}

// ============================================================================
// Fused: softmax(Sg row) -> gp f16  AND  banded local gate from Sl row.
// ============================================================================
__global__ void softmax_gate(const float* __restrict__ Sg,
                             const float* __restrict__ Sl,
                             const float* __restrict__ gbar,
                             const float* __restrict__ wlw,
                             const float* __restrict__ wlb,
                             __half* __restrict__ pHi,
                             float* __restrict__ gate)
{
    __shared__ float sm[16];
    const int l = blockIdx.x, b = blockIdx.y, tid = threadIdx.x;
    const int lane = tid & 31, w = tid >> 5;
    const size_t row = (size_t)b * L_ + l;

    float v = Sg[row * L_ + tid];
    float m = warpMax(v);
    if (lane == 0) sm[w] = m;
    __syncthreads();
    float M = -1e30f;
#pragma unroll
    for (int i = 0; i < 8; i++) M = fmaxf(M, sm[i]);
    float e = __expf(v - M);
    float s = warpSum(e);
    if (lane == 0) sm[8 + w] = s;
    __syncthreads();
    float T = 0.f;
#pragma unroll
    for (int i = 0; i < 8; i++) T += sm[8 + i];
    pHi[row * L_ + tid] = __float2half_rn(e / T);

    if (w == 0) {
        const float* srow = Sl + row * L_;
        const float* gb = gbar + (size_t)b * L_;
        int m0 = l + lane - 32;
        int m1 = l + lane;
        bool v0 = (m0 >= 0) && (m0 < L_);
        bool v1 = (m1 >= 0) && (m1 < L_);
        float s0 = v0 ? srow[m0] : 0.f;
        float s1 = v1 ? srow[m1] : 0.f;
        float g0 = v0 ? gb[m0] : 0.f;
        float g1 = v1 ? gb[m1] : 0.f;
        float mx = warpMax(fmaxf(s0, s1));
        float e0 = __expf(s0 - mx), e1 = __expf(s1 - mx);
        float num = warpSum(e0 * g0 + e1 * g1);
        float den = warpSum(e0 + e1);
        if (lane == 0) {
            float pooled = num / den;
            float z = wlw[0] * pooled + wlb[0];
            gate[b * L_ + l] = 1.f / (1.f + __expf(-z));
        }
    }
}

// ============================================================================
// LN1: h = gout2T*gate + xT32 ; h1 f32 + f16 at row (l*B+b), [*,C]
// ============================================================================
__global__ void ln1_kernel(const float* __restrict__ gout2T,
                           const float* __restrict__ gate,
                           const float* __restrict__ xt32,
                           const float* __restrict__ g1, const float* __restrict__ b1,
                           float* __restrict__ h1,
                           __half* __restrict__ h1hi)
{
    __shared__ float sm[16];
    int l = blockIdx.x, b = blockIdx.y, tid = threadIdx.x;
    int lane = tid & 31, w = tid >> 5;
    float gt = gate[b * L_ + l];
    size_t gbase = ((size_t)b * L_ + l) * C_;
    float v0 = fmaf(gout2T[gbase + tid], gt, xt32[gbase + tid]);
    float v1 = fmaf(gout2T[gbase + tid + 256], gt, xt32[gbase + tid + 256]);
    float s = warpSum(v0 + v1);
    float q = warpSum(v0 * v0 + v1 * v1);
    if (lane == 0) { sm[w] = s; sm[8 + w] = q; }
    __syncthreads();
    float S = 0.f, Q = 0.f;
#pragma unroll
    for (int i = 0; i < 8; i++) { S += sm[i]; Q += sm[8 + i]; }
    float mean = S * (1.f / C_);
    float var = Q * (1.f / C_) - mean * mean;
    float r = rsqrtf(var + 1e-5f);
    size_t o = ((size_t)l * B_ + b) * C_;
    float y0 = (v0 - mean) * r * g1[tid] + b1[tid];
    float y1 = (v1 - mean) * r * g1[tid + 256] + b1[tid + 256];
    h1[o + tid] = y0;
    h1[o + tid + 256] = y1;
    h1hi[o + tid] = __float2half_rn(y0);
    h1hi[o + tid + 256] = __float2half_rn(y1);
}

// ============================================================================
// LN2 + output transpose
// ============================================================================
__global__ void ln2_kernel(const float* __restrict__ m2,
                           const float* __restrict__ h1,
                           const float* __restrict__ g2, const float* __restrict__ b2,
                           float* __restrict__ out)
{
    __shared__ float sm[16];
    int row = blockIdx.x, tid = threadIdx.x;
    int lane = tid & 31, w = tid >> 5;
    int l = row / B_, b = row % B_;
    size_t base = (size_t)row * C_;
    float v0 = m2[base + tid] + h1[base + tid];
    float v1 = m2[base + tid + 256] + h1[base + tid + 256];
    float s = warpSum(v0 + v1);
    float q = warpSum(v0 * v0 + v1 * v1);
    if (lane == 0) { sm[w] = s; sm[8 + w] = q; }
    __syncthreads();
    float S = 0.f, Q = 0.f;
#pragma unroll
    for (int i = 0; i < 8; i++) { S += sm[i]; Q += sm[8 + i]; }
    float mean = S * (1.f / C_);
    float var = Q * (1.f / C_) - mean * mean;
    float r = rsqrtf(var + 1e-5f);
    size_t ob = (size_t)b * CL_ + l;
    out[ob + (size_t)tid * L_]         = (v0 - mean) * r * g2[tid] + b2[tid];
    out[ob + (size_t)(tid + 256) * L_] = (v1 - mean) * r * g2[tid + 256] + b2[tid + 256];
}

} // namespace

// ============================================================================
// Host launcher
// ============================================================================
extern "C" void kernel_launch(void* const* d_in, const int* in_sizes, int n_in,
                              void* d_out, int out_size)
{
    (void)in_sizes; (void)n_in; (void)out_size;
    float* scratch = nullptr;
    cudaGetSymbolAddress((void**)&scratch, d_scratch);

    const float* x       = (const float*)d_in[0];
    const float* theta_w = (const float*)d_in[1];
    const float* theta_b = (const float*)d_in[2];
    const float* phi_w   = (const float*)d_in[3];
    const float* phi_b   = (const float*)d_in[4];
    const float* g_w     = (const float*)d_in[5];
    const float* g_b     = (const float*)d_in[6];
    const float* wl_w    = (const float*)d_in[7];
    const float* wl_b    = (const float*)d_in[8];
    const float* wg_w    = (const float*)d_in[9];
    const float* wg_b    = (const float*)d_in[10];
    const float* conv1_w = (const float*)d_in[11];
    const float* conv1_b = (const float*)d_in[12];
    const float* conv2_w = (const float*)d_in[13];
    const float* conv2_b = (const float*)d_in[14];
    const float* ln1_g   = (const float*)d_in[15];
    const float* ln1_b   = (const float*)d_in[16];
    const float* ln2_g   = (const float*)d_in[17];
    const float* ln2_b   = (const float*)d_in[18];
    float* out = (float*)d_out;

    __half* xtHi   = (__half*)(scratch + OFF_XT_HI);
    float* xt32    = scratch + OFF_XT32;
    __half* wqkvW  = (__half*)(scratch + OFF_WQKV_HI);
    float* qkv_b   = scratch + OFF_QKV_B;
    __half* wwgW   = (__half*)(scratch + OFF_WWG_HI);
    __half* c1W    = (__half*)(scratch + OFF_C1WHI);
    __half* c2W    = (__half*)(scratch + OFF_C2WHI);
    __half* qkvHi  = (__half*)(scratch + OFF_QKVT_HI);
    float* Sg      = scratch + OFF_SG;
    __half* gpHi   = (__half*)(scratch + OFF_GP_HI);
    __half* gg2Hi  = (__half*)(scratch + OFF_GG2_HI);
    float* gbar    = scratch + OFF_GBAR;
    float* gate    = scratch + OFF_GATE;
    __half* goHi   = (__half*)(scratch + OFF_GOUTT_HI);
    float* gout2T  = scratch + OFF_GOUT2T;
    float* h1      = scratch + OFF_H1;
    __half* h1Hi   = (__half*)(scratch + OFF_H1HI);
    __half* m1Hi   = (__half*)(scratch + OFF_M1HI);
    float* m2      = scratch + OFF_M2;

    // SMEM: BN=64 KB=64 3st 1-pass: stage = 18432+9216 = 27648 -> x3 = 82944
    //       BN=128 KB=32 2st 1-pass: stage = 10240+10240 = 20480 -> x2 = 40960
    constexpr int SM_64  = 82944;
    constexpr int SM_128 = 40960;
    cudaFuncSetAttribute(sgsl_gtrans,                      cudaFuncAttributeMaxDynamicSharedMemorySize, SM_64);
    cudaFuncSetAttribute(gemm_mma<64, 2, 0, 0, 3, 64, 4>,  cudaFuncAttributeMaxDynamicSharedMemorySize, SM_64);
    cudaFuncSetAttribute(gemm_mma<64, 0, 0, 0, 3, 64, 4>,  cudaFuncAttributeMaxDynamicSharedMemorySize, SM_64);
    cudaFuncSetAttribute(gemm_mma<128, 2, 0, 0, 2, 32, 2>, cudaFuncAttributeMaxDynamicSharedMemorySize, SM_128);
    cudaFuncSetAttribute(gemm_mma<128, 2, 1, 0, 2, 32, 2>, cudaFuncAttributeMaxDynamicSharedMemorySize, SM_128);

    // 0) prep: weight fp16 conversion + bias concat + x transpose (f16 + f32)
    prep_all<<<PREP_NW4 + PREP_NB + PREP_NT, 256>>>(
        x, theta_w, phi_w, g_w, wg_w, conv1_w, conv2_w, theta_b, phi_b, g_b,
        wqkvW, wwgW, c1W, c2W, qkv_b, xtHi, xt32);

    // 1) fused qkv: qkvT[b,l,:] = xT(b) @ [th;ph;g]^T + bias -> f16
    {
        dim3 grid(C3_ / 128, L_ / 128, B_);
        gemm_mma<128, 2, 0, 0, 2, 32, 2><<<grid, 256, SM_128>>>(
            xtHi, wqkvW, qkv_b, nullptr, qkvHi,
            C_, C_, C_, C3_, (size_t)L_ * C_, 0, (size_t)L_ * C3_, 0, 0, 1.f);
    }

    // 2) Sg & Sl + g-transpose + gbar, ONE launch
    {
        dim3 grid(L_ / 64, L_ / 128, 16 + 8);
        sgsl_gtrans<<<grid, 512, SM_64>>>(qkvHi, Sg, gg2Hi, gbar);
    }

    // 3) fused softmax + local gate
    softmax_gate<<<dim3(L_, B_), 256>>>(Sg, Sg + BLL_, gbar,
                                        wl_w, wl_b, gpHi, gate);

    // 4) goutT = gp @ gg2^T -> f16 ; gout2T = goutT @ wg^T + wg_b -> f32
    {
        dim3 grid(C_ / 64, L_ / 128, B_);
        gemm_mma<64, 2, 0, 0, 3, 64, 4><<<grid, 512, SM_64>>>(
            gpHi, gg2Hi, nullptr, nullptr, goHi,
            L_, L_, L_, C_, (size_t)L_ * L_, (size_t)CL_, (size_t)L_ * C_, 0, 0, 1.f);
        gemm_mma<64, 0, 0, 0, 3, 64, 4><<<grid, 512, SM_64>>>(
            goHi, wwgW, wg_b, gout2T, nullptr,
            C_, C_, C_, C_, (size_t)L_ * C_, 0, (size_t)L_ * C_, 0, 0, 1.f);
    }

    // 5) LN1 -> h1 (f32 + f16)
    ln1_kernel<<<dim3(L_, B_), 256>>>(gout2T, gate, xt32, ln1_g, ln1_b, h1, h1Hi);

    // 6) MLP1: m1 = Mish(h1 @ conv1^T + b) -> f16
    {
        dim3 grid(C4_ / 128, NR_ / 128, 1);
        gemm_mma<128, 2, 1, 0, 2, 32, 2><<<grid, 256, SM_128>>>(
            h1Hi, c1W, conv1_b, nullptr, m1Hi,
            C_, C_, C_, C4_, 0, 0, 0, 0, 0, 1.f);
    }

    // 7) MLP2: m2 = m1 @ conv2^T + b -> f32
    {
        dim3 grid(C_ / 64, NR_ / 128, 1);
        gemm_mma<64, 0, 0, 0, 3, 64, 4><<<grid, 512, SM_64>>>(
            m1Hi, c2W, conv2_b, m2, nullptr,
            C4_, C4_, C4_, C_, 0, 0, 0, 0, 0, 1.f);
    }

    // 8) LN2 + transpose out
    ln2_kernel<<<NR_, 256>>>(m2, h1, ln2_g, ln2_b, out);
}

// round 13
// speedup vs baseline: 2.0642x; 1.0308x over previous
#include <cuda_runtime.h>
#include <cuda_fp16.h>
#include <math.h>
#include <stdint.h>

// ============================================================================
// Problem constants
// ============================================================================
namespace {
constexpr int B_ = 8, C_ = 512, L_ = 256;
constexpr int CL_ = C_ * L_;           // 131072
constexpr int C3_ = 3 * C_;            // 1536
constexpr int C4_ = 4 * C_;            // 2048
constexpr int NR_ = L_ * B_;           // 2048
constexpr size_t BLL_ = (size_t)B_ * L_ * L_;
constexpr float SCALE_ = 0.044194173824159216f; // 512^-0.5

// ---------------- scratch offsets (float units) ----------------
constexpr size_t OFF_XT_HI   = 0;                                    // f16 [B,L,C]
constexpr size_t OFF_XT32    = OFF_XT_HI   + (size_t)B_ * CL_ / 2;   // f32 [B,L,C]
constexpr size_t OFF_WQKV_HI = OFF_XT32    + (size_t)B_ * CL_;       // f16 [3C,C]
constexpr size_t OFF_QKV_B   = OFF_WQKV_HI + (size_t)C3_ * C_ / 2;   // f32 [1536]
constexpr size_t OFF_WWG_HI  = OFF_QKV_B   + 1536;
constexpr size_t OFF_C1WHI   = OFF_WWG_HI  + (size_t)C_ * C_ / 2;
constexpr size_t OFF_C2WHI   = OFF_C1WHI   + (size_t)C4_ * C_ / 2;
constexpr size_t OFF_QKVT_HI = OFF_C2WHI   + (size_t)C_ * C4_ / 2;   // f16 [B,L,3C]
constexpr size_t OFF_SG      = OFF_QKVT_HI + (size_t)B_ * L_ * C3_ / 2; // f32 [2][B,L,L]
constexpr size_t OFF_GP_HI   = OFF_SG      + 2 * BLL_;               // f16 [B,L,L]
constexpr size_t OFF_GG2_HI  = OFF_GP_HI   + BLL_ / 2;               // f16 [B,C,L]
constexpr size_t OFF_GBAR    = OFF_GG2_HI  + (size_t)B_ * CL_ / 2;
constexpr size_t OFF_GATE    = OFF_GBAR    + (size_t)B_ * L_;
constexpr size_t OFF_GOUTT_HI= OFF_GATE    + (size_t)B_ * L_;        // f16 [B,L,C]
constexpr size_t OFF_GOUT2T  = OFF_GOUTT_HI+ (size_t)B_ * CL_ / 2;   // f32 [B,L,C]
constexpr size_t OFF_H1      = OFF_GOUT2T  + (size_t)B_ * CL_;       // f32 [NR,C]
constexpr size_t OFF_H1HI    = OFF_H1      + (size_t)NR_ * C_;       // f16 [NR,C]
constexpr size_t OFF_M1HI    = OFF_H1HI    + (size_t)NR_ * C_ / 2;   // f16 [NR,C4]
constexpr size_t OFF_M2      = OFF_M1HI    + (size_t)NR_ * C4_ / 2;  // f32 [NR,C]
constexpr size_t SCRATCH_TOTAL = OFF_M2    + (size_t)NR_ * C_;
} // namespace

__device__ __align__(256) float d_scratch[SCRATCH_TOTAL];

// ============================================================================
// PTX helpers — sm_80-era only (mma.sync / ldmatrix / cp.async).
// ============================================================================
__device__ __forceinline__ uint32_t smem_to_u32(const void* p) {
    uint32_t a;
    asm("{ .reg .u64 t; cvta.to.shared.u64 t, %1; cvt.u32.u64 %0, t; }" : "=r"(a) : "l"(p));
    return a;
}
__device__ __forceinline__ void ldmat4(uint32_t (&r)[4], uint32_t addr) {
    asm volatile("ldmatrix.sync.aligned.m8n8.x4.shared.b16 {%0,%1,%2,%3}, [%4];"
                 : "=r"(r[0]), "=r"(r[1]), "=r"(r[2]), "=r"(r[3]) : "r"(addr));
}
__device__ __forceinline__ void mma16816(float (&d)[4], const uint32_t (&a)[4], const uint32_t b0, const uint32_t b1) {
    asm volatile("mma.sync.aligned.m16n8k16.row.col.f32.f16.f16.f32 "
                 "{%0,%1,%2,%3}, {%4,%5,%6,%7}, {%8,%9}, {%0,%1,%2,%3};"
                 : "+f"(d[0]), "+f"(d[1]), "+f"(d[2]), "+f"(d[3])
                 : "r"(a[0]), "r"(a[1]), "r"(a[2]), "r"(a[3]), "r"(b0), "r"(b1));
}
__device__ __forceinline__ void cp16(uint32_t saddr, const void* g) {
    asm volatile("cp.async.cg.shared.global [%0], [%1], 16;" :: "r"(saddr), "l"(g));
}
#define CP_COMMIT() asm volatile("cp.async.commit_group;" ::: "memory")
template <int N>
__device__ __forceinline__ void cp_wait() {
    asm volatile("cp.async.wait_group %0;" :: "n"(N) : "memory");
}

namespace {

__device__ __forceinline__ float warpSum(float v) {
#pragma unroll
    for (int o = 16; o; o >>= 1) v += __shfl_xor_sync(0xffffffffu, v, o);
    return v;
}
__device__ __forceinline__ float warpMax(float v) {
#pragma unroll
    for (int o = 16; o; o >>= 1) v = fmaxf(v, __shfl_xor_sync(0xffffffffu, v, o));
    return v;
}
__device__ __forceinline__ float mishf(float v) {
    float sp = fmaxf(v, 0.f) + log1pf(__expf(-fabsf(v)));
    return v * tanhf(sp);
}

// ============================================================================
// fp16 tensor-core GEMM body. 1-pass plain fp16, NT layout:
//   A [M,K] K-contig (lda) ; B [N,K] K-contig (ldb). D = A·B^T (fp32 accum).
// v = scale*D (+ biasN); ACT=1 -> mish. OUTFMT 0: f32 ; 2: f16.
// FUSE=1: z encodes (sel = z>>3, b = z&7); B += sel*selB, out += sel*selO.
// WM = warps along M (2 -> 256 thr; 4 -> 512 thr). 4 warps along N always.
// ============================================================================
template <int BN, int OUTFMT, int ACT, int FUSE, int STAGES, int KB, int WM>
__device__ __forceinline__ void gemm_body(
    const __half* __restrict__ A, const __half* __restrict__ Bm,
    const float* __restrict__ biasN,
    float* __restrict__ outF, __half* __restrict__ outH,
    int K, int lda, int ldb, int ldOut,
    size_t sA, size_t sB, size_t sO, size_t selB, size_t selO, float scale,
    char* smem)
{
    constexpr int BM = 128;
    constexpr int TPB = WM * 128;
    constexpr int MI = BM / (WM * 16);
    constexpr int SROW = KB * 2 + 16;
    constexpr int CHR = KB / 8;
    constexpr int ATILE = BM * SROW;
    constexpr int BTILE = BN * SROW;
    constexpr int STAGE = ATILE + BTILE;
    constexpr int WN = BN / 4;
    constexpr int NFRAG = WN / 8;
    constexpr int NKS = KB / 16;

    const uint32_t sb = smem_to_u32(smem);
    const int tid = threadIdx.x, lane = tid & 31, wid = tid >> 5;
    const int wm = wid & (WM - 1), wn = wid / WM;
    const int m0 = blockIdx.y * BM, n0 = blockIdx.x * BN;
    const int z = blockIdx.z;
    const int b = FUSE ? (z & 7) : z;
    const int sel = FUSE ? (z >> 3) : 0;

    A += (size_t)b * sA;
    Bm += (size_t)b * sB + (size_t)sel * selB;
    if (OUTFMT == 0) outF += (size_t)b * sO + (size_t)sel * selO;
    else             outH += (size_t)b * sO + (size_t)sel * selO;

    float acc[MI][NFRAG][4];
#pragma unroll
    for (int i = 0; i < MI; i++)
#pragma unroll
        for (int j = 0; j < NFRAG; j++)
#pragma unroll
            for (int q = 0; q < 4; q++) acc[i][j][q] = 0.f;

    auto load_stage = [&](int ch, int st) {
        const int k0 = ch * KB;
        const uint32_t base = sb + st * STAGE;
#pragma unroll
        for (int c = tid; c < BM * CHR; c += TPB) {
            int r = c / CHR, cc = c % CHR;
            cp16(base + r * SROW + cc * 16, A + (size_t)(m0 + r) * lda + k0 + cc * 8);
        }
#pragma unroll
        for (int c = tid; c < BN * CHR; c += TPB) {
            int r = c / CHR, cc = c % CHR;
            cp16(base + ATILE + r * SROW + cc * 16, Bm + (size_t)(n0 + r) * ldb + k0 + cc * 8);
        }
        CP_COMMIT();
    };

    const int nch = K / KB;
#pragma unroll
    for (int s = 0; s < STAGES - 1; s++) load_stage(s, s);

    int cs = 0;
    int ps = (STAGES - 1) % STAGES;
    for (int ch = 0; ch < nch; ch++) {
        cp_wait<STAGES - 2>();
        __syncthreads();
        const int pf = ch + STAGES - 1;
        if (pf < nch) load_stage(pf, ps);
        else CP_COMMIT();

        const uint32_t aBase = sb + cs * STAGE;
        const uint32_t bBase = aBase + ATILE;
#pragma unroll
        for (int ks = 0; ks < NKS; ks++) {
            const uint32_t colOff = (uint32_t)(ks * 2 + (lane >> 4)) * 16;
            uint32_t a_f[MI][4];
#pragma unroll
            for (int mi = 0; mi < MI; mi++) {
                uint32_t addr = aBase + (uint32_t)(wm * (MI * 16) + mi * 16 + (lane & 15)) * SROW + colOff;
                ldmat4(a_f[mi], addr);
            }
#pragma unroll
            for (int nt = 0; nt < NFRAG / 2; nt++) {
                uint32_t addr = bBase + (uint32_t)(wn * WN + nt * 16 + (lane & 15)) * SROW + colOff;
                uint32_t bf[4];
                ldmat4(bf, addr);
#pragma unroll
                for (int half = 0; half < 2; half++) {
                    const int ni = nt * 2 + half;
#pragma unroll
                    for (int mi = 0; mi < MI; mi++)
                        mma16816(acc[mi][ni], a_f[mi], bf[half], bf[2 + half]);
                }
            }
        }
        cs = (cs + 1 == STAGES) ? 0 : cs + 1;
        ps = (ps + 1 == STAGES) ? 0 : ps + 1;
    }

    // ---------------- epilogue ----------------
    const int g = lane >> 2, tg = lane & 3;
#pragma unroll
    for (int mi = 0; mi < MI; mi++) {
#pragma unroll
        for (int ni = 0; ni < NFRAG; ni++) {
            const int col = n0 + wn * WN + ni * 8 + tg * 2;
            const float b0 = biasN ? biasN[col] : 0.f;
            const float b1 = biasN ? biasN[col + 1] : 0.f;
#pragma unroll
            for (int h = 0; h < 2; h++) {
                const int row = m0 + wm * (MI * 16) + mi * 16 + g + h * 8;
                float v0 = acc[mi][ni][h * 2 + 0] * scale + b0;
                float v1 = acc[mi][ni][h * 2 + 1] * scale + b1;
                if (ACT == 1) { v0 = mishf(v0); v1 = mishf(v1); }
                const size_t o = (size_t)row * ldOut + col;
                if (OUTFMT == 0) {
                    float2 fp; fp.x = v0; fp.y = v1;
                    *(float2*)(outF + o) = fp;
                } else {
                    __half2 hp;
                    hp.x = __float2half_rn(v0);
                    hp.y = __float2half_rn(v1);
                    *(__half2*)(outH + o) = hp;
                }
            }
        }
    }
}

template <int BN, int OUTFMT, int ACT, int FUSE, int STAGES, int KB, int WM>
__global__ void __launch_bounds__(WM * 128) gemm_mma(
    const __half* __restrict__ A, const __half* __restrict__ Bm,
    const float* __restrict__ biasN,
    float* __restrict__ outF, __half* __restrict__ outH,
    int K, int lda, int ldb, int ldOut,
    size_t sA, size_t sB, size_t sO, size_t selB, size_t selO, float scale)
{
    extern __shared__ char smem[];
    gemm_body<BN, OUTFMT, ACT, FUSE, STAGES, KB, WM>(
        A, Bm, biasN, outF, outH,
        K, lda, ldb, ldOut, sA, sB, sO, selB, selO, scale, smem);
}

// ============================================================================
// Fused Sg/Sl GEMM (z<16) + g-transpose/gbar (z>=16), 256 threads, ONE launch.
// Grid (4, 2, 24). z in [16,24): vb = (z-16)*8 + by*4 + bx in [0,64):
// b = vb>>3, l0 = (vb&7)*32.
// ============================================================================
__global__ void __launch_bounds__(256) sgsl_gtrans(
    const __half* __restrict__ qkvHi,
    float* __restrict__ Sg,
    __half* __restrict__ gg2Hi,
    float* __restrict__ gbar)
{
    extern __shared__ char smem[];
    if (blockIdx.z < 16) {
        gemm_body<64, 0, 0, 1, 3, 64, 2>(
            qkvHi + C_, qkvHi, nullptr, Sg, nullptr,
            C_, C3_, C3_, L_, (size_t)L_ * C3_, (size_t)L_ * C3_, (size_t)L_ * L_,
            (size_t)(2 * C_), BLL_, SCALE_, smem);
        return;
    }
    // ---- transpose + gbar path (256 threads, 8 warps) ----
    __half (*th)[34] = (__half(*)[34])smem;
    const int vb = (blockIdx.z - 16) * 8 + blockIdx.y * 4 + blockIdx.x;
    const int b = vb >> 3;
    const int l0 = (vb & 7) * 32;
    const int tx = threadIdx.x & 31, ty = threadIdx.x >> 5;    // ty in 0..7

    for (int ct = 0; ct < 16; ct++) {
        const int c0 = ct * 32;
#pragma unroll
        for (int j = 0; j < 4; j++) {
            size_t idx = ((size_t)b * L_ + l0 + ty + j * 8) * C3_ + 2 * C_ + c0 + tx;
            th[ty + j * 8][tx] = qkvHi[idx];
        }
        __syncthreads();
#pragma unroll
        for (int j = 0; j < 4; j++) {
            int c = c0 + ty + j * 8;
            size_t o = ((size_t)b * C_ + c) * L_ + l0 + tx;
            gg2Hi[o] = th[tx][ty + j * 8];
        }
        __syncthreads();
    }
    // gbar: 8 warps, each handles 4 l values
#pragma unroll
    for (int i = 0; i < 4; i++) {
        const int l = l0 + ty * 4 + i;
        const size_t base = ((size_t)b * L_ + l) * C3_ + 2 * C_;
        float s = 0.f;
#pragma unroll
        for (int c = tx; c < C_; c += 32)
            s += __half2float(qkvHi[base + c]);
        s = warpSum(s);
        if (tx == 0) gbar[b * L_ + l] = s * (1.f / C_);
    }
}

// ============================================================================
// prep_all: ONE launch = vectorized fp16 weight conversion (8 elems/thread)
//           + qkv bias concat + x transpose (f16 + f32).
// ============================================================================
constexpr int PREP_WELEMS = 3 * C_ * C_ + C_ * C_ + C4_ * C_ + C_ * C4_;  // 3145728
constexpr int PREP_NW8 = PREP_WELEMS / 8 / 256;       // 1536 blocks
constexpr int PREP_NB = 6;
constexpr int PREP_NT = (L_ / 32) * (C_ / 32) * B_;   // 1024 blocks

__global__ void prep_all(const float* __restrict__ x,
                         const float* __restrict__ tw, const float* __restrict__ pw,
                         const float* __restrict__ gw, const float* __restrict__ wgw,
                         const float* __restrict__ c1w, const float* __restrict__ c2w,
                         const float* __restrict__ tb, const float* __restrict__ pb,
                         const float* __restrict__ gb,
                         __half* __restrict__ qkvW, __half* __restrict__ wgW,
                         __half* __restrict__ c1W, __half* __restrict__ c2W,
                         float* __restrict__ qkvb,
                         __half* __restrict__ xtHi, float* __restrict__ xt32)
{
    __shared__ float t[32][33];
    const int bid = blockIdx.x;
    if (bid < PREP_NW8) {
        constexpr int NW = C_ * C_;
        constexpr int N1 = 3 * NW;
        constexpr int N2 = N1 + NW;
        constexpr int N3 = N2 + C4_ * C_;
        const int i = (bid * 256 + threadIdx.x) * 8;
        const float* src;
        __half* dst;
        int j;
        if (i < N1) {
            j = i & (NW - 1);
            src = (i < NW) ? tw : (i < 2 * NW ? pw : gw);
            dst = qkvW + i;
        } else if (i < N2) {
            j = i - N1; src = wgw; dst = wgW + j;
        } else if (i < N3) {
            j = i - N2; src = c1w; dst = c1W + j;
        } else {
            j = i - N3; src = c2w; dst = c2W + j;
        }
        float4 va = *(const float4*)(src + j);
        float4 vb = *(const float4*)(src + j + 4);
        __half2 h[4];
        h[0].x = __float2half_rn(va.x); h[0].y = __float2half_rn(va.y);
        h[1].x = __float2half_rn(va.z); h[1].y = __float2half_rn(va.w);
        h[2].x = __float2half_rn(vb.x); h[2].y = __float2half_rn(vb.y);
        h[3].x = __float2half_rn(vb.z); h[3].y = __float2half_rn(vb.w);
        *(uint4*)dst = *(uint4*)h;
    } else if (bid < PREP_NW8 + PREP_NB) {
        const int j = (bid - PREP_NW8) * 256 + threadIdx.x;
        if (j < C3_)
            qkvb[j] = (j < C_) ? tb[j] : (j < 2 * C_ ? pb[j - C_] : gb[j - 2 * C_]);
    } else {
        const int tI = bid - PREP_NW8 - PREP_NB;
        const int b = tI >> 7;
        const int rem = tI & 127;
        const int c0 = (rem & 15) * 32;
        const int l0 = (rem >> 4) * 32;
        const int tx = threadIdx.x & 31, ty = threadIdx.x >> 5;
        const float* xb = x + (size_t)b * CL_;
#pragma unroll
        for (int j = 0; j < 4; j++)
            t[ty + j * 8][tx] = xb[(size_t)(c0 + ty + j * 8) * L_ + l0 + tx];
        __syncthreads();
#pragma unroll
        for (int j = 0; j < 4; j++) {
            int l = l0 + ty + j * 8;
            float v = t[tx][ty + j * 8];
            size_t o = ((size_t)b * L_ + l) * C_ + c0 + tx;
            xtHi[o] = __float2half_rn(v);
            xt32[o] = v;
        }
    }
}

// ============================================================================
// softmax_gate v2: warp-per-row, NO block syncs.
// grid (L/8, B), block 256 (8 warps). Warp w owns row l = bx*8 + w:
//   softmax over Sg row (8 elems/lane) -> gp f16 (16B store/lane)
//   banded local gate from Sl row + gbar.
// ============================================================================
__global__ void __launch_bounds__(256) softmax_gate(
    const float* __restrict__ Sg,
    const float* __restrict__ Sl,
    const float* __restrict__ gbar,
    const float* __restrict__ wlw,
    const float* __restrict__ wlb,
    __half* __restrict__ pHi,
    float* __restrict__ gate)
{
    const int w = threadIdx.x >> 5, lane = threadIdx.x & 31;
    const int l = blockIdx.x * 8 + w;
    const int b = blockIdx.y;
    const size_t row = (size_t)b * L_ + l;

    // --- softmax over 256 elems: 8 per lane ---
    const float4* srow4 = (const float4*)(Sg + row * L_);
    float4 a = srow4[lane * 2];
    float4 c = srow4[lane * 2 + 1];
    float v[8] = {a.x, a.y, a.z, a.w, c.x, c.y, c.z, c.w};
    float mx = v[0];
#pragma unroll
    for (int i = 1; i < 8; i++) mx = fmaxf(mx, v[i]);
    mx = warpMax(mx);
    float sum = 0.f;
#pragma unroll
    for (int i = 0; i < 8; i++) { v[i] = __expf(v[i] - mx); sum += v[i]; }
    sum = warpSum(sum);
    const float inv = 1.f / sum;
    __half2 hp[4];
#pragma unroll
    for (int i = 0; i < 4; i++) {
        hp[i].x = __float2half_rn(v[2 * i] * inv);
        hp[i].y = __float2half_rn(v[2 * i + 1] * inv);
    }
    *(uint4*)(pHi + row * L_ + lane * 8) = *(uint4*)hp;

    // --- banded local gate (same warp; zeros participate in softmax) ---
    const float* slrow = Sl + row * L_;
    const float* gb = gbar + (size_t)b * L_;
    int m0 = l + lane - 32;
    int m1 = l + lane;
    bool v0 = (m0 >= 0) && (m0 < L_);
    bool v1 = (m1 >= 0) && (m1 < L_);
    float s0 = v0 ? slrow[m0] : 0.f;
    float s1 = v1 ? slrow[m1] : 0.f;
    float g0 = v0 ? gb[m0] : 0.f;
    float g1 = v1 ? gb[m1] : 0.f;
    float bx = warpMax(fmaxf(s0, s1));
    float e0 = __expf(s0 - bx), e1 = __expf(s1 - bx);
    float num = warpSum(e0 * g0 + e1 * g1);
    float den = warpSum(e0 + e1);
    if (lane == 0) {
        float pooled = num / den;
        float z = wlw[0] * pooled + wlb[0];
        gate[b * L_ + l] = 1.f / (1.f + __expf(-z));
    }
}

// ============================================================================
// LN1: h = gout2T*gate + xT32 ; h1 f32 + f16 at row (l*B+b), [*,C]
// ============================================================================
__global__ void ln1_kernel(const float* __restrict__ gout2T,
                           const float* __restrict__ gate,
                           const float* __restrict__ xt32,
                           const float* __restrict__ g1, const float* __restrict__ b1,
                           float* __restrict__ h1,
                           __half* __restrict__ h1hi)
{
    __shared__ float sm[16];
    int l = blockIdx.x, b = blockIdx.y, tid = threadIdx.x;
    int lane = tid & 31, w = tid >> 5;
    float gt = gate[b * L_ + l];
    size_t gbase = ((size_t)b * L_ + l) * C_;
    float v0 = fmaf(gout2T[gbase + tid], gt, xt32[gbase + tid]);
    float v1 = fmaf(gout2T[gbase + tid + 256], gt, xt32[gbase + tid + 256]);
    float s = warpSum(v0 + v1);
    float q = warpSum(v0 * v0 + v1 * v1);
    if (lane == 0) { sm[w] = s; sm[8 + w] = q; }
    __syncthreads();
    float S = 0.f, Q = 0.f;
#pragma unroll
    for (int i = 0; i < 8; i++) { S += sm[i]; Q += sm[8 + i]; }
    float mean = S * (1.f / C_);
    float var = Q * (1.f / C_) - mean * mean;
    float r = rsqrtf(var + 1e-5f);
    size_t o = ((size_t)l * B_ + b) * C_;
    float y0 = (v0 - mean) * r * g1[tid] + b1[tid];
    float y1 = (v1 - mean) * r * g1[tid + 256] + b1[tid + 256];
    h1[o + tid] = y0;
    h1[o + tid + 256] = y1;
    h1hi[o + tid] = __float2half_rn(y0);
    h1hi[o + tid + 256] = __float2half_rn(y1);
}

// ============================================================================
// LN2 + output transpose
// ============================================================================
__global__ void ln2_kernel(const float* __restrict__ m2,
                           const float* __restrict__ h1,
                           const float* __restrict__ g2, const float* __restrict__ b2,
                           float* __restrict__ out)
{
    __shared__ float sm[16];
    int row = blockIdx.x, tid = threadIdx.x;
    int lane = tid & 31, w = tid >> 5;
    int l = row / B_, b = row % B_;
    size_t base = (size_t)row * C_;
    float v0 = m2[base + tid] + h1[base + tid];
    float v1 = m2[base + tid + 256] + h1[base + tid + 256];
    float s = warpSum(v0 + v1);
    float q = warpSum(v0 * v0 + v1 * v1);
    if (lane == 0) { sm[w] = s; sm[8 + w] = q; }
    __syncthreads();
    float S = 0.f, Q = 0.f;
#pragma unroll
    for (int i = 0; i < 8; i++) { S += sm[i]; Q += sm[8 + i]; }
    float mean = S * (1.f / C_);
    float var = Q * (1.f / C_) - mean * mean;
    float r = rsqrtf(var + 1e-5f);
    size_t ob = (size_t)b * CL_ + l;
    out[ob + (size_t)tid * L_]         = (v0 - mean) * r * g2[tid] + b2[tid];
    out[ob + (size_t)(tid + 256) * L_] = (v1 - mean) * r * g2[tid + 256] + b2[tid + 256];
}

} // namespace

// ============================================================================
// Host launcher
// ============================================================================
extern "C" void kernel_launch(void* const* d_in, const int* in_sizes, int n_in,
                              void* d_out, int out_size)
{
    (void)in_sizes; (void)n_in; (void)out_size;
    float* scratch = nullptr;
    cudaGetSymbolAddress((void**)&scratch, d_scratch);

    const float* x       = (const float*)d_in[0];
    const float* theta_w = (const float*)d_in[1];
    const float* theta_b = (const float*)d_in[2];
    const float* phi_w   = (const float*)d_in[3];
    const float* phi_b   = (const float*)d_in[4];
    const float* g_w     = (const float*)d_in[5];
    const float* g_b     = (const float*)d_in[6];
    const float* wl_w    = (const float*)d_in[7];
    const float* wl_b    = (const float*)d_in[8];
    const float* wg_w    = (const float*)d_in[9];
    const float* wg_b    = (const float*)d_in[10];
    const float* conv1_w = (const float*)d_in[11];
    const float* conv1_b = (const float*)d_in[12];
    const float* conv2_w = (const float*)d_in[13];
    const float* conv2_b = (const float*)d_in[14];
    const float* ln1_g   = (const float*)d_in[15];
    const float* ln1_b   = (const float*)d_in[16];
    const float* ln2_g   = (const float*)d_in[17];
    const float* ln2_b   = (const float*)d_in[18];
    float* out = (float*)d_out;

    __half* xtHi   = (__half*)(scratch + OFF_XT_HI);
    float* xt32    = scratch + OFF_XT32;
    __half* wqkvW  = (__half*)(scratch + OFF_WQKV_HI);
    float* qkv_b   = scratch + OFF_QKV_B;
    __half* wwgW   = (__half*)(scratch + OFF_WWG_HI);
    __half* c1W    = (__half*)(scratch + OFF_C1WHI);
    __half* c2W    = (__half*)(scratch + OFF_C2WHI);
    __half* qkvHi  = (__half*)(scratch + OFF_QKVT_HI);
    float* Sg      = scratch + OFF_SG;
    __half* gpHi   = (__half*)(scratch + OFF_GP_HI);
    __half* gg2Hi  = (__half*)(scratch + OFF_GG2_HI);
    float* gbar    = scratch + OFF_GBAR;
    float* gate    = scratch + OFF_GATE;
    __half* goHi   = (__half*)(scratch + OFF_GOUTT_HI);
    float* gout2T  = scratch + OFF_GOUT2T;
    float* h1      = scratch + OFF_H1;
    __half* h1Hi   = (__half*)(scratch + OFF_H1HI);
    __half* m1Hi   = (__half*)(scratch + OFF_M1HI);
    float* m2      = scratch + OFF_M2;

    // SMEM: BN=64 KB=64 3st: stage = 18432+9216 = 27648 -> x3 = 82944 (2 CTA/SM)
    //       BN=128 KB=32 2st: stage = 10240+10240 = 20480 -> x2 = 40960
    constexpr int SM_64  = 82944;
    constexpr int SM_128 = 40960;
    cudaFuncSetAttribute(sgsl_gtrans,                      cudaFuncAttributeMaxDynamicSharedMemorySize, SM_64);
    cudaFuncSetAttribute(gemm_mma<64, 2, 0, 0, 3, 64, 2>,  cudaFuncAttributeMaxDynamicSharedMemorySize, SM_64);
    cudaFuncSetAttribute(gemm_mma<64, 0, 0, 0, 3, 64, 2>,  cudaFuncAttributeMaxDynamicSharedMemorySize, SM_64);
    cudaFuncSetAttribute(gemm_mma<128, 2, 0, 0, 2, 32, 2>, cudaFuncAttributeMaxDynamicSharedMemorySize, SM_128);
    cudaFuncSetAttribute(gemm_mma<128, 2, 1, 0, 2, 32, 2>, cudaFuncAttributeMaxDynamicSharedMemorySize, SM_128);

    // 0) prep: weight fp16 conversion + bias concat + x transpose (f16 + f32)
    prep_all<<<PREP_NW8 + PREP_NB + PREP_NT, 256>>>(
        x, theta_w, phi_w, g_w, wg_w, conv1_w, conv2_w, theta_b, phi_b, g_b,
        wqkvW, wwgW, c1W, c2W, qkv_b, xtHi, xt32);

    // 1) fused qkv: qkvT[b,l,:] = xT(b) @ [th;ph;g]^T + bias -> f16
    {
        dim3 grid(C3_ / 128, L_ / 128, B_);
        gemm_mma<128, 2, 0, 0, 2, 32, 2><<<grid, 256, SM_128>>>(
            xtHi, wqkvW, qkv_b, nullptr, qkvHi,
            C_, C_, C_, C3_, (size_t)L_ * C_, 0, (size_t)L_ * C3_, 0, 0, 1.f);
    }

    // 2) Sg & Sl + g-transpose + gbar, ONE launch (256 thr, 2 CTA/SM)
    {
        dim3 grid(L_ / 64, L_ / 128, 16 + 8);
        sgsl_gtrans<<<grid, 256, SM_64>>>(qkvHi, Sg, gg2Hi, gbar);
    }

    // 3) fused softmax + local gate (warp-per-row)
    softmax_gate<<<dim3(L_ / 8, B_), 256>>>(Sg, Sg + BLL_, gbar,
                                            wl_w, wl_b, gpHi, gate);

    // 4) goutT = gp @ gg2^T -> f16 ; gout2T = goutT @ wg^T + wg_b -> f32
    {
        dim3 grid(C_ / 64, L_ / 128, B_);
        gemm_mma<64, 2, 0, 0, 3, 64, 2><<<grid, 256, SM_64>>>(
            gpHi, gg2Hi, nullptr, nullptr, goHi,
            L_, L_, L_, C_, (size_t)L_ * L_, (size_t)CL_, (size_t)L_ * C_, 0, 0, 1.f);
        gemm_mma<64, 0, 0, 0, 3, 64, 2><<<grid, 256, SM_64>>>(
            goHi, wwgW, wg_b, gout2T, nullptr,
            C_, C_, C_, C_, (size_t)L_ * C_, 0, (size_t)L_ * C_, 0, 0, 1.f);
    }

    // 5) LN1 -> h1 (f32 + f16)
    ln1_kernel<<<dim3(L_, B_), 256>>>(gout2T, gate, xt32, ln1_g, ln1_b, h1, h1Hi);

    // 6) MLP1: m1 = Mish(h1 @ conv1^T + b) -> f16
    {
        dim3 grid(C4_ / 128, NR_ / 128, 1);
        gemm_mma<128, 2, 1, 0, 2, 32, 2><<<grid, 256, SM_128>>>(
            h1Hi, c1W, conv1_b, nullptr, m1Hi,
            C_, C_, C_, C4_, 0, 0, 0, 0, 0, 1.f);
    }

    // 7) MLP2: m2 = m1 @ conv2^T + b -> f32
    {
        dim3 grid(C_ / 64, NR_ / 128, 1);
        gemm_mma<64, 0, 0, 0, 3, 64, 2><<<grid, 256, SM_64>>>(
            m1Hi, c2W, conv2_b, m2, nullptr,
            C4_, C4_, C4_, C_, 0, 0, 0, 0, 0, 1.f);
    }

    // 8) LN2 + transpose out
    ln2_kernel<<<NR_, 256>>>(m2, h1, ln2_g, ln2_b, out);
}